// round 1
// baseline (speedup 1.0000x reference)
#include <cuda_runtime.h>
#include <math.h>

// Problem constants
constexpr int kT = 2048;
constexpr int kB = 2;
constexpr int kE = 1024;
constexpr int kH = 8;
constexpr int kD = 128;
constexpr int kR = 2;
constexpr int kNH = 8;       // NHASH
constexpr int kCH = 32;      // CHUNK
constexpr int kC = kT / kCH; // 64 chunks
constexpr int kM = 3 * kCH;  // 96 window keys
constexpr int kTB = kT * kB; // 4096 rows

constexpr float kScale = 0.08838834764831845f; // D^-0.5
constexpr float kInfM = 1.0e16f;
constexpr float kBigM = 1.0e8f;
constexpr float kLog2 = 0.6931471805599453f;

// ---------------- device scratch ----------------
__device__ float g_QF[kTB * kE];    // raw projected q
__device__ float g_Q[kTB * kE];     // scaled q      [t,b,h,d]
__device__ float g_K[kTB * kE];     // normalized q  [t,b,h,d]
__device__ float g_V[kTB * kE];     // projected v
__device__ float g_comb[kTB * kE];  // combined attention out [t,b,e]
__device__ float g_o[kB * kR * kH * kT * kD];
__device__ float g_z[kB * kR * kH * kT];
__device__ int g_qh[kT * kB * kR * kH];
__device__ int g_kh[kT * kB * kR * kH];
__device__ int g_pq[kB * kR * kH * kT];
__device__ int g_pk[kB * kR * kH * kT];
__device__ int g_invq[kB * kR * kH * kT];
__device__ unsigned g_mask[kB * kR * kH * kC * (kT / 32)];

// ---------------- SGEMM: C[M,N] = A[M,K] @ B[K,N] + bias ----------------
// 128x128 block, BK=16, 256 threads, 8x8 microtile. Assumes M,N,K % 128/16 == 0.
__global__ __launch_bounds__(256) void sgemm128(
    const float* __restrict__ A, const float* __restrict__ Bm,
    const float* __restrict__ bias, float* __restrict__ Cc,
    int M, int N, int K) {
  __shared__ float As[16][128];
  __shared__ float Bs[16][128];
  int tid = threadIdx.x;
  int tx = tid & 15, ty = tid >> 4;
  int row0 = blockIdx.y * 128;
  int col0 = blockIdx.x * 128;
  float acc[8][8];
#pragma unroll
  for (int i = 0; i < 8; i++)
#pragma unroll
    for (int j = 0; j < 8; j++) acc[i][j] = 0.f;

  for (int k0 = 0; k0 < K; k0 += 16) {
#pragma unroll
    for (int i = 0; i < 2; i++) {
      int idx = tid + i * 256;          // 0..511
      int rr = idx >> 2;                // 0..127
      int c4 = (idx & 3) << 2;          // 0,4,8,12
      float4 v = *(const float4*)(A + (size_t)(row0 + rr) * K + k0 + c4);
      As[c4 + 0][rr] = v.x; As[c4 + 1][rr] = v.y;
      As[c4 + 2][rr] = v.z; As[c4 + 3][rr] = v.w;
    }
#pragma unroll
    for (int i = 0; i < 2; i++) {
      int idx = tid + i * 256;
      int rr = idx >> 5;                // 0..15
      int cc = (idx & 31) << 2;         // 0..124
      *(float4*)&Bs[rr][cc] = *(const float4*)(Bm + (size_t)(k0 + rr) * N + col0 + cc);
    }
    __syncthreads();
#pragma unroll
    for (int kk = 0; kk < 16; kk++) {
      float a[8], bb[8];
      *(float4*)a = *(float4*)&As[kk][ty * 8];
      *(float4*)(a + 4) = *(float4*)&As[kk][ty * 8 + 4];
      *(float4*)bb = *(float4*)&Bs[kk][tx * 8];
      *(float4*)(bb + 4) = *(float4*)&Bs[kk][tx * 8 + 4];
#pragma unroll
      for (int i = 0; i < 8; i++)
#pragma unroll
        for (int j = 0; j < 8; j++) acc[i][j] += a[i] * bb[j];
    }
    __syncthreads();
  }
#pragma unroll
  for (int i = 0; i < 8; i++) {
    int row = row0 + ty * 8 + i;
#pragma unroll
    for (int j4 = 0; j4 < 8; j4 += 4) {
      int col = col0 + tx * 8 + j4;
      float4 bv = *(const float4*)(bias + col);
      float4 o;
      o.x = acc[i][j4 + 0] + bv.x;
      o.y = acc[i][j4 + 1] + bv.y;
      o.z = acc[i][j4 + 2] + bv.z;
      o.w = acc[i][j4 + 3] + bv.w;
      *(float4*)(Cc + (size_t)row * N + col) = o;
    }
  }
}

// ---------------- normalize + scale ----------------
// block per row (t*B+b): K = QF/||QF||_E, Q = QF * scale
__global__ __launch_bounds__(256) void normalize_kernel() {
  int row = blockIdx.x;
  const float* x = g_QF + (size_t)row * kE;
  __shared__ float red[256];
  int tid = threadIdx.x;
  float s = 0.f;
#pragma unroll
  for (int i = 0; i < 4; i++) {
    float v = x[tid + i * 256];
    s += v * v;
  }
  red[tid] = s;
  __syncthreads();
  for (int off = 128; off > 0; off >>= 1) {
    if (tid < off) red[tid] += red[tid + off];
    __syncthreads();
  }
  float invn = 1.0f / sqrtf(red[0]);
#pragma unroll
  for (int i = 0; i < 4; i++) {
    int e = tid + i * 256;
    float v = x[e];
    g_Q[(size_t)row * kE + e] = v * kScale;
    g_K[(size_t)row * kE + e] = v * invn;
  }
}

// ---------------- hash kernel ----------------
// one warp per (tb, h, src); computes both rounds' buckets
__global__ __launch_bounds__(256) void hash_kernel(const float* __restrict__ hw) {
  int gw = (blockIdx.x * 256 + threadIdx.x) >> 5;
  int lane = threadIdx.x & 31;
  int src = gw & 1;
  int item = gw >> 1;      // tb*H + h
  int h = item & 7;
  int tb = item >> 3;
  const float* x = (src ? g_K : g_Q) + (size_t)tb * kE + h * kD;
  float acc[2][4] = {{0, 0, 0, 0}, {0, 0, 0, 0}};
#pragma unroll
  for (int i = 0; i < 4; i++) {
    int d = lane + i * 32;
    float xv = x[d];
#pragma unroll
    for (int r = 0; r < 2; r++) {
      float4 w = *(const float4*)(hw + (size_t)(((r * kH + h) * kD + d)) * 4);
      acc[r][0] += xv * w.x;
      acc[r][1] += xv * w.y;
      acc[r][2] += xv * w.z;
      acc[r][3] += xv * w.w;
    }
  }
#pragma unroll
  for (int r = 0; r < 2; r++)
#pragma unroll
    for (int n = 0; n < 4; n++)
      for (int off = 16; off; off >>= 1)
        acc[r][n] += __shfl_xor_sync(0xffffffffu, acc[r][n], off);
  if (lane == 0) {
    int* outp = src ? g_kh : g_qh;
#pragma unroll
    for (int r = 0; r < 2; r++) {
      float best = acc[r][0];
      int bi = 0;
#pragma unroll
      for (int n = 1; n < 4; n++)
        if (acc[r][n] > best) { best = acc[r][n]; bi = n; }
#pragma unroll
      for (int n = 0; n < 4; n++)
        if (-acc[r][n] > best) { best = -acc[r][n]; bi = 4 + n; }
      outp[(tb * kR + r) * kH + h] = bi;
    }
  }
}

// ---------------- stable counting sort per (b,r,h) ----------------
// grid.x = B*R*H (32), grid.y = 2 (0: q-sort + inverse, 1: k-sort)
__global__ __launch_bounds__(256) void sort_kernel() {
  int brh = blockIdx.x;
  int which = blockIdx.y;
  int h = brh & 7;
  int r = (brh >> 3) & 1;
  int b = brh >> 4;
  const int* hv = which ? g_kh : g_qh;
  int* perm = (which ? g_pk : g_pq) + brh * kT;
  __shared__ int shv[kT];
  __shared__ int cnt[kNH];
  __shared__ int offs[kNH];
  int tid = threadIdx.x;
  if (tid < kNH) cnt[tid] = 0;
  __syncthreads();
  for (int t = tid; t < kT; t += 256) {
    int v = hv[(t * kB + b) * (kR * kH) + r * kH + h];
    shv[t] = v;
    atomicAdd(&cnt[v], 1);
  }
  __syncthreads();
  if (tid == 0) {
    int s = 0;
    for (int i = 0; i < kNH; i++) { offs[i] = s; s += cnt[i]; }
  }
  __syncthreads();
  if (tid < kNH) {
    int bkt = tid;
    int pos = offs[bkt];
    for (int t = 0; t < kT; t++) {
      if (shv[t] == bkt) {
        perm[pos] = t;
        if (!which) g_invq[brh * kT + t] = pos;
        pos++;
      }
    }
  }
}

// ---------------- per-chunk window bitmask ----------------
// block per (brh, c): bitset over key token ids in the 96-key window
__global__ __launch_bounds__(128) void mask_kernel() {
  int blk = blockIdx.x;  // brh*kC + c
  int c = blk & (kC - 1);
  int brh = blk >> 6;
  unsigned* mw = g_mask + (size_t)blk * (kT / 32);
  int tid = threadIdx.x;
  if (tid < kT / 32) mw[tid] = 0u;
  __syncthreads();
  if (tid < kM) {
    int cc2 = (c + (tid >> 5) + kC - 1) & (kC - 1);
    int pos = cc2 * kCH + (tid & 31);
    int id = g_pk[brh * kT + pos];
    atomicOr(&mw[id >> 5], 1u << (id & 31));
  }
}

// ---------------- attention kernel ----------------
constexpr int kQS = 132;  // padded row stride for smem tiles
constexpr int ATTN_SMEM =
    (32 * kQS + 96 * kQS + 96 * kQS + 32 * 96 + 64) * 4 + (32 * 3 + 96 * 2) * 4;

__global__ __launch_bounds__(256, 1) void attn_kernel() {
  extern __shared__ float sm[];
  float* sq = sm;                    // 32 x 132
  float* sk = sq + 32 * kQS;         // 96 x 132
  float* sv = sk + 96 * kQS;         // 96 x 132
  float* sc = sv + 96 * kQS;         // 32 x 96
  float* rinv = sc + 32 * 96;        // 32
  float* rowz = rinv + 32;           // 32
  int* qid = (int*)(rowz + 32);      // 32
  int* qhh = qid + 32;               // 32
  int* oc2 = qhh + 32;               // 32
  int* kid = oc2 + 32;               // 96
  int* khh = kid + 96;               // 96

  int blk = blockIdx.x;
  int c = blk & (kC - 1);
  int brh = blk >> 6;
  int h = brh & 7;
  int r = (brh >> 3) & 1;
  int b = brh >> 4;
  int brho = (b * kR + (1 - r)) * kH + h;  // other round
  int tid = threadIdx.x;

  if (tid < 32) {
    int ts = c * kCH + tid;
    int tok = g_pq[brh * kT + ts];
    qid[tid] = tok;
    qhh[tid] = g_qh[(tok * kB + b) * (kR * kH) + r * kH + h];
    oc2[tid] = g_invq[brho * kT + tok] >> 5;  // /CHUNK
  } else if (tid < 128) {
    int m = tid - 32;  // 0..95
    int cc2 = (c + (m >> 5) + kC - 1) & (kC - 1);
    int pos = cc2 * kCH + (m & 31);
    int tokk = g_pk[brh * kT + pos];
    kid[m] = tokk;
    khh[m] = g_kh[(tokk * kB + b) * (kR * kH) + r * kH + h];
  }
  __syncthreads();

  // load q tile: 32 rows x 32 float4
#pragma unroll
  for (int i = 0; i < 4; i++) {
    int idx = tid + i * 256;
    int l = idx >> 5, d4 = idx & 31;
    float4 v = *(const float4*)(g_Q + (size_t)(qid[l] * kB + b) * kE + h * kD + d4 * 4);
    *(float4*)&sq[l * kQS + d4 * 4] = v;
  }
  // load k/v tiles: 96 rows x 32 float4 each
#pragma unroll
  for (int i = 0; i < 12; i++) {
    int idx = tid + i * 256;
    int m = idx >> 5, d4 = idx & 31;
    size_t base = (size_t)(kid[m] * kB + b) * kE + h * kD + d4 * 4;
    *(float4*)&sk[m * kQS + d4 * 4] = *(const float4*)(g_K + base);
    *(float4*)&sv[m * kQS + d4 * 4] = *(const float4*)(g_V + base);
  }
  __syncthreads();

  // scores: 8 threads per row, 12 key columns each
  {
    int l = tid >> 3, sub = tid & 7;
    float acc[12];
#pragma unroll
    for (int j = 0; j < 12; j++) acc[j] = 0.f;
    const float* qrow = sq + l * kQS;
    for (int d = 0; d < kD; d++) {
      float qv = qrow[d];
#pragma unroll
      for (int j = 0; j < 12; j++) acc[j] += qv * sk[(sub + j * 8) * kQS + d];
    }
    int myqh = qhh[l], myqid = qid[l];
    const unsigned* mw = g_mask + (size_t)(brho * kC + oc2[l]) * (kT / 32);
#pragma unroll
    for (int j = 0; j < 12; j++) {
      int m = sub + j * 8;
      float s = acc[j];
      if (myqh != khh[m]) s -= kInfM;       // mask_different_hashes
      int id = kid[m];
      if (myqid == id) s -= kBigM;          // mask_current
      if ((mw[id >> 5] >> (id & 31)) & 1u) s -= kLog2;  // cross-round dup
      sc[l * 96 + m] = s;
    }
  }
  __syncthreads();

  // softmax per row (warp per 4 rows), keep logsumexp z
  {
    int w = tid >> 5, lane = tid & 31;
    for (int rr = 0; rr < 4; rr++) {
      int l = w * 4 + rr;
      float mx = -3.0e38f;
      for (int m = lane; m < 96; m += 32) mx = fmaxf(mx, sc[l * 96 + m]);
      for (int off = 16; off; off >>= 1)
        mx = fmaxf(mx, __shfl_xor_sync(0xffffffffu, mx, off));
      float s = 0.f;
      for (int m = lane; m < 96; m += 32) {
        float e = expf(sc[l * 96 + m] - mx);
        sc[l * 96 + m] = e;
        s += e;
      }
      for (int off = 16; off; off >>= 1)
        s += __shfl_xor_sync(0xffffffffu, s, off);
      if (lane == 0) {
        rinv[l] = 1.0f / s;
        rowz[l] = mx + logf(s);
      }
    }
  }
  __syncthreads();

  // output: scatter directly to original token order
#pragma unroll
  for (int it = 0; it < 16; it++) {
    int idx = tid + it * 256;
    int l = idx >> 7, d = idx & 127;
    float acc = 0.f;
#pragma unroll 4
    for (int m = 0; m < 96; m++) acc += sc[l * 96 + m] * sv[m * kQS + d];
    g_o[(size_t)(brh * kT + qid[l]) * kD + d] = acc * rinv[l];
  }
  if (tid < 32) g_z[brh * kT + qid[tid]] = rowz[tid];
}

// ---------------- combine rounds ----------------
__global__ __launch_bounds__(256) void combine_kernel() {
  int idx = blockIdx.x * 256 + threadIdx.x;  // over B*H*T*D = 4194304
  int d = idx & 127;
  int t = (idx >> 7) & (kT - 1);
  int h = (idx >> 18) & 7;
  int b = idx >> 21;
  int i0 = ((b * kR + 0) * kH + h) * kT + t;
  int i1 = ((b * kR + 1) * kH + h) * kT + t;
  float z0 = g_z[i0], z1 = g_z[i1];
  float m = fmaxf(z0, z1);
  float e0 = expf(z0 - m), e1 = expf(z1 - m);
  float inv = 1.0f / (e0 + e1);
  float val = (e0 * g_o[(size_t)i0 * kD + d] + e1 * g_o[(size_t)i1 * kD + d]) * inv;
  g_comb[(size_t)(t * kB + b) * kE + h * kD + d] = val;
}

// ---------------- launch ----------------
extern "C" void kernel_launch(void* const* d_in, const int* in_sizes, int n_in,
                              void* d_out, int out_size) {
  (void)in_sizes; (void)n_in; (void)out_size;
  const float* query = (const float*)d_in[0];
  // d_in[1] (key) is unused: share_kq=True
  const float* value = (const float*)d_in[2];
  const float* Wq = (const float*)d_in[3];
  const float* bq = (const float*)d_in[4];
  const float* Wv = (const float*)d_in[5];
  const float* bv = (const float*)d_in[6];
  const float* Wo = (const float*)d_in[7];
  const float* bo = (const float*)d_in[8];
  const float* hw = (const float*)d_in[9];
  float* out = (float*)d_out;

  float *pQF, *pV, *pComb;
  cudaGetSymbolAddress((void**)&pQF, g_QF);
  cudaGetSymbolAddress((void**)&pV, g_V);
  cudaGetSymbolAddress((void**)&pComb, g_comb);

  dim3 ggrid(kE / 128, kTB / 128);
  sgemm128<<<ggrid, 256>>>(query, Wq, bq, pQF, kTB, kE, kE);
  sgemm128<<<ggrid, 256>>>(value, Wv, bv, pV, kTB, kE, kE);

  normalize_kernel<<<kTB, 256>>>();

  int hash_warps = kTB * kH * 2;
  hash_kernel<<<(hash_warps * 32) / 256, 256>>>(hw);

  sort_kernel<<<dim3(kB * kR * kH, 2), 256>>>();

  mask_kernel<<<kB * kR * kH * kC, 128>>>();

  cudaFuncSetAttribute(attn_kernel, cudaFuncAttributeMaxDynamicSharedMemorySize,
                       ATTN_SMEM);
  attn_kernel<<<kB * kR * kH * kC, 256, ATTN_SMEM>>>();

  combine_kernel<<<(kB * kH * kT * kD) / 256, 256>>>();

  sgemm128<<<ggrid, 256>>>(pComb, Wo, bo, out, kTB, kE, kE);
}

// round 2
// speedup vs baseline: 1.0514x; 1.0514x over previous
#include <cuda_runtime.h>
#include <math.h>

// Problem constants
constexpr int kT = 2048;
constexpr int kB = 2;
constexpr int kE = 1024;
constexpr int kH = 8;
constexpr int kD = 128;
constexpr int kR = 2;
constexpr int kNH = 8;       // NHASH
constexpr int kCH = 32;      // CHUNK
constexpr int kC = kT / kCH; // 64 chunks
constexpr int kM = 3 * kCH;  // 96 window keys
constexpr int kTB = kT * kB; // 4096 rows

constexpr float kScale = 0.08838834764831845f; // D^-0.5
constexpr float kInfM = 1.0e16f;
constexpr float kBigM = 1.0e8f;
constexpr float kLog2 = 0.6931471805599453f;

// ---------------- device scratch ----------------
__device__ float g_QF[kTB * kE];    // raw projected q
__device__ float g_Q[kTB * kE];     // scaled q      [t,b,h,d]
__device__ float g_K[kTB * kE];     // normalized q  [t,b,h,d]
__device__ float g_V[kTB * kE];     // projected v
__device__ float g_comb[kTB * kE];  // combined attention out [t,b,e]
__device__ float g_o[kB * kR * kH * kT * kD];
__device__ float g_z[kB * kR * kH * kT];
__device__ int g_qh[kT * kB * kR * kH];
__device__ int g_kh[kT * kB * kR * kH];
__device__ int g_pq[kB * kR * kH * kT];
__device__ int g_pk[kB * kR * kH * kT];
__device__ int g_invq[kB * kR * kH * kT];
__device__ unsigned g_mask[kB * kR * kH * kC * (kT / 32)];

// ---------------- SGEMM: C[M,N] = A[M,K] @ B[K,N] + bias ----------------
// 128x128 block, BK=16, 256 threads, 8x8 microtile. Assumes M,N,K % 128/16 == 0.
__global__ __launch_bounds__(256) void sgemm128(
    const float* __restrict__ A, const float* __restrict__ Bm,
    const float* __restrict__ bias, float* __restrict__ Cc,
    int M, int N, int K) {
  __shared__ float As[16][128];
  __shared__ float Bs[16][128];
  int tid = threadIdx.x;
  int tx = tid & 15, ty = tid >> 4;
  int row0 = blockIdx.y * 128;
  int col0 = blockIdx.x * 128;
  float acc[8][8];
#pragma unroll
  for (int i = 0; i < 8; i++)
#pragma unroll
    for (int j = 0; j < 8; j++) acc[i][j] = 0.f;

  for (int k0 = 0; k0 < K; k0 += 16) {
#pragma unroll
    for (int i = 0; i < 2; i++) {
      int idx = tid + i * 256;          // 0..511
      int rr = idx >> 2;                // 0..127
      int c4 = (idx & 3) << 2;          // 0,4,8,12
      float4 v = *(const float4*)(A + (size_t)(row0 + rr) * K + k0 + c4);
      As[c4 + 0][rr] = v.x; As[c4 + 1][rr] = v.y;
      As[c4 + 2][rr] = v.z; As[c4 + 3][rr] = v.w;
    }
#pragma unroll
    for (int i = 0; i < 2; i++) {
      int idx = tid + i * 256;
      int rr = idx >> 5;                // 0..15
      int cc = (idx & 31) << 2;         // 0..124
      *(float4*)&Bs[rr][cc] = *(const float4*)(Bm + (size_t)(k0 + rr) * N + col0 + cc);
    }
    __syncthreads();
#pragma unroll
    for (int kk = 0; kk < 16; kk++) {
      float a[8], bb[8];
      *(float4*)a = *(float4*)&As[kk][ty * 8];
      *(float4*)(a + 4) = *(float4*)&As[kk][ty * 8 + 4];
      *(float4*)bb = *(float4*)&Bs[kk][tx * 8];
      *(float4*)(bb + 4) = *(float4*)&Bs[kk][tx * 8 + 4];
#pragma unroll
      for (int i = 0; i < 8; i++)
#pragma unroll
        for (int j = 0; j < 8; j++) acc[i][j] += a[i] * bb[j];
    }
    __syncthreads();
  }
#pragma unroll
  for (int i = 0; i < 8; i++) {
    int row = row0 + ty * 8 + i;
#pragma unroll
    for (int j4 = 0; j4 < 8; j4 += 4) {
      int col = col0 + tx * 8 + j4;
      float4 bv = *(const float4*)(bias + col);
      float4 o;
      o.x = acc[i][j4 + 0] + bv.x;
      o.y = acc[i][j4 + 1] + bv.y;
      o.z = acc[i][j4 + 2] + bv.z;
      o.w = acc[i][j4 + 3] + bv.w;
      *(float4*)(Cc + (size_t)row * N + col) = o;
    }
  }
}

// ---------------- normalize + scale ----------------
// block per row (t*B+b): K = QF/||QF||_E, Q = QF * scale
__global__ __launch_bounds__(256) void normalize_kernel() {
  int row = blockIdx.x;
  const float* x = g_QF + (size_t)row * kE;
  __shared__ float red[256];
  int tid = threadIdx.x;
  float s = 0.f;
#pragma unroll
  for (int i = 0; i < 4; i++) {
    float v = x[tid + i * 256];
    s += v * v;
  }
  red[tid] = s;
  __syncthreads();
  for (int off = 128; off > 0; off >>= 1) {
    if (tid < off) red[tid] += red[tid + off];
    __syncthreads();
  }
  float invn = 1.0f / sqrtf(red[0]);
#pragma unroll
  for (int i = 0; i < 4; i++) {
    int e = tid + i * 256;
    float v = x[e];
    g_Q[(size_t)row * kE + e] = v * kScale;
    g_K[(size_t)row * kE + e] = v * invn;
  }
}

// ---------------- hash kernel ----------------
// one warp per (tb, h, src); computes both rounds' buckets
__global__ __launch_bounds__(256) void hash_kernel(const float* __restrict__ hw) {
  int gw = (blockIdx.x * 256 + threadIdx.x) >> 5;
  int lane = threadIdx.x & 31;
  int src = gw & 1;
  int item = gw >> 1;      // tb*H + h
  int h = item & 7;
  int tb = item >> 3;
  const float* x = (src ? g_K : g_Q) + (size_t)tb * kE + h * kD;
  float acc[2][4] = {{0, 0, 0, 0}, {0, 0, 0, 0}};
#pragma unroll
  for (int i = 0; i < 4; i++) {
    int d = lane + i * 32;
    float xv = x[d];
#pragma unroll
    for (int r = 0; r < 2; r++) {
      float4 w = *(const float4*)(hw + (size_t)(((r * kH + h) * kD + d)) * 4);
      acc[r][0] += xv * w.x;
      acc[r][1] += xv * w.y;
      acc[r][2] += xv * w.z;
      acc[r][3] += xv * w.w;
    }
  }
#pragma unroll
  for (int r = 0; r < 2; r++)
#pragma unroll
    for (int n = 0; n < 4; n++)
      for (int off = 16; off; off >>= 1)
        acc[r][n] += __shfl_xor_sync(0xffffffffu, acc[r][n], off);
  if (lane == 0) {
    int* outp = src ? g_kh : g_qh;
#pragma unroll
    for (int r = 0; r < 2; r++) {
      float best = acc[r][0];
      int bi = 0;
#pragma unroll
      for (int n = 1; n < 4; n++)
        if (acc[r][n] > best) { best = acc[r][n]; bi = n; }
#pragma unroll
      for (int n = 0; n < 4; n++)
        if (-acc[r][n] > best) { best = -acc[r][n]; bi = 4 + n; }
      outp[(tb * kR + r) * kH + h] = bi;
    }
  }
}

// ---------------- stable counting sort per (b,r,h) ----------------
// grid.x = B*R*H (32), grid.y = 2 (0: q-sort + inverse, 1: k-sort)
__global__ __launch_bounds__(256) void sort_kernel() {
  int brh = blockIdx.x;
  int which = blockIdx.y;
  int h = brh & 7;
  int r = (brh >> 3) & 1;
  int b = brh >> 4;
  const int* hv = which ? g_kh : g_qh;
  int* perm = (which ? g_pk : g_pq) + brh * kT;
  __shared__ int shv[kT];
  __shared__ int cnt[kNH];
  __shared__ int offs[kNH];
  int tid = threadIdx.x;
  if (tid < kNH) cnt[tid] = 0;
  __syncthreads();
  for (int t = tid; t < kT; t += 256) {
    int v = hv[(t * kB + b) * (kR * kH) + r * kH + h];
    shv[t] = v;
    atomicAdd(&cnt[v], 1);
  }
  __syncthreads();
  if (tid == 0) {
    int s = 0;
    for (int i = 0; i < kNH; i++) { offs[i] = s; s += cnt[i]; }
  }
  __syncthreads();
  if (tid < kNH) {
    int bkt = tid;
    int pos = offs[bkt];
    for (int t = 0; t < kT; t++) {
      if (shv[t] == bkt) {
        perm[pos] = t;
        if (!which) g_invq[brh * kT + t] = pos;
        pos++;
      }
    }
  }
}

// ---------------- per-chunk window bitmask ----------------
// block per (brh, c): bitset over key token ids in the 96-key window
__global__ __launch_bounds__(128) void mask_kernel() {
  int blk = blockIdx.x;  // brh*kC + c
  int c = blk & (kC - 1);
  int brh = blk >> 6;
  unsigned* mw = g_mask + (size_t)blk * (kT / 32);
  int tid = threadIdx.x;
  if (tid < kT / 32) mw[tid] = 0u;
  __syncthreads();
  if (tid < kM) {
    int cc2 = (c + (tid >> 5) + kC - 1) & (kC - 1);
    int pos = cc2 * kCH + (tid & 31);
    int id = g_pk[brh * kT + pos];
    atomicOr(&mw[id >> 5], 1u << (id & 31));
  }
}

// ---------------- attention kernel ----------------
constexpr int kQS = 132;  // padded row stride for smem tiles
constexpr int ATTN_SMEM =
    (32 * kQS + 96 * kQS + 96 * kQS + 32 * 96 + 64) * 4 + (32 * 3 + 96 * 2) * 4;

__global__ __launch_bounds__(256, 1) void attn_kernel() {
  extern __shared__ float sm[];
  float* sq = sm;                    // 32 x 132
  float* sk = sq + 32 * kQS;         // 96 x 132
  float* sv = sk + 96 * kQS;         // 96 x 132
  float* sc = sv + 96 * kQS;         // 32 x 96
  float* rinv = sc + 32 * 96;        // 32
  float* rowz = rinv + 32;           // 32
  int* qid = (int*)(rowz + 32);      // 32
  int* qhh = qid + 32;               // 32
  int* oc2 = qhh + 32;               // 32
  int* kid = oc2 + 32;               // 96
  int* khh = kid + 96;               // 96

  int blk = blockIdx.x;
  int c = blk & (kC - 1);
  int brh = blk >> 6;
  int h = brh & 7;
  int r = (brh >> 3) & 1;
  int b = brh >> 4;
  int brho = (b * kR + (1 - r)) * kH + h;  // other round
  int tid = threadIdx.x;

  if (tid < 32) {
    int ts = c * kCH + tid;
    int tok = g_pq[brh * kT + ts];
    qid[tid] = tok;
    qhh[tid] = g_qh[(tok * kB + b) * (kR * kH) + r * kH + h];
    oc2[tid] = g_invq[brho * kT + tok] >> 5;  // /CHUNK
  } else if (tid < 128) {
    int m = tid - 32;  // 0..95
    int cc2 = (c + (m >> 5) + kC - 1) & (kC - 1);
    int pos = cc2 * kCH + (m & 31);
    int tokk = g_pk[brh * kT + pos];
    kid[m] = tokk;
    khh[m] = g_kh[(tokk * kB + b) * (kR * kH) + r * kH + h];
  }
  __syncthreads();

  // load q tile: 32 rows x 32 float4
#pragma unroll
  for (int i = 0; i < 4; i++) {
    int idx = tid + i * 256;
    int l = idx >> 5, d4 = idx & 31;
    float4 v = *(const float4*)(g_Q + (size_t)(qid[l] * kB + b) * kE + h * kD + d4 * 4);
    *(float4*)&sq[l * kQS + d4 * 4] = v;
  }
  // load k/v tiles: 96 rows x 32 float4 each
#pragma unroll
  for (int i = 0; i < 12; i++) {
    int idx = tid + i * 256;
    int m = idx >> 5, d4 = idx & 31;
    size_t base = (size_t)(kid[m] * kB + b) * kE + h * kD + d4 * 4;
    *(float4*)&sk[m * kQS + d4 * 4] = *(const float4*)(g_K + base);
    *(float4*)&sv[m * kQS + d4 * 4] = *(const float4*)(g_V + base);
  }
  __syncthreads();

  // scores: 8 threads per row, 12 key columns each
  {
    int l = tid >> 3, sub = tid & 7;
    float acc[12];
#pragma unroll
    for (int j = 0; j < 12; j++) acc[j] = 0.f;
    const float* qrow = sq + l * kQS;
    for (int d = 0; d < kD; d++) {
      float qv = qrow[d];
#pragma unroll
      for (int j = 0; j < 12; j++) acc[j] += qv * sk[(sub + j * 8) * kQS + d];
    }
    int myqh = qhh[l], myqid = qid[l];
    const unsigned* mw = g_mask + (size_t)(brho * kC + oc2[l]) * (kT / 32);
#pragma unroll
    for (int j = 0; j < 12; j++) {
      int m = sub + j * 8;
      float s = acc[j];
      if (myqh != khh[m]) s -= kInfM;       // mask_different_hashes
      int id = kid[m];
      if (myqid == id) s -= kBigM;          // mask_current
      if ((mw[id >> 5] >> (id & 31)) & 1u) s -= kLog2;  // cross-round dup
      sc[l * 96 + m] = s;
    }
  }
  __syncthreads();

  // softmax per row (warp per 4 rows), keep logsumexp z
  {
    int w = tid >> 5, lane = tid & 31;
    for (int rr = 0; rr < 4; rr++) {
      int l = w * 4 + rr;
      float mx = -3.0e38f;
      for (int m = lane; m < 96; m += 32) mx = fmaxf(mx, sc[l * 96 + m]);
      for (int off = 16; off; off >>= 1)
        mx = fmaxf(mx, __shfl_xor_sync(0xffffffffu, mx, off));
      float s = 0.f;
      for (int m = lane; m < 96; m += 32) {
        float e = expf(sc[l * 96 + m] - mx);
        sc[l * 96 + m] = e;
        s += e;
      }
      for (int off = 16; off; off >>= 1)
        s += __shfl_xor_sync(0xffffffffu, s, off);
      if (lane == 0) {
        rinv[l] = 1.0f / s;
        rowz[l] = mx + logf(s);
      }
    }
  }
  __syncthreads();

  // output: scatter directly to original token order
#pragma unroll
  for (int it = 0; it < 16; it++) {
    int idx = tid + it * 256;
    int l = idx >> 7, d = idx & 127;
    float acc = 0.f;
#pragma unroll 4
    for (int m = 0; m < 96; m++) acc += sc[l * 96 + m] * sv[m * kQS + d];
    g_o[(size_t)(brh * kT + qid[l]) * kD + d] = acc * rinv[l];
  }
  if (tid < 32) g_z[brh * kT + qid[tid]] = rowz[tid];
}

// ---------------- combine rounds ----------------
__global__ __launch_bounds__(256) void combine_kernel() {
  int idx = blockIdx.x * 256 + threadIdx.x;  // over B*H*T*D = 4194304
  int d = idx & 127;
  int t = (idx >> 7) & (kT - 1);
  int h = (idx >> 18) & 7;
  int b = idx >> 21;
  int i0 = ((b * kR + 0) * kH + h) * kT + t;
  int i1 = ((b * kR + 1) * kH + h) * kT + t;
  float z0 = g_z[i0], z1 = g_z[i1];
  float m = fmaxf(z0, z1);
  float e0 = expf(z0 - m), e1 = expf(z1 - m);
  float inv = 1.0f / (e0 + e1);
  float val = (e0 * g_o[(size_t)i0 * kD + d] + e1 * g_o[(size_t)i1 * kD + d]) * inv;
  g_comb[(size_t)(t * kB + b) * kE + h * kD + d] = val;
}

// ---------------- launch ----------------
extern "C" void kernel_launch(void* const* d_in, const int* in_sizes, int n_in,
                              void* d_out, int out_size) {
  (void)in_sizes; (void)n_in; (void)out_size;
  const float* query = (const float*)d_in[0];
  // d_in[1] (key) is unused: share_kq=True
  const float* value = (const float*)d_in[2];
  const float* Wq = (const float*)d_in[3];
  const float* bq = (const float*)d_in[4];
  const float* Wv = (const float*)d_in[5];
  const float* bv = (const float*)d_in[6];
  const float* Wo = (const float*)d_in[7];
  const float* bo = (const float*)d_in[8];
  const float* hw = (const float*)d_in[9];
  float* out = (float*)d_out;

  float *pQF, *pV, *pComb;
  cudaGetSymbolAddress((void**)&pQF, g_QF);
  cudaGetSymbolAddress((void**)&pV, g_V);
  cudaGetSymbolAddress((void**)&pComb, g_comb);

  dim3 ggrid(kE / 128, kTB / 128);
  sgemm128<<<ggrid, 256>>>(query, Wq, bq, pQF, kTB, kE, kE);
  sgemm128<<<ggrid, 256>>>(value, Wv, bv, pV, kTB, kE, kE);

  normalize_kernel<<<kTB, 256>>>();

  int hash_warps = kTB * kH * 2;
  hash_kernel<<<(hash_warps * 32) / 256, 256>>>(hw);

  sort_kernel<<<dim3(kB * kR * kH, 2), 256>>>();

  mask_kernel<<<kB * kR * kH * kC, 128>>>();

  cudaFuncSetAttribute(attn_kernel, cudaFuncAttributeMaxDynamicSharedMemorySize,
                       ATTN_SMEM);
  attn_kernel<<<kB * kR * kH * kC, 256, ATTN_SMEM>>>();

  combine_kernel<<<(kB * kH * kT * kD) / 256, 256>>>();

  sgemm128<<<ggrid, 256>>>(pComb, Wo, bo, out, kTB, kE, kE);
}

// round 5
// speedup vs baseline: 1.3772x; 1.3099x over previous
#include <cuda_runtime.h>
#include <cuda_bf16.h>
#include <math.h>
#include <stdint.h>

// ---------------- problem constants ----------------
constexpr int kT = 2048;
constexpr int kB = 2;
constexpr int kE = 1024;
constexpr int kH = 8;
constexpr int kD = 128;
constexpr int kR = 2;
constexpr int kNH = 8;
constexpr int kCH = 32;
constexpr int kC = kT / kCH;  // 64
constexpr int kM = 3 * kCH;   // 96
constexpr int kTB = kT * kB;  // 4096

constexpr float kScale = 0.08838834764831845f;  // D^-0.5
constexpr float kInfM = 1.0e16f;
constexpr float kBigM = 1.0e8f;
constexpr float kLog2 = 0.6931471805599453f;

// ---------------- device scratch ----------------
__device__ float g_QF[kTB * kE];
__device__ float g_Q[kTB * kE];
__device__ float g_K[kTB * kE];
__device__ float g_V[kTB * kE];
__device__ float g_comb[kTB * kE];
__device__ float g_o[kB * kR * kH * kT * kD];
__device__ float g_z[kB * kR * kH * kT];
__device__ int g_hash[kTB * 16];  // [tb][r*8+h]
__device__ int g_pq[kB * kR * kH * kT];
__device__ int g_invq[kB * kR * kH * kT];
__device__ unsigned g_mask[kB * kR * kH * kC * (kT / 32)];
__device__ float g_Mq[kE * 64];
__device__ float g_cq[64];
// A split (reused across the three GEMMs, sequential stream ordering)
__device__ __nv_bfloat16 g_Ahi[kTB * kE];
__device__ __nv_bfloat16 g_Alo[kTB * kE];
// transposed + hi/lo split weights, [N=1024][K=1024]
__device__ __nv_bfloat16 g_WqThi[kE * kE];
__device__ __nv_bfloat16 g_WqTlo[kE * kE];
__device__ __nv_bfloat16 g_WvThi[kE * kE];
__device__ __nv_bfloat16 g_WvTlo[kE * kE];
__device__ __nv_bfloat16 g_WoThi[kE * kE];
__device__ __nv_bfloat16 g_WoTlo[kE * kE];

// ---------------- helpers ----------------
__device__ __forceinline__ uint32_t smem_u32(const void* p) {
  uint32_t a;
  asm("{ .reg .u64 t; cvta.to.shared.u64 t, %1; cvt.u32.u64 %0, t; }"
      : "=r"(a) : "l"(p));
  return a;
}
__device__ __forceinline__ void ldsm_x4(uint32_t* r, uint32_t addr) {
  asm volatile(
      "ldmatrix.sync.aligned.m8n8.x4.shared.b16 {%0,%1,%2,%3}, [%4];"
      : "=r"(r[0]), "=r"(r[1]), "=r"(r[2]), "=r"(r[3]) : "r"(addr));
}
// B operand from [n][k] row-major smem: NON-trans x2 delivers the
// (n = lane/4, k-pair) fragment layout mma.m16n8k16 expects.
__device__ __forceinline__ void ldsm_x2(uint32_t* r, uint32_t addr) {
  asm volatile(
      "ldmatrix.sync.aligned.m8n8.x2.shared.b16 {%0,%1}, [%2];"
      : "=r"(r[0]), "=r"(r[1]) : "r"(addr));
}
__device__ __forceinline__ void mma16816(float* d, const uint32_t* a,
                                         const uint32_t* b) {
  asm volatile(
      "mma.sync.aligned.m16n8k16.row.col.f32.bf16.bf16.f32 "
      "{%0,%1,%2,%3}, {%4,%5,%6,%7}, {%8,%9}, {%0,%1,%2,%3};"
      : "+f"(d[0]), "+f"(d[1]), "+f"(d[2]), "+f"(d[3])
      : "r"(a[0]), "r"(a[1]), "r"(a[2]), "r"(a[3]), "r"(b[0]), "r"(b[1]));
}
__device__ __forceinline__ void cp16(uint32_t dst, const void* src) {
  asm volatile("cp.async.cg.shared.global [%0], [%1], 16;" ::"r"(dst),
               "l"(src));
}

// ---------------- A fp32 -> bf16 hi/lo split ----------------
__global__ __launch_bounds__(256) void asplit_kernel(
    const float* __restrict__ A) {
  int idx = blockIdx.x * 256 + threadIdx.x;  // over 1M float4s
  float4 v = ((const float4*)A)[idx];
  __nv_bfloat16 h0 = __float2bfloat16(v.x), h1 = __float2bfloat16(v.y);
  __nv_bfloat16 h2 = __float2bfloat16(v.z), h3 = __float2bfloat16(v.w);
  __nv_bfloat16 l0 = __float2bfloat16(v.x - __bfloat162float(h0));
  __nv_bfloat16 l1 = __float2bfloat16(v.y - __bfloat162float(h1));
  __nv_bfloat16 l2 = __float2bfloat16(v.z - __bfloat162float(h2));
  __nv_bfloat16 l3 = __float2bfloat16(v.w - __bfloat162float(h3));
  __nv_bfloat162 ph0 = {h0, h1}, ph1 = {h2, h3};
  __nv_bfloat162 pl0 = {l0, l1}, pl1 = {l2, l3};
  uint2 uh = {*(uint32_t*)&ph0, *(uint32_t*)&ph1};
  uint2 ul = {*(uint32_t*)&pl0, *(uint32_t*)&pl1};
  ((uint2*)g_Ahi)[idx] = uh;
  ((uint2*)g_Alo)[idx] = ul;
}

// ---------------- weight transpose + bf16 hi/lo split ----------------
__global__ __launch_bounds__(256) void wsplit_kernel(
    const float* __restrict__ W, __nv_bfloat16* __restrict__ hi,
    __nv_bfloat16* __restrict__ lo) {
  __shared__ float t[32][33];
  int bx = blockIdx.x * 32;  // n block
  int by = blockIdx.y * 32;  // k block
  int x = threadIdx.x, y = threadIdx.y;
#pragma unroll
  for (int i = 0; i < 32; i += 8)
    t[y + i][x] = W[(size_t)(by + y + i) * kE + bx + x];
  __syncthreads();
#pragma unroll
  for (int i = 0; i < 32; i += 8) {
    float v = t[x][y + i];  // = W[by+x][bx+y+i]
    __nv_bfloat16 h = __float2bfloat16(v);
    __nv_bfloat16 l = __float2bfloat16(v - __bfloat162float(h));
    size_t o = (size_t)(bx + y + i) * kE + by + x;
    hi[o] = h;
    lo[o] = l;
  }
}

// ---------------- bf16x3 HMMA GEMM ----------------
// C[4096,1024] = A @ W + bias, A pre-split (g_Ahi/g_Alo), W transposed/split.
// 128x128 tile, BK=32, 2-stage cp.async pipeline. smem row stride 80B.
constexpr int kTileB = 128 * 80;       // one operand tile (rows x 80B)
constexpr int kStageB = 4 * kTileB;    // Ahi, Alo, Bhi, Blo
constexpr int kGSmem = 2 * kStageB;    // 81920

__global__ __launch_bounds__(256) void gemm_mma(
    const __nv_bfloat16* __restrict__ Bhi, const __nv_bfloat16* __restrict__ Blo,
    const float* __restrict__ bias, float* __restrict__ C) {
  extern __shared__ char smc[];
  uint32_t sbase = smem_u32(smc);
  int tid = threadIdx.x;
  int lane = tid & 31, wid = tid >> 5;
  int row0 = blockIdx.y * 128, col0 = blockIdx.x * 128;
  int m0w = (wid >> 1) * 32, n0w = (wid & 1) * 64;

  float acc[2][8][4];
#pragma unroll
  for (int i = 0; i < 2; i++)
#pragma unroll
    for (int j = 0; j < 8; j++)
#pragma unroll
      for (int q = 0; q < 4; q++) acc[i][j][q] = 0.f;

  const __nv_bfloat16* srcs[4] = {g_Ahi, g_Alo, Bhi, Blo};

  auto issue = [&](int ch, int s) {
    int k0 = ch * 32;
#pragma unroll
    for (int t = 0; t < 4; t++) {
      const __nv_bfloat16* src = srcs[t];
      int base0 = (t < 2) ? row0 : col0;
#pragma unroll
      for (int i = 0; i < 2; i++) {
        int idx = tid + i * 256;
        int row = idx >> 2, seg = idx & 3;
        uint32_t dst = sbase + s * kStageB + t * kTileB + row * 80 + seg * 16;
        cp16(dst, src + (size_t)(base0 + row) * kE + k0 + seg * 8);
      }
    }
    asm volatile("cp.async.commit_group;");
  };

  issue(0, 0);
  for (int ch = 0; ch < 32; ch++) {
    int s = ch & 1;
    if (ch + 1 < 32) {
      issue(ch + 1, s ^ 1);
      asm volatile("cp.async.wait_group 1;");
    } else {
      asm volatile("cp.async.wait_group 0;");
    }
    __syncthreads();
    // passes: 0 = Ahi*Bhi, 1 = Ahi*Blo, 2 = Alo*Bhi
#pragma unroll
    for (int pass = 0; pass < 3; pass++) {
      uint32_t abase = sbase + s * kStageB + ((pass == 2) ? kTileB : 0);
      uint32_t bbase = sbase + s * kStageB + 2 * kTileB +
                       ((pass == 1) ? kTileB : 0);
#pragma unroll
      for (int k16 = 0; k16 < 2; k16++) {
        uint32_t a[2][4], bfr[8][2];
#pragma unroll
        for (int mt = 0; mt < 2; mt++)
          ldsm_x4(a[mt], abase + (m0w + mt * 16 + (lane & 15)) * 80 +
                             (k16 * 16 + (lane >> 4) * 8) * 2);
#pragma unroll
        for (int nt = 0; nt < 8; nt++)
          ldsm_x2(bfr[nt], bbase + (n0w + nt * 8 + (lane & 7)) * 80 +
                               (k16 * 16 + ((lane >> 3) & 1) * 8) * 2);
#pragma unroll
        for (int mt = 0; mt < 2; mt++)
#pragma unroll
          for (int nt = 0; nt < 8; nt++) mma16816(acc[mt][nt], a[mt], bfr[nt]);
      }
    }
    __syncthreads();
  }
  // epilogue
#pragma unroll
  for (int mt = 0; mt < 2; mt++) {
#pragma unroll
    for (int nt = 0; nt < 8; nt++) {
      int r = row0 + m0w + mt * 16 + (lane >> 2);
      int cc = col0 + n0w + nt * 8 + (lane & 3) * 2;
      float2 b0 = *(const float2*)(bias + cc);
      float2 v0 = {acc[mt][nt][0] + b0.x, acc[mt][nt][1] + b0.y};
      *(float2*)(C + (size_t)r * kE + cc) = v0;
      float2 v1 = {acc[mt][nt][2] + b0.x, acc[mt][nt][3] + b0.y};
      *(float2*)(C + (size_t)(r + 8) * kE + cc) = v1;
    }
  }
}

// ---------------- exact hash path ----------------
__global__ __launch_bounds__(256) void prepM_kernel(
    const float* __restrict__ Wq, const float* __restrict__ bq,
    const float* __restrict__ hw) {
  int j = blockIdx.x * 256 + threadIdx.x;  // e*64 + col
  int col = j & 63;
  int e = j >> 6;
  int rh = col >> 2;
  int n = col & 3;
  int h = rh & 7;
  float s = 0.f;
  for (int d = 0; d < kD; d++)
    s += Wq[(size_t)e * kE + h * kD + d] * hw[(rh * kD + d) * 4 + n];
  g_Mq[e * 64 + col] = s;
  if (e == 0) {
    float c = 0.f;
    for (int d = 0; d < kD; d++)
      c += bq[h * kD + d] * hw[(rh * kD + d) * 4 + n];
    g_cq[col] = c;
  }
}

__global__ __launch_bounds__(256) void linhash_kernel(
    const float* __restrict__ query) {
  __shared__ float slin[8][64];
  int warp = threadIdx.x >> 5, lane = threadIdx.x & 31;
  int tb = blockIdx.x * 8 + warp;
  float acc0 = g_cq[lane], acc1 = g_cq[lane + 32];
  for (int e0 = 0; e0 < kE; e0 += 32) {
    float xv = query[(size_t)tb * kE + e0 + lane];
#pragma unroll
    for (int l2 = 0; l2 < 32; l2++) {
      float v = __shfl_sync(0xffffffffu, xv, l2);
      acc0 += v * g_Mq[(e0 + l2) * 64 + lane];
      acc1 += v * g_Mq[(e0 + l2) * 64 + lane + 32];
    }
  }
  slin[warp][lane] = acc0;
  slin[warp][lane + 32] = acc1;
  __syncwarp();
  if (lane < 16) {
    const float* p = &slin[warp][lane * 4];
    float best = p[0];
    int bi = 0;
#pragma unroll
    for (int n = 1; n < 4; n++)
      if (p[n] > best) { best = p[n]; bi = n; }
#pragma unroll
    for (int n = 0; n < 4; n++)
      if (-p[n] > best) { best = -p[n]; bi = 4 + n; }
    g_hash[tb * 16 + lane] = bi;
  }
}

// ---------------- normalize + scale ----------------
__global__ __launch_bounds__(256) void normalize_kernel() {
  int row = blockIdx.x;
  const float* x = g_QF + (size_t)row * kE;
  __shared__ float red[256];
  int tid = threadIdx.x;
  float s = 0.f;
#pragma unroll
  for (int i = 0; i < 4; i++) {
    float v = x[tid + i * 256];
    s += v * v;
  }
  red[tid] = s;
  __syncthreads();
  for (int off = 128; off > 0; off >>= 1) {
    if (tid < off) red[tid] += red[tid + off];
    __syncthreads();
  }
  float invn = 1.0f / sqrtf(red[0]);
#pragma unroll
  for (int i = 0; i < 4; i++) {
    int e = tid + i * 256;
    float v = x[e];
    g_Q[(size_t)row * kE + e] = v * kScale;
    g_K[(size_t)row * kE + e] = v * invn;
  }
}

// ---------------- stable counting sort per (b,r,h) ----------------
__global__ __launch_bounds__(256) void sort_kernel() {
  int brh = blockIdx.x;
  int h = brh & 7;
  int r = (brh >> 3) & 1;
  int b = brh >> 4;
  __shared__ int shv[kT];
  __shared__ int cnt[kNH];
  __shared__ int offs[kNH];
  int tid = threadIdx.x;
  if (tid < kNH) cnt[tid] = 0;
  __syncthreads();
  for (int t = tid; t < kT; t += 256) {
    int v = g_hash[(t * kB + b) * 16 + r * 8 + h];
    shv[t] = v;
    atomicAdd(&cnt[v], 1);
  }
  __syncthreads();
  if (tid == 0) {
    int s = 0;
    for (int i = 0; i < kNH; i++) {
      offs[i] = s;
      s += cnt[i];
    }
  }
  __syncthreads();
  if (tid < kNH) {
    int bkt = tid;
    int pos = offs[bkt];
    for (int t = 0; t < kT; t++) {
      if (shv[t] == bkt) {
        g_pq[brh * kT + pos] = t;
        g_invq[brh * kT + t] = pos;
        pos++;
      }
    }
  }
}

// ---------------- per-chunk window bitmask ----------------
__global__ __launch_bounds__(128) void mask_kernel() {
  int blk = blockIdx.x;
  int c = blk & (kC - 1);
  int brh = blk >> 6;
  unsigned* mw = g_mask + (size_t)blk * (kT / 32);
  int tid = threadIdx.x;
  if (tid < kT / 32) mw[tid] = 0u;
  __syncthreads();
  if (tid < kM) {
    int cc2 = (c + (tid >> 5) + kC - 1) & (kC - 1);
    int pos = cc2 * kCH + (tid & 31);
    int id = g_pq[brh * kT + pos];
    atomicOr(&mw[id >> 5], 1u << (id & 31));
  }
}

// ---------------- attention ----------------
constexpr int kQS = 132;
constexpr int ATTN_SMEM =
    (32 * kQS + 96 * kQS + 96 * kQS + 32 * 96 + 64) * 4 + (32 * 3 + 96 * 2) * 4;

__global__ __launch_bounds__(256, 1) void attn_kernel() {
  extern __shared__ float sm[];
  float* sq = sm;
  float* sk = sq + 32 * kQS;
  float* sv = sk + 96 * kQS;
  float* sc = sv + 96 * kQS;
  float* rinv = sc + 32 * 96;
  float* rowz = rinv + 32;
  int* qid = (int*)(rowz + 32);
  int* qhh = qid + 32;
  int* oc2 = qhh + 32;
  int* kid = oc2 + 32;
  int* khh = kid + 96;

  int blk = blockIdx.x;
  int c = blk & (kC - 1);
  int brh = blk >> 6;
  int h = brh & 7;
  int r = (brh >> 3) & 1;
  int b = brh >> 4;
  int brho = (b * kR + (1 - r)) * kH + h;
  int tid = threadIdx.x;

  if (tid < 32) {
    int ts = c * kCH + tid;
    int tok = g_pq[brh * kT + ts];
    qid[tid] = tok;
    qhh[tid] = g_hash[(tok * kB + b) * 16 + r * 8 + h];
    oc2[tid] = g_invq[brho * kT + tok] >> 5;
  } else if (tid < 128) {
    int m = tid - 32;
    int cc2 = (c + (m >> 5) + kC - 1) & (kC - 1);
    int pos = cc2 * kCH + (m & 31);
    int tokk = g_pq[brh * kT + pos];
    kid[m] = tokk;
    khh[m] = g_hash[(tokk * kB + b) * 16 + r * 8 + h];
  }
  __syncthreads();

#pragma unroll
  for (int i = 0; i < 4; i++) {
    int idx = tid + i * 256;
    int l = idx >> 5, d4 = idx & 31;
    float4 v =
        *(const float4*)(g_Q + (size_t)(qid[l] * kB + b) * kE + h * kD + d4 * 4);
    *(float4*)&sq[l * kQS + d4 * 4] = v;
  }
#pragma unroll
  for (int i = 0; i < 12; i++) {
    int idx = tid + i * 256;
    int m = idx >> 5, d4 = idx & 31;
    size_t base = (size_t)(kid[m] * kB + b) * kE + h * kD + d4 * 4;
    *(float4*)&sk[m * kQS + d4 * 4] = *(const float4*)(g_K + base);
    *(float4*)&sv[m * kQS + d4 * 4] = *(const float4*)(g_V + base);
  }
  __syncthreads();

  {
    int l = tid >> 3, sub = tid & 7;
    float acc[12];
#pragma unroll
    for (int j = 0; j < 12; j++) acc[j] = 0.f;
    const float* qrow = sq + l * kQS;
    for (int d = 0; d < kD; d++) {
      float qv = qrow[d];
#pragma unroll
      for (int j = 0; j < 12; j++) acc[j] += qv * sk[(sub + j * 8) * kQS + d];
    }
    int myqh = qhh[l], myqid = qid[l];
    const unsigned* mw = g_mask + (size_t)(brho * kC + oc2[l]) * (kT / 32);
#pragma unroll
    for (int j = 0; j < 12; j++) {
      int m = sub + j * 8;
      float s = acc[j];
      if (myqh != khh[m]) s -= kInfM;
      int id = kid[m];
      if (myqid == id) s -= kBigM;
      if ((mw[id >> 5] >> (id & 31)) & 1u) s -= kLog2;
      sc[l * 96 + m] = s;
    }
  }
  __syncthreads();

  {
    int w = tid >> 5, lane = tid & 31;
    for (int rr = 0; rr < 4; rr++) {
      int l = w * 4 + rr;
      float mx = -3.0e38f;
      for (int m = lane; m < 96; m += 32) mx = fmaxf(mx, sc[l * 96 + m]);
      for (int off = 16; off; off >>= 1)
        mx = fmaxf(mx, __shfl_xor_sync(0xffffffffu, mx, off));
      float s = 0.f;
      for (int m = lane; m < 96; m += 32) {
        float e = expf(sc[l * 96 + m] - mx);
        sc[l * 96 + m] = e;
        s += e;
      }
      for (int off = 16; off; off >>= 1)
        s += __shfl_xor_sync(0xffffffffu, s, off);
      if (lane == 0) {
        rinv[l] = 1.0f / s;
        rowz[l] = mx + logf(s);
      }
    }
  }
  __syncthreads();

#pragma unroll
  for (int it = 0; it < 16; it++) {
    int idx = tid + it * 256;
    int l = idx >> 7, d = idx & 127;
    float acc = 0.f;
#pragma unroll 4
    for (int m = 0; m < 96; m++) acc += sc[l * 96 + m] * sv[m * kQS + d];
    g_o[(size_t)(brh * kT + qid[l]) * kD + d] = acc * rinv[l];
  }
  if (tid < 32) g_z[brh * kT + qid[tid]] = rowz[tid];
}

// ---------------- combine rounds ----------------
__global__ __launch_bounds__(256) void combine_kernel() {
  int idx = blockIdx.x * 256 + threadIdx.x;
  int d = idx & 127;
  int t = (idx >> 7) & (kT - 1);
  int h = (idx >> 18) & 7;
  int b = idx >> 21;
  int i0 = ((b * kR + 0) * kH + h) * kT + t;
  int i1 = ((b * kR + 1) * kH + h) * kT + t;
  float z0 = g_z[i0], z1 = g_z[i1];
  float m = fmaxf(z0, z1);
  float e0 = expf(z0 - m), e1 = expf(z1 - m);
  float inv = 1.0f / (e0 + e1);
  float val =
      (e0 * g_o[(size_t)i0 * kD + d] + e1 * g_o[(size_t)i1 * kD + d]) * inv;
  g_comb[(size_t)(t * kB + b) * kE + h * kD + d] = val;
}

// ---------------- launch ----------------
extern "C" void kernel_launch(void* const* d_in, const int* in_sizes, int n_in,
                              void* d_out, int out_size) {
  (void)in_sizes;
  (void)n_in;
  (void)out_size;
  const float* query = (const float*)d_in[0];
  const float* value = (const float*)d_in[2];
  const float* Wq = (const float*)d_in[3];
  const float* bq = (const float*)d_in[4];
  const float* Wv = (const float*)d_in[5];
  const float* bv = (const float*)d_in[6];
  const float* Wo = (const float*)d_in[7];
  const float* bo = (const float*)d_in[8];
  const float* hw = (const float*)d_in[9];
  float* out = (float*)d_out;

  float *pQF, *pV, *pComb;
  cudaGetSymbolAddress((void**)&pQF, g_QF);
  cudaGetSymbolAddress((void**)&pV, g_V);
  cudaGetSymbolAddress((void**)&pComb, g_comb);
  __nv_bfloat16 *pWqH, *pWqL, *pWvH, *pWvL, *pWoH, *pWoL;
  cudaGetSymbolAddress((void**)&pWqH, g_WqThi);
  cudaGetSymbolAddress((void**)&pWqL, g_WqTlo);
  cudaGetSymbolAddress((void**)&pWvH, g_WvThi);
  cudaGetSymbolAddress((void**)&pWvL, g_WvTlo);
  cudaGetSymbolAddress((void**)&pWoH, g_WoThi);
  cudaGetSymbolAddress((void**)&pWoL, g_WoTlo);

  dim3 tgrid(32, 32);
  dim3 tblk(32, 8);
  wsplit_kernel<<<tgrid, tblk>>>(Wq, pWqH, pWqL);
  wsplit_kernel<<<tgrid, tblk>>>(Wv, pWvH, pWvL);
  wsplit_kernel<<<tgrid, tblk>>>(Wo, pWoH, pWoL);
  prepM_kernel<<<256, 256>>>(Wq, bq, hw);
  linhash_kernel<<<kTB / 8, 256>>>(query);
  sort_kernel<<<kB * kR * kH, 256>>>();
  mask_kernel<<<kB * kR * kH * kC, 128>>>();

  cudaFuncSetAttribute(gemm_mma, cudaFuncAttributeMaxDynamicSharedMemorySize,
                       kGSmem);
  dim3 ggrid(kE / 128, kTB / 128);

  asplit_kernel<<<(kTB * kE / 4) / 256, 256>>>(query);
  gemm_mma<<<ggrid, 256, kGSmem>>>(pWqH, pWqL, bq, pQF);
  normalize_kernel<<<kTB, 256>>>();

  asplit_kernel<<<(kTB * kE / 4) / 256, 256>>>(value);
  gemm_mma<<<ggrid, 256, kGSmem>>>(pWvH, pWvL, bv, pV);

  cudaFuncSetAttribute(attn_kernel, cudaFuncAttributeMaxDynamicSharedMemorySize,
                       ATTN_SMEM);
  attn_kernel<<<kB * kR * kH * kC, 256, ATTN_SMEM>>>();

  combine_kernel<<<(kB * kH * kT * kD) / 256, 256>>>();

  asplit_kernel<<<(kTB * kE / 4) / 256, 256>>>(pComb);
  gemm_mma<<<ggrid, 256, kGSmem>>>(pWoH, pWoL, bo, out);
}

// round 7
// speedup vs baseline: 1.7249x; 1.2524x over previous
#include <cuda_runtime.h>
#include <cuda_bf16.h>
#include <math.h>
#include <stdint.h>

// ---------------- problem constants ----------------
constexpr int kT = 2048;
constexpr int kB = 2;
constexpr int kE = 1024;
constexpr int kH = 8;
constexpr int kD = 128;
constexpr int kR = 2;
constexpr int kNH = 8;
constexpr int kCH = 32;
constexpr int kC = kT / kCH;  // 64
constexpr int kM = 3 * kCH;   // 96
constexpr int kTB = kT * kB;  // 4096

constexpr float kScale = 0.08838834764831845f;  // D^-0.5
constexpr float kInfM = 1.0e16f;
constexpr float kBigM = 1.0e8f;
constexpr float kLog2 = 0.6931471805599453f;

// ---------------- device scratch ----------------
__device__ float g_QF[kTB * kE];
__device__ float g_Q[kTB * kE];
__device__ float g_K[kTB * kE];
__device__ float g_V[kTB * kE];
__device__ float g_o[kB * kR * kH * kT * kD];
__device__ float g_z[kB * kR * kH * kT];
__device__ int g_hash[kTB * 16];  // [tb][r*8+h]
__device__ int g_pq[kB * kR * kH * kT];
__device__ int g_invq[kB * kR * kH * kT];
__device__ unsigned g_mask[kB * kR * kH * kC * (kT / 32)];
__device__ float g_Mq[kE * 64];
__device__ float g_cq[64];
// A split (reused across the three GEMMs, sequential stream ordering)
__device__ __nv_bfloat16 g_Ahi[kTB * kE];
__device__ __nv_bfloat16 g_Alo[kTB * kE];
// transposed + hi/lo split weights, [N=1024][K=1024]
__device__ __nv_bfloat16 g_WqThi[kE * kE];
__device__ __nv_bfloat16 g_WqTlo[kE * kE];
__device__ __nv_bfloat16 g_WvThi[kE * kE];
__device__ __nv_bfloat16 g_WvTlo[kE * kE];
__device__ __nv_bfloat16 g_WoThi[kE * kE];
__device__ __nv_bfloat16 g_WoTlo[kE * kE];

// ---------------- helpers ----------------
__device__ __forceinline__ uint32_t smem_u32(const void* p) {
  uint32_t a;
  asm("{ .reg .u64 t; cvta.to.shared.u64 t, %1; cvt.u32.u64 %0, t; }"
      : "=r"(a) : "l"(p));
  return a;
}
__device__ __forceinline__ void ldsm_x4(uint32_t* r, uint32_t addr) {
  asm volatile(
      "ldmatrix.sync.aligned.m8n8.x4.shared.b16 {%0,%1,%2,%3}, [%4];"
      : "=r"(r[0]), "=r"(r[1]), "=r"(r[2]), "=r"(r[3]) : "r"(addr));
}
// B operand from [n][k] row-major smem: NON-trans x2 delivers the
// (n = lane/4, k-pair) fragment layout mma.m16n8k16 expects.
__device__ __forceinline__ void ldsm_x2(uint32_t* r, uint32_t addr) {
  asm volatile(
      "ldmatrix.sync.aligned.m8n8.x2.shared.b16 {%0,%1}, [%2];"
      : "=r"(r[0]), "=r"(r[1]) : "r"(addr));
}
__device__ __forceinline__ void mma16816(float* d, const uint32_t* a,
                                         const uint32_t* b) {
  asm volatile(
      "mma.sync.aligned.m16n8k16.row.col.f32.bf16.bf16.f32 "
      "{%0,%1,%2,%3}, {%4,%5,%6,%7}, {%8,%9}, {%0,%1,%2,%3};"
      : "+f"(d[0]), "+f"(d[1]), "+f"(d[2]), "+f"(d[3])
      : "r"(a[0]), "r"(a[1]), "r"(a[2]), "r"(a[3]), "r"(b[0]), "r"(b[1]));
}
__device__ __forceinline__ void cp16(uint32_t dst, const void* src) {
  asm volatile("cp.async.cg.shared.global [%0], [%1], 16;" ::"r"(dst),
               "l"(src));
}

// ---------------- A fp32 -> bf16 hi/lo split ----------------
__global__ __launch_bounds__(256) void asplit_kernel(
    const float* __restrict__ A) {
  int idx = blockIdx.x * 256 + threadIdx.x;  // over 1M float4s
  float4 v = ((const float4*)A)[idx];
  __nv_bfloat16 h0 = __float2bfloat16(v.x), h1 = __float2bfloat16(v.y);
  __nv_bfloat16 h2 = __float2bfloat16(v.z), h3 = __float2bfloat16(v.w);
  __nv_bfloat16 l0 = __float2bfloat16(v.x - __bfloat162float(h0));
  __nv_bfloat16 l1 = __float2bfloat16(v.y - __bfloat162float(h1));
  __nv_bfloat16 l2 = __float2bfloat16(v.z - __bfloat162float(h2));
  __nv_bfloat16 l3 = __float2bfloat16(v.w - __bfloat162float(h3));
  __nv_bfloat162 ph0 = {h0, h1}, ph1 = {h2, h3};
  __nv_bfloat162 pl0 = {l0, l1}, pl1 = {l2, l3};
  uint2 uh = {*(uint32_t*)&ph0, *(uint32_t*)&ph1};
  uint2 ul = {*(uint32_t*)&pl0, *(uint32_t*)&pl1};
  ((uint2*)g_Ahi)[idx] = uh;
  ((uint2*)g_Alo)[idx] = ul;
}

// ---------------- weight transpose + bf16 hi/lo split ----------------
__global__ __launch_bounds__(256) void wsplit_kernel(
    const float* __restrict__ W, __nv_bfloat16* __restrict__ hi,
    __nv_bfloat16* __restrict__ lo) {
  __shared__ float t[32][33];
  int bx = blockIdx.x * 32;  // n block
  int by = blockIdx.y * 32;  // k block
  int x = threadIdx.x, y = threadIdx.y;
#pragma unroll
  for (int i = 0; i < 32; i += 8)
    t[y + i][x] = W[(size_t)(by + y + i) * kE + bx + x];
  __syncthreads();
#pragma unroll
  for (int i = 0; i < 32; i += 8) {
    float v = t[x][y + i];  // = W[by+x][bx+y+i]
    __nv_bfloat16 h = __float2bfloat16(v);
    __nv_bfloat16 l = __float2bfloat16(v - __bfloat162float(h));
    size_t o = (size_t)(bx + y + i) * kE + by + x;
    hi[o] = h;
    lo[o] = l;
  }
}

// ---------------- bf16x3 HMMA GEMM ----------------
// C[4096,1024] = A @ W + bias, A pre-split (g_Ahi/g_Alo), W transposed/split.
// 128x128 tile, BK=32, 2-stage cp.async pipeline. smem row stride 80B.
// Fragment-hoisted 3-pass: (a_hi,b_hi),(a_lo,b_hi),(a_hi,b_lo).
constexpr int kTileB = 128 * 80;       // one operand tile (rows x 80B)
constexpr int kStageB = 4 * kTileB;    // Ahi, Alo, Bhi, Blo
constexpr int kGSmem = 2 * kStageB;    // 81920

__global__ __launch_bounds__(256) void gemm_mma(
    const __nv_bfloat16* __restrict__ Bhi, const __nv_bfloat16* __restrict__ Blo,
    const float* __restrict__ bias, float* __restrict__ C) {
  extern __shared__ char smc[];
  uint32_t sbase = smem_u32(smc);
  int tid = threadIdx.x;
  int lane = tid & 31, wid = tid >> 5;
  int row0 = blockIdx.y * 128, col0 = blockIdx.x * 128;
  int m0w = (wid >> 1) * 32, n0w = (wid & 1) * 64;

  float acc[2][8][4];
#pragma unroll
  for (int i = 0; i < 2; i++)
#pragma unroll
    for (int j = 0; j < 8; j++)
#pragma unroll
      for (int q = 0; q < 4; q++) acc[i][j][q] = 0.f;

  const __nv_bfloat16* srcs[4] = {g_Ahi, g_Alo, Bhi, Blo};

  auto issue = [&](int ch, int s) {
    int k0 = ch * 32;
#pragma unroll
    for (int t = 0; t < 4; t++) {
      const __nv_bfloat16* src = srcs[t];
      int base0 = (t < 2) ? row0 : col0;
#pragma unroll
      for (int i = 0; i < 2; i++) {
        int idx = tid + i * 256;
        int row = idx >> 2, seg = idx & 3;
        uint32_t dst = sbase + s * kStageB + t * kTileB + row * 80 + seg * 16;
        cp16(dst, src + (size_t)(base0 + row) * kE + k0 + seg * 8);
      }
    }
    asm volatile("cp.async.commit_group;");
  };

  issue(0, 0);
  for (int ch = 0; ch < 32; ch++) {
    int s = ch & 1;
    if (ch + 1 < 32) {
      issue(ch + 1, s ^ 1);
      asm volatile("cp.async.wait_group 1;");
    } else {
      asm volatile("cp.async.wait_group 0;");
    }
    __syncthreads();
    uint32_t abase = sbase + s * kStageB;
    uint32_t bbase = sbase + s * kStageB + 2 * kTileB;
#pragma unroll
    for (int k16 = 0; k16 < 2; k16++) {
      uint32_t a_hi[2][4], a_lo[2][4], bf[8][2];
      uint32_t aoff = (k16 * 16 + (lane >> 4) * 8) * 2;
      uint32_t boff = (k16 * 16 + ((lane >> 3) & 1) * 8) * 2;
#pragma unroll
      for (int mt = 0; mt < 2; mt++) {
        uint32_t ra = (m0w + mt * 16 + (lane & 15)) * 80 + aoff;
        ldsm_x4(a_hi[mt], abase + ra);
        ldsm_x4(a_lo[mt], abase + kTileB + ra);
      }
#pragma unroll
      for (int nt = 0; nt < 8; nt++)
        ldsm_x2(bf[nt], bbase + (n0w + nt * 8 + (lane & 7)) * 80 + boff);
#pragma unroll
      for (int mt = 0; mt < 2; mt++)
#pragma unroll
        for (int nt = 0; nt < 8; nt++) mma16816(acc[mt][nt], a_hi[mt], bf[nt]);
#pragma unroll
      for (int mt = 0; mt < 2; mt++)
#pragma unroll
        for (int nt = 0; nt < 8; nt++) mma16816(acc[mt][nt], a_lo[mt], bf[nt]);
#pragma unroll
      for (int nt = 0; nt < 8; nt++)
        ldsm_x2(bf[nt],
                bbase + kTileB + (n0w + nt * 8 + (lane & 7)) * 80 + boff);
#pragma unroll
      for (int mt = 0; mt < 2; mt++)
#pragma unroll
        for (int nt = 0; nt < 8; nt++) mma16816(acc[mt][nt], a_hi[mt], bf[nt]);
    }
    __syncthreads();
  }
  // epilogue
#pragma unroll
  for (int mt = 0; mt < 2; mt++) {
#pragma unroll
    for (int nt = 0; nt < 8; nt++) {
      int r = row0 + m0w + mt * 16 + (lane >> 2);
      int cc = col0 + n0w + nt * 8 + (lane & 3) * 2;
      float2 b0 = *(const float2*)(bias + cc);
      float2 v0 = {acc[mt][nt][0] + b0.x, acc[mt][nt][1] + b0.y};
      *(float2*)(C + (size_t)r * kE + cc) = v0;
      float2 v1 = {acc[mt][nt][2] + b0.x, acc[mt][nt][3] + b0.y};
      *(float2*)(C + (size_t)(r + 8) * kE + cc) = v1;
    }
  }
}

// ---------------- exact hash path ----------------
// grid = kE blocks, 64 threads: g_Mq[e][col] = sum_d Wq[e][h*128+d]*hw[rh][d][n]
__global__ __launch_bounds__(64) void prepM_kernel(
    const float* __restrict__ Wq, const float* __restrict__ bq,
    const float* __restrict__ hw) {
  __shared__ float wrow[8 * 132];
  int e = blockIdx.x;
  for (int i = threadIdx.x; i < kE; i += 64)
    wrow[(i >> 7) * 132 + (i & 127)] = Wq[(size_t)e * kE + i];
  __syncthreads();
  int col = threadIdx.x;
  int rh = col >> 2, n = col & 3, h = rh & 7;
  float s = 0.f;
#pragma unroll 4
  for (int d = 0; d < kD; d++)
    s += wrow[h * 132 + d] * hw[(rh * kD + d) * 4 + n];
  g_Mq[e * 64 + col] = s;
  if (e == 0) {
    float c = 0.f;
    for (int d = 0; d < kD; d++)
      c += bq[h * kD + d] * hw[(rh * kD + d) * 4 + n];
    g_cq[col] = c;
  }
}

__global__ __launch_bounds__(256) void linhash_kernel(
    const float* __restrict__ query) {
  __shared__ float slin[8][64];
  int warp = threadIdx.x >> 5, lane = threadIdx.x & 31;
  int tb = blockIdx.x * 8 + warp;
  float acc0 = g_cq[lane], acc1 = g_cq[lane + 32];
  for (int e0 = 0; e0 < kE; e0 += 32) {
    float xv = query[(size_t)tb * kE + e0 + lane];
#pragma unroll
    for (int l2 = 0; l2 < 32; l2++) {
      float v = __shfl_sync(0xffffffffu, xv, l2);
      acc0 += v * g_Mq[(e0 + l2) * 64 + lane];
      acc1 += v * g_Mq[(e0 + l2) * 64 + lane + 32];
    }
  }
  slin[warp][lane] = acc0;
  slin[warp][lane + 32] = acc1;
  __syncwarp();
  if (lane < 16) {
    const float* p = &slin[warp][lane * 4];
    float best = p[0];
    int bi = 0;
#pragma unroll
    for (int n = 1; n < 4; n++)
      if (p[n] > best) { best = p[n]; bi = n; }
#pragma unroll
    for (int n = 0; n < 4; n++)
      if (-p[n] > best) { best = -p[n]; bi = 4 + n; }
    g_hash[tb * 16 + lane] = bi;
  }
}

// ---------------- normalize + scale ----------------
__global__ __launch_bounds__(256) void normalize_kernel() {
  int row = blockIdx.x;
  const float* x = g_QF + (size_t)row * kE;
  __shared__ float red[256];
  int tid = threadIdx.x;
  float s = 0.f;
#pragma unroll
  for (int i = 0; i < 4; i++) {
    float v = x[tid + i * 256];
    s += v * v;
  }
  red[tid] = s;
  __syncthreads();
  for (int off = 128; off > 0; off >>= 1) {
    if (tid < off) red[tid] += red[tid + off];
    __syncthreads();
  }
  float invn = 1.0f / sqrtf(red[0]);
#pragma unroll
  for (int i = 0; i < 4; i++) {
    int e = tid + i * 256;
    float v = x[e];
    g_Q[(size_t)row * kE + e] = v * kScale;
    g_K[(size_t)row * kE + e] = v * invn;
  }
}

// ---------------- stable counting sort per (b,r,h), scan-based ----------------
__global__ __launch_bounds__(256) void sort_kernel() {
  int brh = blockIdx.x;
  int h = brh & 7;
  int r = (brh >> 3) & 1;
  int b = brh >> 4;
  __shared__ int cntmat[kNH][256];
  __shared__ int btot[kNH];
  __shared__ int bbase[kNH];
  int tid = threadIdx.x;
  int w = tid >> 5, lane = tid & 31;

  int vals[8];
  int cnt[kNH];
#pragma unroll
  for (int i = 0; i < kNH; i++) cnt[i] = 0;
#pragma unroll
  for (int i = 0; i < 8; i++) {
    int t = tid * 8 + i;
    int v = g_hash[(t * kB + b) * 16 + r * 8 + h];
    vals[i] = v;
    cnt[v]++;
  }
#pragma unroll
  for (int i = 0; i < kNH; i++) cntmat[i][tid] = cnt[i];
  __syncthreads();
  // per-bucket exclusive prefix over 256 thread-counts; warp w owns bucket w
  {
    int run = 0;
#pragma unroll
    for (int chk = 0; chk < 8; chk++) {
      int orig = cntmat[w][chk * 32 + lane];
      int x = orig;
#pragma unroll
      for (int off = 1; off < 32; off <<= 1) {
        int y = __shfl_up_sync(0xffffffffu, x, off);
        if (lane >= off) x += y;
      }
      cntmat[w][chk * 32 + lane] = run + x - orig;
      run += __shfl_sync(0xffffffffu, x, 31);
    }
    if (lane == 0) btot[w] = run;
  }
  __syncthreads();
  if (tid == 0) {
    int s = 0;
    for (int i = 0; i < kNH; i++) {
      bbase[i] = s;
      s += btot[i];
    }
  }
  __syncthreads();
  int off[kNH];
#pragma unroll
  for (int i = 0; i < kNH; i++) off[i] = bbase[i] + cntmat[i][tid];
#pragma unroll
  for (int i = 0; i < 8; i++) {
    int v = vals[i];
    int pos = off[v]++;
    int t = tid * 8 + i;
    g_pq[brh * kT + pos] = t;
    g_invq[brh * kT + t] = pos;
  }
}

// ---------------- per-chunk window bitmask ----------------
__global__ __launch_bounds__(128) void mask_kernel() {
  int blk = blockIdx.x;
  int c = blk & (kC - 1);
  int brh = blk >> 6;
  unsigned* mw = g_mask + (size_t)blk * (kT / 32);
  int tid = threadIdx.x;
  if (tid < kT / 32) mw[tid] = 0u;
  __syncthreads();
  if (tid < kM) {
    int cc2 = (c + (tid >> 5) + kC - 1) & (kC - 1);
    int pos = cc2 * kCH + (tid & 31);
    int id = g_pq[brh * kT + pos];
    atomicOr(&mw[id >> 5], 1u << (id & 31));
  }
}

// ---------------- attention ----------------
constexpr int kQS = 132;
constexpr int ATTN_SMEM =
    (32 * kQS + 96 * kQS + 96 * kQS + 32 * 96 + 64) * 4 + (32 * 3 + 96 * 2) * 4;

__global__ __launch_bounds__(256, 1) void attn_kernel() {
  extern __shared__ float sm[];
  float* sq = sm;
  float* sk = sq + 32 * kQS;
  float* sv = sk + 96 * kQS;
  float* sc = sv + 96 * kQS;
  float* rinv = sc + 32 * 96;
  float* rowz = rinv + 32;
  int* qid = (int*)(rowz + 32);
  int* qhh = qid + 32;
  int* oc2 = qhh + 32;
  int* kid = oc2 + 32;
  int* khh = kid + 96;

  int blk = blockIdx.x;
  int c = blk & (kC - 1);
  int brh = blk >> 6;
  int h = brh & 7;
  int r = (brh >> 3) & 1;
  int b = brh >> 4;
  int brho = (b * kR + (1 - r)) * kH + h;
  int tid = threadIdx.x;

  if (tid < 32) {
    int ts = c * kCH + tid;
    int tok = g_pq[brh * kT + ts];
    qid[tid] = tok;
    qhh[tid] = g_hash[(tok * kB + b) * 16 + r * 8 + h];
    oc2[tid] = g_invq[brho * kT + tok] >> 5;
  } else if (tid < 128) {
    int m = tid - 32;
    int cc2 = (c + (m >> 5) + kC - 1) & (kC - 1);
    int pos = cc2 * kCH + (m & 31);
    int tokk = g_pq[brh * kT + pos];
    kid[m] = tokk;
    khh[m] = g_hash[(tokk * kB + b) * 16 + r * 8 + h];
  }
  __syncthreads();

#pragma unroll
  for (int i = 0; i < 4; i++) {
    int idx = tid + i * 256;
    int l = idx >> 5, d4 = idx & 31;
    float4 v =
        *(const float4*)(g_Q + (size_t)(qid[l] * kB + b) * kE + h * kD + d4 * 4);
    *(float4*)&sq[l * kQS + d4 * 4] = v;
  }
#pragma unroll
  for (int i = 0; i < 12; i++) {
    int idx = tid + i * 256;
    int m = idx >> 5, d4 = idx & 31;
    size_t base = (size_t)(kid[m] * kB + b) * kE + h * kD + d4 * 4;
    *(float4*)&sk[m * kQS + d4 * 4] = *(const float4*)(g_K + base);
    *(float4*)&sv[m * kQS + d4 * 4] = *(const float4*)(g_V + base);
  }
  __syncthreads();

  // scores: 8 threads per row, 12 key columns each, float4 dots
  {
    int l = tid >> 3, sub = tid & 7;
    float acc[12];
#pragma unroll
    for (int j = 0; j < 12; j++) acc[j] = 0.f;
    const float* qrow = sq + l * kQS;
    for (int d4 = 0; d4 < 32; d4++) {
      float4 qv = *(const float4*)&qrow[d4 * 4];
#pragma unroll
      for (int j = 0; j < 12; j++) {
        float4 kv = *(const float4*)&sk[(sub + j * 8) * kQS + d4 * 4];
        acc[j] += qv.x * kv.x + qv.y * kv.y + qv.z * kv.z + qv.w * kv.w;
      }
    }
    int myqh = qhh[l], myqid = qid[l];
    const unsigned* mw = g_mask + (size_t)(brho * kC + oc2[l]) * (kT / 32);
#pragma unroll
    for (int j = 0; j < 12; j++) {
      int m = sub + j * 8;
      float s = acc[j];
      if (myqh != khh[m]) s -= kInfM;
      int id = kid[m];
      if (myqid == id) s -= kBigM;
      if ((mw[id >> 5] >> (id & 31)) & 1u) s -= kLog2;
      sc[l * 96 + m] = s;
    }
  }
  __syncthreads();

  {
    int w = tid >> 5, lane = tid & 31;
    for (int rr = 0; rr < 4; rr++) {
      int l = w * 4 + rr;
      float mx = -3.0e38f;
      for (int m = lane; m < 96; m += 32) mx = fmaxf(mx, sc[l * 96 + m]);
      for (int off = 16; off; off >>= 1)
        mx = fmaxf(mx, __shfl_xor_sync(0xffffffffu, mx, off));
      float s = 0.f;
      for (int m = lane; m < 96; m += 32) {
        float e = expf(sc[l * 96 + m] - mx);
        sc[l * 96 + m] = e;
        s += e;
      }
      for (int off = 16; off; off >>= 1)
        s += __shfl_xor_sync(0xffffffffu, s, off);
      if (lane == 0) {
        rinv[l] = 1.0f / s;
        rowz[l] = mx + logf(s);
      }
    }
  }
  __syncthreads();

  // output: thread owns 4 d (float4) x 4 rows; sc broadcasts per warp
  {
    int d4 = tid & 31, g = tid >> 5;  // g = 0..7, rows g*4..g*4+3
    float4 acc[4];
#pragma unroll
    for (int ll = 0; ll < 4; ll++) acc[ll] = {0.f, 0.f, 0.f, 0.f};
    for (int m = 0; m < 96; m++) {
      float4 v = *(const float4*)&sv[m * kQS + d4 * 4];
#pragma unroll
      for (int ll = 0; ll < 4; ll++) {
        float s = sc[(g * 4 + ll) * 96 + m];
        acc[ll].x += s * v.x;
        acc[ll].y += s * v.y;
        acc[ll].z += s * v.z;
        acc[ll].w += s * v.w;
      }
    }
#pragma unroll
    for (int ll = 0; ll < 4; ll++) {
      int l = g * 4 + ll;
      float ri = rinv[l];
      float4 o = {acc[ll].x * ri, acc[ll].y * ri, acc[ll].z * ri,
                  acc[ll].w * ri};
      *(float4*)(g_o + (size_t)(brh * kT + qid[l]) * kD + d4 * 4) = o;
    }
  }
  if (tid < 32) g_z[brh * kT + qid[tid]] = rowz[tid];
}

// ---------------- combine rounds (+ fused bf16 hi/lo split) ----------------
__global__ __launch_bounds__(256) void combine_kernel() {
  int idx = blockIdx.x * 256 + threadIdx.x;
  int d = idx & 127;
  int t = (idx >> 7) & (kT - 1);
  int h = (idx >> 18) & 7;
  int b = idx >> 21;
  int i0 = ((b * kR + 0) * kH + h) * kT + t;
  int i1 = ((b * kR + 1) * kH + h) * kT + t;
  float z0 = g_z[i0], z1 = g_z[i1];
  float m = fmaxf(z0, z1);
  float e0 = expf(z0 - m), e1 = expf(z1 - m);
  float inv = 1.0f / (e0 + e1);
  float val =
      (e0 * g_o[(size_t)i0 * kD + d] + e1 * g_o[(size_t)i1 * kD + d]) * inv;
  __nv_bfloat16 hi = __float2bfloat16(val);
  __nv_bfloat16 lo = __float2bfloat16(val - __bfloat162float(hi));
  size_t o = (size_t)(t * kB + b) * kE + h * kD + d;
  g_Ahi[o] = hi;
  g_Alo[o] = lo;
}

// ---------------- launch ----------------
extern "C" void kernel_launch(void* const* d_in, const int* in_sizes, int n_in,
                              void* d_out, int out_size) {
  (void)in_sizes;
  (void)n_in;
  (void)out_size;
  const float* query = (const float*)d_in[0];
  const float* value = (const float*)d_in[2];
  const float* Wq = (const float*)d_in[3];
  const float* bq = (const float*)d_in[4];
  const float* Wv = (const float*)d_in[5];
  const float* bv = (const float*)d_in[6];
  const float* Wo = (const float*)d_in[7];
  const float* bo = (const float*)d_in[8];
  const float* hw = (const float*)d_in[9];
  float* out = (float*)d_out;

  float *pQF, *pV;
  cudaGetSymbolAddress((void**)&pQF, g_QF);
  cudaGetSymbolAddress((void**)&pV, g_V);
  __nv_bfloat16 *pWqH, *pWqL, *pWvH, *pWvL, *pWoH, *pWoL;
  cudaGetSymbolAddress((void**)&pWqH, g_WqThi);
  cudaGetSymbolAddress((void**)&pWqL, g_WqTlo);
  cudaGetSymbolAddress((void**)&pWvH, g_WvThi);
  cudaGetSymbolAddress((void**)&pWvL, g_WvTlo);
  cudaGetSymbolAddress((void**)&pWoH, g_WoThi);
  cudaGetSymbolAddress((void**)&pWoL, g_WoTlo);

  dim3 tgrid(32, 32);
  dim3 tblk(32, 8);
  wsplit_kernel<<<tgrid, tblk>>>(Wq, pWqH, pWqL);
  wsplit_kernel<<<tgrid, tblk>>>(Wv, pWvH, pWvL);
  wsplit_kernel<<<tgrid, tblk>>>(Wo, pWoH, pWoL);
  prepM_kernel<<<kE, 64>>>(Wq, bq, hw);
  linhash_kernel<<<kTB / 8, 256>>>(query);
  sort_kernel<<<kB * kR * kH, 256>>>();
  mask_kernel<<<kB * kR * kH * kC, 128>>>();

  cudaFuncSetAttribute(gemm_mma, cudaFuncAttributeMaxDynamicSharedMemorySize,
                       kGSmem);
  dim3 ggrid(kE / 128, kTB / 128);

  asplit_kernel<<<(kTB * kE / 4) / 256, 256>>>(query);
  gemm_mma<<<ggrid, 256, kGSmem>>>(pWqH, pWqL, bq, pQF);
  normalize_kernel<<<kTB, 256>>>();

  asplit_kernel<<<(kTB * kE / 4) / 256, 256>>>(value);
  gemm_mma<<<ggrid, 256, kGSmem>>>(pWvH, pWvL, bv, pV);

  cudaFuncSetAttribute(attn_kernel, cudaFuncAttributeMaxDynamicSharedMemorySize,
                       ATTN_SMEM);
  attn_kernel<<<kB * kR * kH * kC, 256, ATTN_SMEM>>>();

  combine_kernel<<<(kB * kH * kT * kD) / 256, 256>>>();

  gemm_mma<<<ggrid, 256, kGSmem>>>(pWoH, pWoL, bo, out);
}

// round 9
// speedup vs baseline: 1.9508x; 1.1310x over previous
#include <cuda_runtime.h>
#include <cuda_bf16.h>
#include <math.h>
#include <stdint.h>

// ---------------- problem constants ----------------
constexpr int kT = 2048;
constexpr int kB = 2;
constexpr int kE = 1024;
constexpr int kH = 8;
constexpr int kD = 128;
constexpr int kR = 2;
constexpr int kNH = 8;
constexpr int kCH = 32;
constexpr int kC = kT / kCH;  // 64
constexpr int kM = 3 * kCH;   // 96
constexpr int kTB = kT * kB;  // 4096

constexpr float kScale = 0.08838834764831845f;  // D^-0.5
constexpr float kInfM = 1.0e16f;
constexpr float kBigM = 1.0e8f;
constexpr float kLog2 = 0.6931471805599453f;

// ---------------- device scratch ----------------
__device__ float g_QF[kTB * kE];
__device__ float g_Q[kTB * kE];
__device__ float g_K[kTB * kE];
__device__ float g_V[kTB * kE];
__device__ float g_o[kB * kR * kH * kT * kD];
__device__ float g_z[kB * kR * kH * kT];
__device__ int g_hash[kTB * 16];  // [tb][r*8+h]
__device__ int g_pq[kB * kR * kH * kT];
__device__ int g_invq[kB * kR * kH * kT];
__device__ unsigned g_mask[kB * kR * kH * kC * (kT / 32)];
__device__ float g_Mq[kE * 64];
__device__ float g_cq[64];
// input splits: query/out-combine use g_Ahi/g_Alo, value uses its own pair
__device__ __nv_bfloat16 g_Ahi[kTB * kE];
__device__ __nv_bfloat16 g_Alo[kTB * kE];
__device__ __nv_bfloat16 g_Vhi[kTB * kE];
__device__ __nv_bfloat16 g_Vlo[kTB * kE];
// transposed + hi/lo split weights, [N=1024][K=1024]
__device__ __nv_bfloat16 g_WqThi[kE * kE];
__device__ __nv_bfloat16 g_WqTlo[kE * kE];
__device__ __nv_bfloat16 g_WvThi[kE * kE];
__device__ __nv_bfloat16 g_WvTlo[kE * kE];
__device__ __nv_bfloat16 g_WoThi[kE * kE];
__device__ __nv_bfloat16 g_WoTlo[kE * kE];

// ---------------- helpers ----------------
__device__ __forceinline__ uint32_t smem_u32(const void* p) {
  uint32_t a;
  asm("{ .reg .u64 t; cvta.to.shared.u64 t, %1; cvt.u32.u64 %0, t; }"
      : "=r"(a) : "l"(p));
  return a;
}
__device__ __forceinline__ void ldsm_x4(uint32_t* r, uint32_t addr) {
  asm volatile(
      "ldmatrix.sync.aligned.m8n8.x4.shared.b16 {%0,%1,%2,%3}, [%4];"
      : "=r"(r[0]), "=r"(r[1]), "=r"(r[2]), "=r"(r[3]) : "r"(addr));
}
__device__ __forceinline__ void ldsm_x2(uint32_t* r, uint32_t addr) {
  asm volatile(
      "ldmatrix.sync.aligned.m8n8.x2.shared.b16 {%0,%1}, [%2];"
      : "=r"(r[0]), "=r"(r[1]) : "r"(addr));
}
__device__ __forceinline__ void mma16816(float* d, const uint32_t* a,
                                         const uint32_t* b) {
  asm volatile(
      "mma.sync.aligned.m16n8k16.row.col.f32.bf16.bf16.f32 "
      "{%0,%1,%2,%3}, {%4,%5,%6,%7}, {%8,%9}, {%0,%1,%2,%3};"
      : "+f"(d[0]), "+f"(d[1]), "+f"(d[2]), "+f"(d[3])
      : "r"(a[0]), "r"(a[1]), "r"(a[2]), "r"(a[3]), "r"(b[0]), "r"(b[1]));
}
__device__ __forceinline__ void cp16(uint32_t dst, const void* src) {
  asm volatile("cp.async.cg.shared.global [%0], [%1], 16;" ::"r"(dst),
               "l"(src));
}

// ---------------- A fp32 -> bf16 hi/lo split ----------------
__global__ __launch_bounds__(256) void asplit_kernel(
    const float* __restrict__ A, __nv_bfloat16* __restrict__ outhi,
    __nv_bfloat16* __restrict__ outlo) {
  int idx = blockIdx.x * 256 + threadIdx.x;
  float4 v = ((const float4*)A)[idx];
  __nv_bfloat16 h0 = __float2bfloat16(v.x), h1 = __float2bfloat16(v.y);
  __nv_bfloat16 h2 = __float2bfloat16(v.z), h3 = __float2bfloat16(v.w);
  __nv_bfloat16 l0 = __float2bfloat16(v.x - __bfloat162float(h0));
  __nv_bfloat16 l1 = __float2bfloat16(v.y - __bfloat162float(h1));
  __nv_bfloat16 l2 = __float2bfloat16(v.z - __bfloat162float(h2));
  __nv_bfloat16 l3 = __float2bfloat16(v.w - __bfloat162float(h3));
  __nv_bfloat162 ph0 = {h0, h1}, ph1 = {h2, h3};
  __nv_bfloat162 pl0 = {l0, l1}, pl1 = {l2, l3};
  uint2 uh = {*(uint32_t*)&ph0, *(uint32_t*)&ph1};
  uint2 ul = {*(uint32_t*)&pl0, *(uint32_t*)&pl1};
  ((uint2*)outhi)[idx] = uh;
  ((uint2*)outlo)[idx] = ul;
}

// ---------------- weight transpose + bf16 hi/lo split ----------------
__global__ __launch_bounds__(256) void wsplit_kernel(
    const float* __restrict__ W, __nv_bfloat16* __restrict__ hi,
    __nv_bfloat16* __restrict__ lo) {
  __shared__ float t[32][33];
  int bx = blockIdx.x * 32;  // n block
  int by = blockIdx.y * 32;  // k block
  int x = threadIdx.x, y = threadIdx.y;
#pragma unroll
  for (int i = 0; i < 32; i += 8)
    t[y + i][x] = W[(size_t)(by + y + i) * kE + bx + x];
  __syncthreads();
#pragma unroll
  for (int i = 0; i < 32; i += 8) {
    float v = t[x][y + i];
    __nv_bfloat16 h = __float2bfloat16(v);
    __nv_bfloat16 l = __float2bfloat16(v - __bfloat162float(h));
    size_t o = (size_t)(bx + y + i) * kE + by + x;
    hi[o] = h;
    lo[o] = l;
  }
}

// ---------------- bf16x3 HMMA GEMM ----------------
constexpr int kTileB = 128 * 80;
constexpr int kStageB = 4 * kTileB;
constexpr int kGSmem = 2 * kStageB;  // 81920

__global__ __launch_bounds__(256) void gemm_mma(
    const __nv_bfloat16* __restrict__ Ahi, const __nv_bfloat16* __restrict__ Alo,
    const __nv_bfloat16* __restrict__ Bhi, const __nv_bfloat16* __restrict__ Blo,
    const float* __restrict__ bias, float* __restrict__ C) {
  extern __shared__ char smc[];
  uint32_t sbase = smem_u32(smc);
  int tid = threadIdx.x;
  int lane = tid & 31, wid = tid >> 5;
  int row0 = blockIdx.y * 128, col0 = blockIdx.x * 128;
  int m0w = (wid >> 1) * 32, n0w = (wid & 1) * 64;

  float acc[2][8][4];
#pragma unroll
  for (int i = 0; i < 2; i++)
#pragma unroll
    for (int j = 0; j < 8; j++)
#pragma unroll
      for (int q = 0; q < 4; q++) acc[i][j][q] = 0.f;

  const __nv_bfloat16* srcs[4] = {Ahi, Alo, Bhi, Blo};

  auto issue = [&](int ch, int s) {
    int k0 = ch * 32;
#pragma unroll
    for (int t = 0; t < 4; t++) {
      const __nv_bfloat16* src = srcs[t];
      int base0 = (t < 2) ? row0 : col0;
#pragma unroll
      for (int i = 0; i < 2; i++) {
        int idx = tid + i * 256;
        int row = idx >> 2, seg = idx & 3;
        uint32_t dst = sbase + s * kStageB + t * kTileB + row * 80 + seg * 16;
        cp16(dst, src + (size_t)(base0 + row) * kE + k0 + seg * 8);
      }
    }
    asm volatile("cp.async.commit_group;");
  };

  issue(0, 0);
  for (int ch = 0; ch < 32; ch++) {
    int s = ch & 1;
    if (ch + 1 < 32) {
      issue(ch + 1, s ^ 1);
      asm volatile("cp.async.wait_group 1;");
    } else {
      asm volatile("cp.async.wait_group 0;");
    }
    __syncthreads();
    uint32_t abase = sbase + s * kStageB;
    uint32_t bbase = sbase + s * kStageB + 2 * kTileB;
#pragma unroll
    for (int k16 = 0; k16 < 2; k16++) {
      uint32_t a_hi[2][4], a_lo[2][4], bf[8][2];
      uint32_t aoff = (k16 * 16 + (lane >> 4) * 8) * 2;
      uint32_t boff = (k16 * 16 + ((lane >> 3) & 1) * 8) * 2;
#pragma unroll
      for (int mt = 0; mt < 2; mt++) {
        uint32_t ra = (m0w + mt * 16 + (lane & 15)) * 80 + aoff;
        ldsm_x4(a_hi[mt], abase + ra);
        ldsm_x4(a_lo[mt], abase + kTileB + ra);
      }
#pragma unroll
      for (int nt = 0; nt < 8; nt++)
        ldsm_x2(bf[nt], bbase + (n0w + nt * 8 + (lane & 7)) * 80 + boff);
#pragma unroll
      for (int mt = 0; mt < 2; mt++)
#pragma unroll
        for (int nt = 0; nt < 8; nt++) mma16816(acc[mt][nt], a_hi[mt], bf[nt]);
#pragma unroll
      for (int mt = 0; mt < 2; mt++)
#pragma unroll
        for (int nt = 0; nt < 8; nt++) mma16816(acc[mt][nt], a_lo[mt], bf[nt]);
#pragma unroll
      for (int nt = 0; nt < 8; nt++)
        ldsm_x2(bf[nt],
                bbase + kTileB + (n0w + nt * 8 + (lane & 7)) * 80 + boff);
#pragma unroll
      for (int mt = 0; mt < 2; mt++)
#pragma unroll
        for (int nt = 0; nt < 8; nt++) mma16816(acc[mt][nt], a_hi[mt], bf[nt]);
    }
    __syncthreads();
  }
#pragma unroll
  for (int mt = 0; mt < 2; mt++) {
#pragma unroll
    for (int nt = 0; nt < 8; nt++) {
      int r = row0 + m0w + mt * 16 + (lane >> 2);
      int cc = col0 + n0w + nt * 8 + (lane & 3) * 2;
      float2 b0 = *(const float2*)(bias + cc);
      float2 v0 = {acc[mt][nt][0] + b0.x, acc[mt][nt][1] + b0.y};
      *(float2*)(C + (size_t)r * kE + cc) = v0;
      float2 v1 = {acc[mt][nt][2] + b0.x, acc[mt][nt][3] + b0.y};
      *(float2*)(C + (size_t)(r + 8) * kE + cc) = v1;
    }
  }
}

// ---------------- exact hash path ----------------
// grid (rh=16, ec=8), 128 threads. Tile of Wq h-slice in padded smem.
constexpr int kPrepSmem = (128 * 129 + 512) * 4;
__global__ __launch_bounds__(128) void prepM_kernel(
    const float* __restrict__ Wq, const float* __restrict__ bq,
    const float* __restrict__ hw) {
  extern __shared__ float ps[];
  float* wtile = ps;            // 128 x 129
  float* hws = ps + 128 * 129;  // 512
  int rh = blockIdx.x, ec = blockIdx.y;
  int h = rh & 7;
  int tid = threadIdx.x;
  for (int i = tid; i < 512; i += 128) hws[i] = hw[rh * 512 + i];
  for (int i = tid; i < 128 * 128; i += 128) {
    int row = i >> 7, col = i & 127;
    wtile[row * 129 + col] = Wq[(size_t)(ec * 128 + row) * kE + h * kD + col];
  }
  __syncthreads();
  float s0 = 0.f, s1 = 0.f, s2 = 0.f, s3 = 0.f;
  const float* wr = wtile + tid * 129;
#pragma unroll 4
  for (int d = 0; d < kD; d++) {
    float w = wr[d];
    s0 += w * hws[d * 4 + 0];
    s1 += w * hws[d * 4 + 1];
    s2 += w * hws[d * 4 + 2];
    s3 += w * hws[d * 4 + 3];
  }
  float4 o = {s0, s1, s2, s3};
  *(float4*)(g_Mq + (size_t)(ec * 128 + tid) * 64 + rh * 4) = o;
  if (ec == 0 && tid < 4) {
    float c = 0.f;
    for (int d = 0; d < kD; d++) c += bq[h * kD + d] * hws[d * 4 + tid];
    g_cq[rh * 4 + tid] = c;
  }
}

__global__ __launch_bounds__(256) void linhash_kernel(
    const float* __restrict__ query) {
  __shared__ float slin[8][64];
  int warp = threadIdx.x >> 5, lane = threadIdx.x & 31;
  int tb = blockIdx.x * 8 + warp;
  float acc0 = g_cq[lane], acc1 = g_cq[lane + 32];
  for (int e0 = 0; e0 < kE; e0 += 32) {
    float xv = query[(size_t)tb * kE + e0 + lane];
#pragma unroll
    for (int l2 = 0; l2 < 32; l2++) {
      float v = __shfl_sync(0xffffffffu, xv, l2);
      acc0 += v * g_Mq[(e0 + l2) * 64 + lane];
      acc1 += v * g_Mq[(e0 + l2) * 64 + lane + 32];
    }
  }
  slin[warp][lane] = acc0;
  slin[warp][lane + 32] = acc1;
  __syncwarp();
  if (lane < 16) {
    const float* p = &slin[warp][lane * 4];
    float best = p[0];
    int bi = 0;
#pragma unroll
    for (int n = 1; n < 4; n++)
      if (p[n] > best) { best = p[n]; bi = n; }
#pragma unroll
    for (int n = 0; n < 4; n++)
      if (-p[n] > best) { best = -p[n]; bi = 4 + n; }
    g_hash[tb * 16 + lane] = bi;
  }
}

// ---------------- normalize + scale ----------------
__global__ __launch_bounds__(256) void normalize_kernel() {
  int row = blockIdx.x;
  const float* x = g_QF + (size_t)row * kE;
  __shared__ float red[256];
  int tid = threadIdx.x;
  float s = 0.f;
#pragma unroll
  for (int i = 0; i < 4; i++) {
    float v = x[tid + i * 256];
    s += v * v;
  }
  red[tid] = s;
  __syncthreads();
  for (int off = 128; off > 0; off >>= 1) {
    if (tid < off) red[tid] += red[tid + off];
    __syncthreads();
  }
  float invn = 1.0f / sqrtf(red[0]);
#pragma unroll
  for (int i = 0; i < 4; i++) {
    int e = tid + i * 256;
    float v = x[e];
    g_Q[(size_t)row * kE + e] = v * kScale;
    g_K[(size_t)row * kE + e] = v * invn;
  }
}

// ---------------- stable counting sort per (b,r,h), scan-based ----------------
__global__ __launch_bounds__(256) void sort_kernel() {
  int brh = blockIdx.x;
  int h = brh & 7;
  int r = (brh >> 3) & 1;
  int b = brh >> 4;
  __shared__ int cntmat[kNH][256];
  __shared__ int btot[kNH];
  __shared__ int bbase[kNH];
  int tid = threadIdx.x;
  int w = tid >> 5, lane = tid & 31;

  int vals[8];
  int cnt[kNH];
#pragma unroll
  for (int i = 0; i < kNH; i++) cnt[i] = 0;
#pragma unroll
  for (int i = 0; i < 8; i++) {
    int t = tid * 8 + i;
    int v = g_hash[(t * kB + b) * 16 + r * 8 + h];
    vals[i] = v;
    cnt[v]++;
  }
#pragma unroll
  for (int i = 0; i < kNH; i++) cntmat[i][tid] = cnt[i];
  __syncthreads();
  {
    int run = 0;
#pragma unroll
    for (int chk = 0; chk < 8; chk++) {
      int orig = cntmat[w][chk * 32 + lane];
      int x = orig;
#pragma unroll
      for (int off = 1; off < 32; off <<= 1) {
        int y = __shfl_up_sync(0xffffffffu, x, off);
        if (lane >= off) x += y;
      }
      cntmat[w][chk * 32 + lane] = run + x - orig;
      run += __shfl_sync(0xffffffffu, x, 31);
    }
    if (lane == 0) btot[w] = run;
  }
  __syncthreads();
  if (tid == 0) {
    int s = 0;
    for (int i = 0; i < kNH; i++) {
      bbase[i] = s;
      s += btot[i];
    }
  }
  __syncthreads();
  int off[kNH];
#pragma unroll
  for (int i = 0; i < kNH; i++) off[i] = bbase[i] + cntmat[i][tid];
#pragma unroll
  for (int i = 0; i < 8; i++) {
    int v = vals[i];
    int pos = off[v]++;
    int t = tid * 8 + i;
    g_pq[brh * kT + pos] = t;
    g_invq[brh * kT + t] = pos;
  }
}

// ---------------- per-chunk window bitmask ----------------
__global__ __launch_bounds__(128) void mask_kernel() {
  int blk = blockIdx.x;
  int c = blk & (kC - 1);
  int brh = blk >> 6;
  unsigned* mw = g_mask + (size_t)blk * (kT / 32);
  int tid = threadIdx.x;
  if (tid < kT / 32) mw[tid] = 0u;
  __syncthreads();
  if (tid < kM) {
    int cc2 = (c + (tid >> 5) + kC - 1) & (kC - 1);
    int pos = cc2 * kCH + (tid & 31);
    int id = g_pq[brh * kT + pos];
    atomicOr(&mw[id >> 5], 1u << (id & 31));
  }
}

// ---------------- attention (no V smem tile; V streamed from L2) -------------
constexpr int kQS = 132;
constexpr int ATTN_SMEM =
    (32 * kQS + 96 * kQS + 32 * 96 + 64) * 4 + (32 * 3 + 96 * 2) * 4;

__global__ __launch_bounds__(256, 2) void attn_kernel() {
  extern __shared__ float sm[];
  float* sq = sm;
  float* sk = sq + 32 * kQS;
  float* sc = sk + 96 * kQS;
  float* rinv = sc + 32 * 96;
  float* rowz = rinv + 32;
  int* qid = (int*)(rowz + 32);
  int* qhh = qid + 32;
  int* oc2 = qhh + 32;
  int* kid = oc2 + 32;
  int* khh = kid + 96;

  int blk = blockIdx.x;
  int c = blk & (kC - 1);
  int brh = blk >> 6;
  int h = brh & 7;
  int r = (brh >> 3) & 1;
  int b = brh >> 4;
  int brho = (b * kR + (1 - r)) * kH + h;
  int tid = threadIdx.x;

  if (tid < 32) {
    int ts = c * kCH + tid;
    int tok = g_pq[brh * kT + ts];
    qid[tid] = tok;
    qhh[tid] = g_hash[(tok * kB + b) * 16 + r * 8 + h];
    oc2[tid] = g_invq[brho * kT + tok] >> 5;
  } else if (tid < 128) {
    int m = tid - 32;
    int cc2 = (c + (m >> 5) + kC - 1) & (kC - 1);
    int pos = cc2 * kCH + (m & 31);
    int tokk = g_pq[brh * kT + pos];
    kid[m] = tokk;
    khh[m] = g_hash[(tokk * kB + b) * 16 + r * 8 + h];
  }
  __syncthreads();

#pragma unroll
  for (int i = 0; i < 4; i++) {
    int idx = tid + i * 256;
    int l = idx >> 5, d4 = idx & 31;
    float4 v =
        *(const float4*)(g_Q + (size_t)(qid[l] * kB + b) * kE + h * kD + d4 * 4);
    *(float4*)&sq[l * kQS + d4 * 4] = v;
  }
#pragma unroll
  for (int i = 0; i < 12; i++) {
    int idx = tid + i * 256;
    int m = idx >> 5, d4 = idx & 31;
    size_t base = (size_t)(kid[m] * kB + b) * kE + h * kD + d4 * 4;
    *(float4*)&sk[m * kQS + d4 * 4] = *(const float4*)(g_K + base);
  }
  __syncthreads();

  // scores: 8 threads per row, 12 key columns each, float4 dots
  {
    int l = tid >> 3, sub = tid & 7;
    float acc[12];
#pragma unroll
    for (int j = 0; j < 12; j++) acc[j] = 0.f;
    const float* qrow = sq + l * kQS;
    for (int d4 = 0; d4 < 32; d4++) {
      float4 qv = *(const float4*)&qrow[d4 * 4];
#pragma unroll
      for (int j = 0; j < 12; j++) {
        float4 kv = *(const float4*)&sk[(sub + j * 8) * kQS + d4 * 4];
        acc[j] += qv.x * kv.x + qv.y * kv.y + qv.z * kv.z + qv.w * kv.w;
      }
    }
    int myqh = qhh[l], myqid = qid[l];
    const unsigned* mw = g_mask + (size_t)(brho * kC + oc2[l]) * (kT / 32);
#pragma unroll
    for (int j = 0; j < 12; j++) {
      int m = sub + j * 8;
      float s = acc[j];
      if (myqh != khh[m]) s -= kInfM;
      int id = kid[m];
      if (myqid == id) s -= kBigM;
      if ((mw[id >> 5] >> (id & 31)) & 1u) s -= kLog2;
      sc[l * 96 + m] = s;
    }
  }
  __syncthreads();

  {
    int w = tid >> 5, lane = tid & 31;
    for (int rr = 0; rr < 4; rr++) {
      int l = w * 4 + rr;
      float mx = -3.0e38f;
      for (int m = lane; m < 96; m += 32) mx = fmaxf(mx, sc[l * 96 + m]);
      for (int off = 16; off; off >>= 1)
        mx = fmaxf(mx, __shfl_xor_sync(0xffffffffu, mx, off));
      float s = 0.f;
      for (int m = lane; m < 96; m += 32) {
        float e = expf(sc[l * 96 + m] - mx);
        sc[l * 96 + m] = e;
        s += e;
      }
      for (int off = 16; off; off >>= 1)
        s += __shfl_xor_sync(0xffffffffu, s, off);
      if (lane == 0) {
        rinv[l] = 1.0f / s;
        rowz[l] = mx + logf(s);
      }
    }
  }
  __syncthreads();

  // output: thread owns 4 d (float4) x 4 rows; V streamed from L2
  {
    int d4 = tid & 31, g = tid >> 5;
    float4 acc[4];
#pragma unroll
    for (int ll = 0; ll < 4; ll++) acc[ll] = {0.f, 0.f, 0.f, 0.f};
#pragma unroll 2
    for (int m = 0; m < 96; m += 2) {
      float4 v0 = *(const float4*)(g_V + (size_t)(kid[m] * kB + b) * kE +
                                   h * kD + d4 * 4);
      float4 v1 = *(const float4*)(g_V + (size_t)(kid[m + 1] * kB + b) * kE +
                                   h * kD + d4 * 4);
#pragma unroll
      for (int ll = 0; ll < 4; ll++) {
        float s0 = sc[(g * 4 + ll) * 96 + m];
        float s1 = sc[(g * 4 + ll) * 96 + m + 1];
        acc[ll].x += s0 * v0.x + s1 * v1.x;
        acc[ll].y += s0 * v0.y + s1 * v1.y;
        acc[ll].z += s0 * v0.z + s1 * v1.z;
        acc[ll].w += s0 * v0.w + s1 * v1.w;
      }
    }
#pragma unroll
    for (int ll = 0; ll < 4; ll++) {
      int l = g * 4 + ll;
      float ri = rinv[l];
      float4 o = {acc[ll].x * ri, acc[ll].y * ri, acc[ll].z * ri,
                  acc[ll].w * ri};
      *(float4*)(g_o + (size_t)(brh * kT + qid[l]) * kD + d4 * 4) = o;
    }
  }
  if (tid < 32) g_z[brh * kT + qid[tid]] = rowz[tid];
}

// ---------------- combine rounds (+ fused bf16 hi/lo split) ----------------
__global__ __launch_bounds__(256) void combine_kernel() {
  int idx = blockIdx.x * 256 + threadIdx.x;
  int d = idx & 127;
  int t = (idx >> 7) & (kT - 1);
  int h = (idx >> 18) & 7;
  int b = idx >> 21;
  int i0 = ((b * kR + 0) * kH + h) * kT + t;
  int i1 = ((b * kR + 1) * kH + h) * kT + t;
  float z0 = g_z[i0], z1 = g_z[i1];
  float m = fmaxf(z0, z1);
  float e0 = expf(z0 - m), e1 = expf(z1 - m);
  float inv = 1.0f / (e0 + e1);
  float val =
      (e0 * g_o[(size_t)i0 * kD + d] + e1 * g_o[(size_t)i1 * kD + d]) * inv;
  __nv_bfloat16 hi = __float2bfloat16(val);
  __nv_bfloat16 lo = __float2bfloat16(val - __bfloat162float(hi));
  size_t o = (size_t)(t * kB + b) * kE + h * kD + d;
  g_Ahi[o] = hi;
  g_Alo[o] = lo;
}

// ---------------- launch ----------------
extern "C" void kernel_launch(void* const* d_in, const int* in_sizes, int n_in,
                              void* d_out, int out_size) {
  (void)in_sizes;
  (void)n_in;
  (void)out_size;
  const float* query = (const float*)d_in[0];
  const float* value = (const float*)d_in[2];
  const float* Wq = (const float*)d_in[3];
  const float* bq = (const float*)d_in[4];
  const float* Wv = (const float*)d_in[5];
  const float* bv = (const float*)d_in[6];
  const float* Wo = (const float*)d_in[7];
  const float* bo = (const float*)d_in[8];
  const float* hw = (const float*)d_in[9];
  float* out = (float*)d_out;

  float *pQF, *pV;
  cudaGetSymbolAddress((void**)&pQF, g_QF);
  cudaGetSymbolAddress((void**)&pV, g_V);
  __nv_bfloat16 *pAH, *pAL, *pVH, *pVL;
  cudaGetSymbolAddress((void**)&pAH, g_Ahi);
  cudaGetSymbolAddress((void**)&pAL, g_Alo);
  cudaGetSymbolAddress((void**)&pVH, g_Vhi);
  cudaGetSymbolAddress((void**)&pVL, g_Vlo);
  __nv_bfloat16 *pWqH, *pWqL, *pWvH, *pWvL, *pWoH, *pWoL;
  cudaGetSymbolAddress((void**)&pWqH, g_WqThi);
  cudaGetSymbolAddress((void**)&pWqL, g_WqTlo);
  cudaGetSymbolAddress((void**)&pWvH, g_WvThi);
  cudaGetSymbolAddress((void**)&pWvL, g_WvTlo);
  cudaGetSymbolAddress((void**)&pWoH, g_WoThi);
  cudaGetSymbolAddress((void**)&pWoL, g_WoTlo);

  cudaFuncSetAttribute(gemm_mma, cudaFuncAttributeMaxDynamicSharedMemorySize,
                       kGSmem);
  cudaFuncSetAttribute(attn_kernel, cudaFuncAttributeMaxDynamicSharedMemorySize,
                       ATTN_SMEM);
  cudaFuncSetAttribute(prepM_kernel, cudaFuncAttributeMaxDynamicSharedMemorySize,
                       kPrepSmem);

  // lazily-created side stream + fork/join events (host resources, made once
  // on the uncaptured correctness call; capture call only records/waits)
  static cudaStream_t s2 = nullptr;
  static cudaEvent_t evF = nullptr, evJ = nullptr;
  if (s2 == nullptr) {
    cudaStreamCreateWithFlags(&s2, cudaStreamNonBlocking);
    cudaEventCreateWithFlags(&evF, cudaEventDisableTiming);
    cudaEventCreateWithFlags(&evJ, cudaEventDisableTiming);
  }

  dim3 tgrid(32, 32);
  dim3 tblk(32, 8);
  dim3 ggrid(kE / 128, kTB / 128);

  bool use_side = (s2 != nullptr);
  cudaStream_t sv = use_side ? s2 : (cudaStream_t)0;

  if (use_side) {
    cudaEventRecord(evF, 0);
    cudaStreamWaitEvent(s2, evF, 0);
  }

  // ---- side chain: V projection + prep (independent of Q chain) ----
  wsplit_kernel<<<tgrid, tblk, 0, sv>>>(Wv, pWvH, pWvL);
  wsplit_kernel<<<tgrid, tblk, 0, sv>>>(Wo, pWoH, pWoL);
  asplit_kernel<<<(kTB * kE / 4) / 256, 256, 0, sv>>>(value, pVH, pVL);
  prepM_kernel<<<dim3(16, 8), 128, kPrepSmem, sv>>>(Wq, bq, hw);
  linhash_kernel<<<kTB / 8, 256, 0, sv>>>(query);
  sort_kernel<<<kB * kR * kH, 256, 0, sv>>>();
  mask_kernel<<<kB * kR * kH * kC, 128, 0, sv>>>();
  gemm_mma<<<ggrid, 256, kGSmem, sv>>>(pVH, pVL, pWvH, pWvL, bv, pV);

  // ---- main chain: Q projection ----
  wsplit_kernel<<<tgrid, tblk>>>(Wq, pWqH, pWqL);
  asplit_kernel<<<(kTB * kE / 4) / 256, 256>>>(query, pAH, pAL);
  gemm_mma<<<ggrid, 256, kGSmem>>>(pAH, pAL, pWqH, pWqL, bq, pQF);
  normalize_kernel<<<kTB, 256>>>();

  if (use_side) {
    cudaEventRecord(evJ, s2);
    cudaStreamWaitEvent((cudaStream_t)0, evJ, 0);
  }

  attn_kernel<<<kB * kR * kH * kC, 256, ATTN_SMEM>>>();
  combine_kernel<<<(kB * kH * kT * kD) / 256, 256>>>();
  gemm_mma<<<ggrid, 256, kGSmem>>>(pAH, pAL, pWoH, pWoL, bo, out);
}

// round 10
// speedup vs baseline: 2.1173x; 1.0853x over previous
#include <cuda_runtime.h>
#include <cuda_bf16.h>
#include <math.h>
#include <stdint.h>

// ---------------- problem constants ----------------
constexpr int kT = 2048;
constexpr int kB = 2;
constexpr int kE = 1024;
constexpr int kH = 8;
constexpr int kD = 128;
constexpr int kR = 2;
constexpr int kNH = 8;
constexpr int kCH = 32;
constexpr int kC = kT / kCH;  // 64
constexpr int kM = 3 * kCH;   // 96
constexpr int kTB = kT * kB;  // 4096

constexpr float kScale = 0.08838834764831845f;  // D^-0.5
constexpr float kInfM = 1.0e16f;
constexpr float kBigM = 1.0e8f;
constexpr float kLog2 = 0.6931471805599453f;

// ---------------- device scratch ----------------
__device__ float g_QF[kTB * kE];
__device__ float g_Q[kTB * kE];
__device__ float g_K[kTB * kE];
__device__ float g_V[kTB * kE];
__device__ float g_o[kB * kR * kH * kT * kD];
__device__ float g_z[kB * kR * kH * kT];
__device__ int g_hash[kTB * 16];  // [tb][r*8+h]
__device__ int g_pq[kB * kR * kH * kT];
__device__ int g_invq[kB * kR * kH * kT];
__device__ unsigned g_mask[kB * kR * kH * kC * (kT / 32)];
__device__ float g_Mq[kE * 64];
__device__ float g_cq[64];
// input splits: query/out-combine use g_Ahi/g_Alo, value uses its own pair
__device__ __nv_bfloat16 g_Ahi[kTB * kE];
__device__ __nv_bfloat16 g_Alo[kTB * kE];
__device__ __nv_bfloat16 g_Vhi[kTB * kE];
__device__ __nv_bfloat16 g_Vlo[kTB * kE];
// transposed + hi/lo split weights, [N=1024][K=1024]
__device__ __nv_bfloat16 g_WqThi[kE * kE];
__device__ __nv_bfloat16 g_WqTlo[kE * kE];
__device__ __nv_bfloat16 g_WvThi[kE * kE];
__device__ __nv_bfloat16 g_WvTlo[kE * kE];
__device__ __nv_bfloat16 g_WoThi[kE * kE];
__device__ __nv_bfloat16 g_WoTlo[kE * kE];

// ---------------- helpers ----------------
__device__ __forceinline__ uint32_t smem_u32(const void* p) {
  uint32_t a;
  asm("{ .reg .u64 t; cvta.to.shared.u64 t, %1; cvt.u32.u64 %0, t; }"
      : "=r"(a) : "l"(p));
  return a;
}
__device__ __forceinline__ void ldsm_x4(uint32_t* r, uint32_t addr) {
  asm volatile(
      "ldmatrix.sync.aligned.m8n8.x4.shared.b16 {%0,%1,%2,%3}, [%4];"
      : "=r"(r[0]), "=r"(r[1]), "=r"(r[2]), "=r"(r[3]) : "r"(addr));
}
__device__ __forceinline__ void ldsm_x2(uint32_t* r, uint32_t addr) {
  asm volatile(
      "ldmatrix.sync.aligned.m8n8.x2.shared.b16 {%0,%1}, [%2];"
      : "=r"(r[0]), "=r"(r[1]) : "r"(addr));
}
__device__ __forceinline__ void mma16816(float* d, const uint32_t* a,
                                         const uint32_t* b) {
  asm volatile(
      "mma.sync.aligned.m16n8k16.row.col.f32.bf16.bf16.f32 "
      "{%0,%1,%2,%3}, {%4,%5,%6,%7}, {%8,%9}, {%0,%1,%2,%3};"
      : "+f"(d[0]), "+f"(d[1]), "+f"(d[2]), "+f"(d[3])
      : "r"(a[0]), "r"(a[1]), "r"(a[2]), "r"(a[3]), "r"(b[0]), "r"(b[1]));
}
__device__ __forceinline__ void cp16(uint32_t dst, const void* src) {
  asm volatile("cp.async.cg.shared.global [%0], [%1], 16;" ::"r"(dst),
               "l"(src));
}

// ---------------- A fp32 -> bf16 hi/lo split ----------------
__global__ __launch_bounds__(256) void asplit_kernel(
    const float* __restrict__ A, __nv_bfloat16* __restrict__ outhi,
    __nv_bfloat16* __restrict__ outlo) {
  int idx = blockIdx.x * 256 + threadIdx.x;
  float4 v = ((const float4*)A)[idx];
  __nv_bfloat16 h0 = __float2bfloat16(v.x), h1 = __float2bfloat16(v.y);
  __nv_bfloat16 h2 = __float2bfloat16(v.z), h3 = __float2bfloat16(v.w);
  __nv_bfloat16 l0 = __float2bfloat16(v.x - __bfloat162float(h0));
  __nv_bfloat16 l1 = __float2bfloat16(v.y - __bfloat162float(h1));
  __nv_bfloat16 l2 = __float2bfloat16(v.z - __bfloat162float(h2));
  __nv_bfloat16 l3 = __float2bfloat16(v.w - __bfloat162float(h3));
  __nv_bfloat162 ph0 = {h0, h1}, ph1 = {h2, h3};
  __nv_bfloat162 pl0 = {l0, l1}, pl1 = {l2, l3};
  uint2 uh = {*(uint32_t*)&ph0, *(uint32_t*)&ph1};
  uint2 ul = {*(uint32_t*)&pl0, *(uint32_t*)&pl1};
  ((uint2*)outhi)[idx] = uh;
  ((uint2*)outlo)[idx] = ul;
}

// ---------------- weight transpose + bf16 hi/lo split ----------------
__global__ __launch_bounds__(256) void wsplit_kernel(
    const float* __restrict__ W, __nv_bfloat16* __restrict__ hi,
    __nv_bfloat16* __restrict__ lo) {
  __shared__ float t[32][33];
  int bx = blockIdx.x * 32;  // n block
  int by = blockIdx.y * 32;  // k block
  int x = threadIdx.x, y = threadIdx.y;
#pragma unroll
  for (int i = 0; i < 32; i += 8)
    t[y + i][x] = W[(size_t)(by + y + i) * kE + bx + x];
  __syncthreads();
#pragma unroll
  for (int i = 0; i < 32; i += 8) {
    float v = t[x][y + i];
    __nv_bfloat16 h = __float2bfloat16(v);
    __nv_bfloat16 l = __float2bfloat16(v - __bfloat162float(h));
    size_t o = (size_t)(bx + y + i) * kE + by + x;
    hi[o] = h;
    lo[o] = l;
  }
}

// ---------------- bf16x3 HMMA GEMM ----------------
constexpr int kTileB = 128 * 80;
constexpr int kStageB = 4 * kTileB;
constexpr int kGSmem = 2 * kStageB;  // 81920

__global__ __launch_bounds__(256) void gemm_mma(
    const __nv_bfloat16* __restrict__ Ahi, const __nv_bfloat16* __restrict__ Alo,
    const __nv_bfloat16* __restrict__ Bhi, const __nv_bfloat16* __restrict__ Blo,
    const float* __restrict__ bias, float* __restrict__ C) {
  extern __shared__ char smc[];
  uint32_t sbase = smem_u32(smc);
  int tid = threadIdx.x;
  int lane = tid & 31, wid = tid >> 5;
  int row0 = blockIdx.y * 128, col0 = blockIdx.x * 128;
  int m0w = (wid >> 1) * 32, n0w = (wid & 1) * 64;

  float acc[2][8][4];
#pragma unroll
  for (int i = 0; i < 2; i++)
#pragma unroll
    for (int j = 0; j < 8; j++)
#pragma unroll
      for (int q = 0; q < 4; q++) acc[i][j][q] = 0.f;

  const __nv_bfloat16* srcs[4] = {Ahi, Alo, Bhi, Blo};

  auto issue = [&](int ch, int s) {
    int k0 = ch * 32;
#pragma unroll
    for (int t = 0; t < 4; t++) {
      const __nv_bfloat16* src = srcs[t];
      int base0 = (t < 2) ? row0 : col0;
#pragma unroll
      for (int i = 0; i < 2; i++) {
        int idx = tid + i * 256;
        int row = idx >> 2, seg = idx & 3;
        uint32_t dst = sbase + s * kStageB + t * kTileB + row * 80 + seg * 16;
        cp16(dst, src + (size_t)(base0 + row) * kE + k0 + seg * 8);
      }
    }
    asm volatile("cp.async.commit_group;");
  };

  issue(0, 0);
  for (int ch = 0; ch < 32; ch++) {
    int s = ch & 1;
    if (ch + 1 < 32) {
      issue(ch + 1, s ^ 1);
      asm volatile("cp.async.wait_group 1;");
    } else {
      asm volatile("cp.async.wait_group 0;");
    }
    __syncthreads();
    uint32_t abase = sbase + s * kStageB;
    uint32_t bbase = sbase + s * kStageB + 2 * kTileB;
#pragma unroll
    for (int k16 = 0; k16 < 2; k16++) {
      uint32_t a_hi[2][4], a_lo[2][4], bf[8][2];
      uint32_t aoff = (k16 * 16 + (lane >> 4) * 8) * 2;
      uint32_t boff = (k16 * 16 + ((lane >> 3) & 1) * 8) * 2;
#pragma unroll
      for (int mt = 0; mt < 2; mt++) {
        uint32_t ra = (m0w + mt * 16 + (lane & 15)) * 80 + aoff;
        ldsm_x4(a_hi[mt], abase + ra);
        ldsm_x4(a_lo[mt], abase + kTileB + ra);
      }
#pragma unroll
      for (int nt = 0; nt < 8; nt++)
        ldsm_x2(bf[nt], bbase + (n0w + nt * 8 + (lane & 7)) * 80 + boff);
#pragma unroll
      for (int mt = 0; mt < 2; mt++)
#pragma unroll
        for (int nt = 0; nt < 8; nt++) mma16816(acc[mt][nt], a_hi[mt], bf[nt]);
#pragma unroll
      for (int mt = 0; mt < 2; mt++)
#pragma unroll
        for (int nt = 0; nt < 8; nt++) mma16816(acc[mt][nt], a_lo[mt], bf[nt]);
#pragma unroll
      for (int nt = 0; nt < 8; nt++)
        ldsm_x2(bf[nt],
                bbase + kTileB + (n0w + nt * 8 + (lane & 7)) * 80 + boff);
#pragma unroll
      for (int mt = 0; mt < 2; mt++)
#pragma unroll
        for (int nt = 0; nt < 8; nt++) mma16816(acc[mt][nt], a_hi[mt], bf[nt]);
    }
    __syncthreads();
  }
#pragma unroll
  for (int mt = 0; mt < 2; mt++) {
#pragma unroll
    for (int nt = 0; nt < 8; nt++) {
      int r = row0 + m0w + mt * 16 + (lane >> 2);
      int cc = col0 + n0w + nt * 8 + (lane & 3) * 2;
      float2 b0 = *(const float2*)(bias + cc);
      float2 v0 = {acc[mt][nt][0] + b0.x, acc[mt][nt][1] + b0.y};
      *(float2*)(C + (size_t)r * kE + cc) = v0;
      float2 v1 = {acc[mt][nt][2] + b0.x, acc[mt][nt][3] + b0.y};
      *(float2*)(C + (size_t)(r + 8) * kE + cc) = v1;
    }
  }
}

// ---------------- exact hash path ----------------
// grid (rh=16, ec=8), 128 threads. Wq h-slice tile in padded smem, float4 ld.
constexpr int kPrepSmem = (128 * 132 + 512) * 4;
__global__ __launch_bounds__(128) void prepM_kernel(
    const float* __restrict__ Wq, const float* __restrict__ bq,
    const float* __restrict__ hw) {
  extern __shared__ float ps[];
  float* wtile = ps;            // 128 x 132 (float4-aligned rows)
  float* hws = ps + 128 * 132;  // 512
  int rh = blockIdx.x, ec = blockIdx.y;
  int h = rh & 7;
  int tid = threadIdx.x;
  for (int i = tid; i < 128; i += 128)
    *(float4*)&hws[i * 4] = *(const float4*)&hw[rh * 512 + i * 4];
#pragma unroll
  for (int it = 0; it < 32; it++) {
    int i = tid + it * 128;  // over 4096 float4s
    int row = i >> 5, c4 = i & 31;
    float4 v = *(const float4*)(Wq + (size_t)(ec * 128 + row) * kE + h * kD +
                                c4 * 4);
    *(float4*)&wtile[row * 132 + c4 * 4] = v;
  }
  __syncthreads();
  float s0 = 0.f, s1 = 0.f, s2 = 0.f, s3 = 0.f;
  const float* wr = wtile + tid * 132;
#pragma unroll 4
  for (int d = 0; d < kD; d++) {
    float w = wr[d];
    s0 += w * hws[d * 4 + 0];
    s1 += w * hws[d * 4 + 1];
    s2 += w * hws[d * 4 + 2];
    s3 += w * hws[d * 4 + 3];
  }
  float4 o = {s0, s1, s2, s3};
  *(float4*)(g_Mq + (size_t)(ec * 128 + tid) * 64 + rh * 4) = o;
  if (ec == 0 && tid < 4) {
    float c = 0.f;
    for (int d = 0; d < kD; d++) c += bq[h * kD + d] * hws[d * 4 + tid];
    g_cq[rh * 4 + tid] = c;
  }
}

__global__ __launch_bounds__(256) void linhash_kernel(
    const float* __restrict__ query) {
  __shared__ float slin[8][64];
  int warp = threadIdx.x >> 5, lane = threadIdx.x & 31;
  int tb = blockIdx.x * 8 + warp;
  float acc0 = g_cq[lane], acc1 = g_cq[lane + 32];
  for (int e0 = 0; e0 < kE; e0 += 32) {
    float xv = query[(size_t)tb * kE + e0 + lane];
#pragma unroll
    for (int l2 = 0; l2 < 32; l2++) {
      float v = __shfl_sync(0xffffffffu, xv, l2);
      acc0 += v * g_Mq[(e0 + l2) * 64 + lane];
      acc1 += v * g_Mq[(e0 + l2) * 64 + lane + 32];
    }
  }
  slin[warp][lane] = acc0;
  slin[warp][lane + 32] = acc1;
  __syncwarp();
  if (lane < 16) {
    const float* p = &slin[warp][lane * 4];
    float best = p[0];
    int bi = 0;
#pragma unroll
    for (int n = 1; n < 4; n++)
      if (p[n] > best) { best = p[n]; bi = n; }
#pragma unroll
    for (int n = 0; n < 4; n++)
      if (-p[n] > best) { best = -p[n]; bi = 4 + n; }
    g_hash[tb * 16 + lane] = bi;
  }
}

// ---------------- normalize + scale ----------------
__global__ __launch_bounds__(256) void normalize_kernel() {
  int row = blockIdx.x;
  const float* x = g_QF + (size_t)row * kE;
  __shared__ float red[256];
  int tid = threadIdx.x;
  float s = 0.f;
#pragma unroll
  for (int i = 0; i < 4; i++) {
    float v = x[tid + i * 256];
    s += v * v;
  }
  red[tid] = s;
  __syncthreads();
  for (int off = 128; off > 0; off >>= 1) {
    if (tid < off) red[tid] += red[tid + off];
    __syncthreads();
  }
  float invn = 1.0f / sqrtf(red[0]);
#pragma unroll
  for (int i = 0; i < 4; i++) {
    int e = tid + i * 256;
    float v = x[e];
    g_Q[(size_t)row * kE + e] = v * kScale;
    g_K[(size_t)row * kE + e] = v * invn;
  }
}

// ---------------- stable counting sort per (b,r,h), scan-based ----------------
__global__ __launch_bounds__(256) void sort_kernel() {
  int brh = blockIdx.x;
  int h = brh & 7;
  int r = (brh >> 3) & 1;
  int b = brh >> 4;
  __shared__ int cntmat[kNH][256];
  __shared__ int btot[kNH];
  __shared__ int bbase[kNH];
  int tid = threadIdx.x;
  int w = tid >> 5, lane = tid & 31;

  int vals[8];
  int cnt[kNH];
#pragma unroll
  for (int i = 0; i < kNH; i++) cnt[i] = 0;
#pragma unroll
  for (int i = 0; i < 8; i++) {
    int t = tid * 8 + i;
    int v = g_hash[(t * kB + b) * 16 + r * 8 + h];
    vals[i] = v;
    cnt[v]++;
  }
#pragma unroll
  for (int i = 0; i < kNH; i++) cntmat[i][tid] = cnt[i];
  __syncthreads();
  {
    int run = 0;
#pragma unroll
    for (int chk = 0; chk < 8; chk++) {
      int orig = cntmat[w][chk * 32 + lane];
      int x = orig;
#pragma unroll
      for (int off = 1; off < 32; off <<= 1) {
        int y = __shfl_up_sync(0xffffffffu, x, off);
        if (lane >= off) x += y;
      }
      cntmat[w][chk * 32 + lane] = run + x - orig;
      run += __shfl_sync(0xffffffffu, x, 31);
    }
    if (lane == 0) btot[w] = run;
  }
  __syncthreads();
  if (tid == 0) {
    int s = 0;
    for (int i = 0; i < kNH; i++) {
      bbase[i] = s;
      s += btot[i];
    }
  }
  __syncthreads();
  int off[kNH];
#pragma unroll
  for (int i = 0; i < kNH; i++) off[i] = bbase[i] + cntmat[i][tid];
#pragma unroll
  for (int i = 0; i < 8; i++) {
    int v = vals[i];
    int pos = off[v]++;
    int t = tid * 8 + i;
    g_pq[brh * kT + pos] = t;
    g_invq[brh * kT + t] = pos;
  }
}

// ---------------- per-chunk window bitmask ----------------
__global__ __launch_bounds__(128) void mask_kernel() {
  int blk = blockIdx.x;
  int c = blk & (kC - 1);
  int brh = blk >> 6;
  unsigned* mw = g_mask + (size_t)blk * (kT / 32);
  int tid = threadIdx.x;
  if (tid < kT / 32) mw[tid] = 0u;
  __syncthreads();
  if (tid < kM) {
    int cc2 = (c + (tid >> 5) + kC - 1) & (kC - 1);
    int pos = cc2 * kCH + (tid & 31);
    int id = g_pq[brh * kT + pos];
    atomicOr(&mw[id >> 5], 1u << (id & 31));
  }
}

// ---------------- attention ----------------
// smem: sq 32x132, skv 96x132 (K for scores, then V via cp.async overlapped
// with softmax), sc 32x96. ~81KB -> 2 CTAs/SM.
constexpr int kQS = 132;
constexpr int ATTN_SMEM =
    (32 * kQS + 96 * kQS + 32 * 96 + 64) * 4 + (32 * 3 + 96 * 2) * 4;

__global__ __launch_bounds__(256, 2) void attn_kernel() {
  extern __shared__ float sm[];
  float* sq = sm;
  float* skv = sq + 32 * kQS;  // K, then V
  float* sc = skv + 96 * kQS;
  float* rinv = sc + 32 * 96;
  float* rowz = rinv + 32;
  int* qid = (int*)(rowz + 32);
  int* qhh = qid + 32;
  int* oc2 = qhh + 32;
  int* kid = oc2 + 32;
  int* khh = kid + 96;
  uint32_t skv_base = smem_u32(skv);

  int blk = blockIdx.x;
  int c = blk & (kC - 1);
  int brh = blk >> 6;
  int h = brh & 7;
  int r = (brh >> 3) & 1;
  int b = brh >> 4;
  int brho = (b * kR + (1 - r)) * kH + h;
  int tid = threadIdx.x;

  if (tid < 32) {
    int ts = c * kCH + tid;
    int tok = g_pq[brh * kT + ts];
    qid[tid] = tok;
    qhh[tid] = g_hash[(tok * kB + b) * 16 + r * 8 + h];
    oc2[tid] = g_invq[brho * kT + tok] >> 5;
  } else if (tid < 128) {
    int m = tid - 32;
    int cc2 = (c + (m >> 5) + kC - 1) & (kC - 1);
    int pos = cc2 * kCH + (m & 31);
    int tokk = g_pq[brh * kT + pos];
    kid[m] = tokk;
    khh[m] = g_hash[(tokk * kB + b) * 16 + r * 8 + h];
  }
  __syncthreads();

#pragma unroll
  for (int i = 0; i < 4; i++) {
    int idx = tid + i * 256;
    int l = idx >> 5, d4 = idx & 31;
    float4 v =
        *(const float4*)(g_Q + (size_t)(qid[l] * kB + b) * kE + h * kD + d4 * 4);
    *(float4*)&sq[l * kQS + d4 * 4] = v;
  }
#pragma unroll
  for (int i = 0; i < 12; i++) {
    int idx = tid + i * 256;
    int m = idx >> 5, d4 = idx & 31;
    *(float4*)&skv[m * kQS + d4 * 4] =
        *(const float4*)(g_K + (size_t)(kid[m] * kB + b) * kE + h * kD + d4 * 4);
  }
  __syncthreads();

  // scores: 8 threads per row, 12 key columns each, float4 dots
  {
    int l = tid >> 3, sub = tid & 7;
    float acc[12];
#pragma unroll
    for (int j = 0; j < 12; j++) acc[j] = 0.f;
    const float* qrow = sq + l * kQS;
    for (int d4 = 0; d4 < 32; d4++) {
      float4 qv = *(const float4*)&qrow[d4 * 4];
#pragma unroll
      for (int j = 0; j < 12; j++) {
        float4 kv = *(const float4*)&skv[(sub + j * 8) * kQS + d4 * 4];
        acc[j] += qv.x * kv.x + qv.y * kv.y + qv.z * kv.z + qv.w * kv.w;
      }
    }
    int myqh = qhh[l], myqid = qid[l];
    const unsigned* mw = g_mask + (size_t)(brho * kC + oc2[l]) * (kT / 32);
#pragma unroll
    for (int j = 0; j < 12; j++) {
      int m = sub + j * 8;
      float s = acc[j];
      if (myqh != khh[m]) s -= kInfM;
      int id = kid[m];
      if (myqid == id) s -= kBigM;
      if ((mw[id >> 5] >> (id & 31)) & 1u) s -= kLog2;
      sc[l * 96 + m] = s;
    }
  }
  __syncthreads();  // all K reads done; safe to overwrite skv with V

  // issue async V loads into skv; overlap with softmax below
#pragma unroll
  for (int i = 0; i < 12; i++) {
    int idx = tid + i * 256;  // 0..3071
    int m = idx >> 5, seg = idx & 31;
    cp16(skv_base + m * (kQS * 4) + seg * 16,
         g_V + (size_t)(kid[m] * kB + b) * kE + h * kD + seg * 4);
  }
  asm volatile("cp.async.commit_group;");

  {
    int w = tid >> 5, lane = tid & 31;
    for (int rr = 0; rr < 4; rr++) {
      int l = w * 4 + rr;
      float mx = -3.0e38f;
      for (int m = lane; m < 96; m += 32) mx = fmaxf(mx, sc[l * 96 + m]);
      for (int off = 16; off; off >>= 1)
        mx = fmaxf(mx, __shfl_xor_sync(0xffffffffu, mx, off));
      float s = 0.f;
      for (int m = lane; m < 96; m += 32) {
        float e = expf(sc[l * 96 + m] - mx);
        sc[l * 96 + m] = e;
        s += e;
      }
      for (int off = 16; off; off >>= 1)
        s += __shfl_xor_sync(0xffffffffu, s, off);
      if (lane == 0) {
        rinv[l] = 1.0f / s;
        rowz[l] = mx + logf(s);
      }
    }
  }
  asm volatile("cp.async.wait_group 0;");
  __syncthreads();

  // output: thread owns 4 d (float4) x 4 rows; V now in smem
  {
    int d4 = tid & 31, g = tid >> 5;
    float4 acc[4];
#pragma unroll
    for (int ll = 0; ll < 4; ll++) acc[ll] = {0.f, 0.f, 0.f, 0.f};
    for (int m = 0; m < 96; m++) {
      float4 v = *(const float4*)&skv[m * kQS + d4 * 4];
#pragma unroll
      for (int ll = 0; ll < 4; ll++) {
        float s = sc[(g * 4 + ll) * 96 + m];
        acc[ll].x += s * v.x;
        acc[ll].y += s * v.y;
        acc[ll].z += s * v.z;
        acc[ll].w += s * v.w;
      }
    }
#pragma unroll
    for (int ll = 0; ll < 4; ll++) {
      int l = g * 4 + ll;
      float ri = rinv[l];
      float4 o = {acc[ll].x * ri, acc[ll].y * ri, acc[ll].z * ri,
                  acc[ll].w * ri};
      *(float4*)(g_o + (size_t)(brh * kT + qid[l]) * kD + d4 * 4) = o;
    }
  }
  if (tid < 32) g_z[brh * kT + qid[tid]] = rowz[tid];
}

// ---------------- combine rounds (+ fused bf16 hi/lo split) ----------------
__global__ __launch_bounds__(256) void combine_kernel() {
  int idx = blockIdx.x * 256 + threadIdx.x;
  int d = idx & 127;
  int t = (idx >> 7) & (kT - 1);
  int h = (idx >> 18) & 7;
  int b = idx >> 21;
  int i0 = ((b * kR + 0) * kH + h) * kT + t;
  int i1 = ((b * kR + 1) * kH + h) * kT + t;
  float z0 = g_z[i0], z1 = g_z[i1];
  float m = fmaxf(z0, z1);
  float e0 = expf(z0 - m), e1 = expf(z1 - m);
  float inv = 1.0f / (e0 + e1);
  float val =
      (e0 * g_o[(size_t)i0 * kD + d] + e1 * g_o[(size_t)i1 * kD + d]) * inv;
  __nv_bfloat16 hi = __float2bfloat16(val);
  __nv_bfloat16 lo = __float2bfloat16(val - __bfloat162float(hi));
  size_t o = (size_t)(t * kB + b) * kE + h * kD + d;
  g_Ahi[o] = hi;
  g_Alo[o] = lo;
}

// ---------------- launch ----------------
extern "C" void kernel_launch(void* const* d_in, const int* in_sizes, int n_in,
                              void* d_out, int out_size) {
  (void)in_sizes;
  (void)n_in;
  (void)out_size;
  const float* query = (const float*)d_in[0];
  const float* value = (const float*)d_in[2];
  const float* Wq = (const float*)d_in[3];
  const float* bq = (const float*)d_in[4];
  const float* Wv = (const float*)d_in[5];
  const float* bv = (const float*)d_in[6];
  const float* Wo = (const float*)d_in[7];
  const float* bo = (const float*)d_in[8];
  const float* hw = (const float*)d_in[9];
  float* out = (float*)d_out;

  float *pQF, *pV;
  cudaGetSymbolAddress((void**)&pQF, g_QF);
  cudaGetSymbolAddress((void**)&pV, g_V);
  __nv_bfloat16 *pAH, *pAL, *pVH, *pVL;
  cudaGetSymbolAddress((void**)&pAH, g_Ahi);
  cudaGetSymbolAddress((void**)&pAL, g_Alo);
  cudaGetSymbolAddress((void**)&pVH, g_Vhi);
  cudaGetSymbolAddress((void**)&pVL, g_Vlo);
  __nv_bfloat16 *pWqH, *pWqL, *pWvH, *pWvL, *pWoH, *pWoL;
  cudaGetSymbolAddress((void**)&pWqH, g_WqThi);
  cudaGetSymbolAddress((void**)&pWqL, g_WqTlo);
  cudaGetSymbolAddress((void**)&pWvH, g_WvThi);
  cudaGetSymbolAddress((void**)&pWvL, g_WvTlo);
  cudaGetSymbolAddress((void**)&pWoH, g_WoThi);
  cudaGetSymbolAddress((void**)&pWoL, g_WoTlo);

  cudaFuncSetAttribute(gemm_mma, cudaFuncAttributeMaxDynamicSharedMemorySize,
                       kGSmem);
  cudaFuncSetAttribute(attn_kernel, cudaFuncAttributeMaxDynamicSharedMemorySize,
                       ATTN_SMEM);
  cudaFuncSetAttribute(prepM_kernel, cudaFuncAttributeMaxDynamicSharedMemorySize,
                       kPrepSmem);

  static cudaStream_t s2 = nullptr;
  static cudaEvent_t evF = nullptr, evJ = nullptr;
  if (s2 == nullptr) {
    cudaStreamCreateWithFlags(&s2, cudaStreamNonBlocking);
    cudaEventCreateWithFlags(&evF, cudaEventDisableTiming);
    cudaEventCreateWithFlags(&evJ, cudaEventDisableTiming);
  }

  dim3 tgrid(32, 32);
  dim3 tblk(32, 8);
  dim3 ggrid(kE / 128, kTB / 128);

  bool use_side = (s2 != nullptr);
  cudaStream_t sv = use_side ? s2 : (cudaStream_t)0;

  if (use_side) {
    cudaEventRecord(evF, 0);
    cudaStreamWaitEvent(s2, evF, 0);
  }

  // ---- side chain: V projection + prep (independent of Q chain) ----
  wsplit_kernel<<<tgrid, tblk, 0, sv>>>(Wv, pWvH, pWvL);
  wsplit_kernel<<<tgrid, tblk, 0, sv>>>(Wo, pWoH, pWoL);
  asplit_kernel<<<(kTB * kE / 4) / 256, 256, 0, sv>>>(value, pVH, pVL);
  prepM_kernel<<<dim3(16, 8), 128, kPrepSmem, sv>>>(Wq, bq, hw);
  linhash_kernel<<<kTB / 8, 256, 0, sv>>>(query);
  sort_kernel<<<kB * kR * kH, 256, 0, sv>>>();
  mask_kernel<<<kB * kR * kH * kC, 128, 0, sv>>>();
  gemm_mma<<<ggrid, 256, kGSmem, sv>>>(pVH, pVL, pWvH, pWvL, bv, pV);

  // ---- main chain: Q projection ----
  wsplit_kernel<<<tgrid, tblk>>>(Wq, pWqH, pWqL);
  asplit_kernel<<<(kTB * kE / 4) / 256, 256>>>(query, pAH, pAL);
  gemm_mma<<<ggrid, 256, kGSmem>>>(pAH, pAL, pWqH, pWqL, bq, pQF);
  normalize_kernel<<<kTB, 256>>>();

  if (use_side) {
    cudaEventRecord(evJ, s2);
    cudaStreamWaitEvent((cudaStream_t)0, evJ, 0);
  }

  attn_kernel<<<kB * kR * kH * kC, 256, ATTN_SMEM>>>();
  combine_kernel<<<(kB * kH * kT * kD) / 256, 256>>>();
  gemm_mma<<<ggrid, 256, kGSmem>>>(pAH, pAL, pWoH, pWoL, bo, out);
}

// round 11
// speedup vs baseline: 2.3076x; 1.0899x over previous
#include <cuda_runtime.h>
#include <cuda_bf16.h>
#include <math.h>
#include <stdint.h>

// ---------------- problem constants ----------------
constexpr int kT = 2048;
constexpr int kB = 2;
constexpr int kE = 1024;
constexpr int kH = 8;
constexpr int kD = 128;
constexpr int kR = 2;
constexpr int kNH = 8;
constexpr int kCH = 32;
constexpr int kC = kT / kCH;  // 64
constexpr int kM = 3 * kCH;   // 96
constexpr int kTB = kT * kB;  // 4096

constexpr float kScale = 0.08838834764831845f;  // D^-0.5
constexpr float kInfM = 1.0e16f;
constexpr float kBigM = 1.0e8f;
constexpr float kLog2 = 0.6931471805599453f;

// ---------------- device scratch ----------------
__device__ float g_QF[kTB * kE];
__device__ float g_Q[kTB * kE];
__device__ float g_K[kTB * kE];
__device__ float g_V[kTB * kE];
__device__ float g_o[kB * kR * kH * kT * kD];
__device__ float g_z[kB * kR * kH * kT];
__device__ int g_hash[kTB * 16];  // [tb][r*8+h]
__device__ int g_pq[kB * kR * kH * kT];
__device__ int g_invq[kB * kR * kH * kT];
__device__ unsigned g_mask[kB * kR * kH * kC * (kT / 32)];
__device__ float g_Mq[kE * 64];
__device__ float g_cq[64];
__device__ __nv_bfloat16 g_Ahi[kTB * kE];
__device__ __nv_bfloat16 g_Alo[kTB * kE];
__device__ __nv_bfloat16 g_Vhi[kTB * kE];
__device__ __nv_bfloat16 g_Vlo[kTB * kE];
__device__ __nv_bfloat16 g_WqThi[kE * kE];
__device__ __nv_bfloat16 g_WqTlo[kE * kE];
__device__ __nv_bfloat16 g_WvThi[kE * kE];
__device__ __nv_bfloat16 g_WvTlo[kE * kE];
__device__ __nv_bfloat16 g_WoThi[kE * kE];
__device__ __nv_bfloat16 g_WoTlo[kE * kE];

// ---------------- helpers ----------------
__device__ __forceinline__ uint32_t smem_u32(const void* p) {
  uint32_t a;
  asm("{ .reg .u64 t; cvta.to.shared.u64 t, %1; cvt.u32.u64 %0, t; }"
      : "=r"(a) : "l"(p));
  return a;
}
__device__ __forceinline__ void ldsm_x4(uint32_t* r, uint32_t addr) {
  asm volatile(
      "ldmatrix.sync.aligned.m8n8.x4.shared.b16 {%0,%1,%2,%3}, [%4];"
      : "=r"(r[0]), "=r"(r[1]), "=r"(r[2]), "=r"(r[3]) : "r"(addr));
}
__device__ __forceinline__ void ldsm_x2(uint32_t* r, uint32_t addr) {
  asm volatile(
      "ldmatrix.sync.aligned.m8n8.x2.shared.b16 {%0,%1}, [%2];"
      : "=r"(r[0]), "=r"(r[1]) : "r"(addr));
}
__device__ __forceinline__ void mma16816(float* d, const uint32_t* a,
                                         const uint32_t* b) {
  asm volatile(
      "mma.sync.aligned.m16n8k16.row.col.f32.bf16.bf16.f32 "
      "{%0,%1,%2,%3}, {%4,%5,%6,%7}, {%8,%9}, {%0,%1,%2,%3};"
      : "+f"(d[0]), "+f"(d[1]), "+f"(d[2]), "+f"(d[3])
      : "r"(a[0]), "r"(a[1]), "r"(a[2]), "r"(a[3]), "r"(b[0]), "r"(b[1]));
}
__device__ __forceinline__ void cp16(uint32_t dst, const void* src) {
  asm volatile("cp.async.cg.shared.global [%0], [%1], 16;" ::"r"(dst),
               "l"(src));
}

// ---------------- A fp32 -> bf16 hi/lo split ----------------
__global__ __launch_bounds__(256) void asplit_kernel(
    const float* __restrict__ A, __nv_bfloat16* __restrict__ outhi,
    __nv_bfloat16* __restrict__ outlo) {
  int idx = blockIdx.x * 256 + threadIdx.x;
  float4 v = ((const float4*)A)[idx];
  __nv_bfloat16 h0 = __float2bfloat16(v.x), h1 = __float2bfloat16(v.y);
  __nv_bfloat16 h2 = __float2bfloat16(v.z), h3 = __float2bfloat16(v.w);
  __nv_bfloat16 l0 = __float2bfloat16(v.x - __bfloat162float(h0));
  __nv_bfloat16 l1 = __float2bfloat16(v.y - __bfloat162float(h1));
  __nv_bfloat16 l2 = __float2bfloat16(v.z - __bfloat162float(h2));
  __nv_bfloat16 l3 = __float2bfloat16(v.w - __bfloat162float(h3));
  __nv_bfloat162 ph0 = {h0, h1}, ph1 = {h2, h3};
  __nv_bfloat162 pl0 = {l0, l1}, pl1 = {l2, l3};
  uint2 uh = {*(uint32_t*)&ph0, *(uint32_t*)&ph1};
  uint2 ul = {*(uint32_t*)&pl0, *(uint32_t*)&pl1};
  ((uint2*)outhi)[idx] = uh;
  ((uint2*)outlo)[idx] = ul;
}

// ---------------- weight transpose + bf16 hi/lo split ----------------
__global__ __launch_bounds__(256) void wsplit_kernel(
    const float* __restrict__ W, __nv_bfloat16* __restrict__ hi,
    __nv_bfloat16* __restrict__ lo) {
  __shared__ float t[32][33];
  int bx = blockIdx.x * 32;
  int by = blockIdx.y * 32;
  int x = threadIdx.x, y = threadIdx.y;
#pragma unroll
  for (int i = 0; i < 32; i += 8)
    t[y + i][x] = W[(size_t)(by + y + i) * kE + bx + x];
  __syncthreads();
#pragma unroll
  for (int i = 0; i < 32; i += 8) {
    float v = t[x][y + i];
    __nv_bfloat16 h = __float2bfloat16(v);
    __nv_bfloat16 l = __float2bfloat16(v - __bfloat162float(h));
    size_t o = (size_t)(bx + y + i) * kE + by + x;
    hi[o] = h;
    lo[o] = l;
  }
}

// ---------------- bf16x3 HMMA GEMM (4 warps, 64x64 warp tiles) ----------------
constexpr int kTileB = 128 * 80;
constexpr int kStageB = 4 * kTileB;
constexpr int kGSmem = 2 * kStageB;  // 81920

__global__ __launch_bounds__(128) void gemm_mma(
    const __nv_bfloat16* __restrict__ Ahi, const __nv_bfloat16* __restrict__ Alo,
    const __nv_bfloat16* __restrict__ Bhi, const __nv_bfloat16* __restrict__ Blo,
    const float* __restrict__ bias, float* __restrict__ C) {
  extern __shared__ char smc[];
  uint32_t sbase = smem_u32(smc);
  int tid = threadIdx.x;
  int lane = tid & 31, wid = tid >> 5;
  int row0 = blockIdx.y * 128, col0 = blockIdx.x * 128;
  int m0w = (wid >> 1) * 64, n0w = (wid & 1) * 64;

  float acc[4][8][4];
#pragma unroll
  for (int i = 0; i < 4; i++)
#pragma unroll
    for (int j = 0; j < 8; j++)
#pragma unroll
      for (int q = 0; q < 4; q++) acc[i][j][q] = 0.f;

  const __nv_bfloat16* srcs[4] = {Ahi, Alo, Bhi, Blo};

  auto issue = [&](int ch, int s) {
    int k0 = ch * 32;
#pragma unroll
    for (int t = 0; t < 4; t++) {
      const __nv_bfloat16* src = srcs[t];
      int base0 = (t < 2) ? row0 : col0;
#pragma unroll
      for (int i = 0; i < 4; i++) {
        int idx = tid + i * 128;  // 0..511
        int row = idx >> 2, seg = idx & 3;
        uint32_t dst = sbase + s * kStageB + t * kTileB + row * 80 + seg * 16;
        cp16(dst, src + (size_t)(base0 + row) * kE + k0 + seg * 8);
      }
    }
    asm volatile("cp.async.commit_group;");
  };

  issue(0, 0);
  for (int ch = 0; ch < 32; ch++) {
    int s = ch & 1;
    if (ch + 1 < 32) {
      issue(ch + 1, s ^ 1);
      asm volatile("cp.async.wait_group 1;");
    } else {
      asm volatile("cp.async.wait_group 0;");
    }
    __syncthreads();
    uint32_t abase = sbase + s * kStageB;
    uint32_t bbase = sbase + s * kStageB + 2 * kTileB;
#pragma unroll
    for (int k16 = 0; k16 < 2; k16++) {
      uint32_t a_hi[4][4], a_lo[4][4], bf[8][2];
      uint32_t aoff = (k16 * 16 + (lane >> 4) * 8) * 2;
      uint32_t boff = (k16 * 16 + ((lane >> 3) & 1) * 8) * 2;
#pragma unroll
      for (int mt = 0; mt < 4; mt++) {
        uint32_t ra = (m0w + mt * 16 + (lane & 15)) * 80 + aoff;
        ldsm_x4(a_hi[mt], abase + ra);
        ldsm_x4(a_lo[mt], abase + kTileB + ra);
      }
#pragma unroll
      for (int nt = 0; nt < 8; nt++)
        ldsm_x2(bf[nt], bbase + (n0w + nt * 8 + (lane & 7)) * 80 + boff);
#pragma unroll
      for (int mt = 0; mt < 4; mt++)
#pragma unroll
        for (int nt = 0; nt < 8; nt++) mma16816(acc[mt][nt], a_hi[mt], bf[nt]);
#pragma unroll
      for (int mt = 0; mt < 4; mt++)
#pragma unroll
        for (int nt = 0; nt < 8; nt++) mma16816(acc[mt][nt], a_lo[mt], bf[nt]);
#pragma unroll
      for (int nt = 0; nt < 8; nt++)
        ldsm_x2(bf[nt],
                bbase + kTileB + (n0w + nt * 8 + (lane & 7)) * 80 + boff);
#pragma unroll
      for (int mt = 0; mt < 4; mt++)
#pragma unroll
        for (int nt = 0; nt < 8; nt++) mma16816(acc[mt][nt], a_hi[mt], bf[nt]);
    }
    __syncthreads();
  }
#pragma unroll
  for (int mt = 0; mt < 4; mt++) {
#pragma unroll
    for (int nt = 0; nt < 8; nt++) {
      int r = row0 + m0w + mt * 16 + (lane >> 2);
      int cc = col0 + n0w + nt * 8 + (lane & 3) * 2;
      float2 b0 = *(const float2*)(bias + cc);
      float2 v0 = {acc[mt][nt][0] + b0.x, acc[mt][nt][1] + b0.y};
      *(float2*)(C + (size_t)r * kE + cc) = v0;
      float2 v1 = {acc[mt][nt][2] + b0.x, acc[mt][nt][3] + b0.y};
      *(float2*)(C + (size_t)(r + 8) * kE + cc) = v1;
    }
  }
}

// ---------------- exact hash path ----------------
constexpr int kPrepSmem = (128 * 132 + 512) * 4;
__global__ __launch_bounds__(128) void prepM_kernel(
    const float* __restrict__ Wq, const float* __restrict__ bq,
    const float* __restrict__ hw) {
  extern __shared__ float ps[];
  float* wtile = ps;
  float* hws = ps + 128 * 132;
  int rh = blockIdx.x, ec = blockIdx.y;
  int h = rh & 7;
  int tid = threadIdx.x;
  for (int i = tid; i < 128; i += 128)
    *(float4*)&hws[i * 4] = *(const float4*)&hw[rh * 512 + i * 4];
#pragma unroll
  for (int it = 0; it < 32; it++) {
    int i = tid + it * 128;
    int row = i >> 5, c4 = i & 31;
    float4 v = *(const float4*)(Wq + (size_t)(ec * 128 + row) * kE + h * kD +
                                c4 * 4);
    *(float4*)&wtile[row * 132 + c4 * 4] = v;
  }
  __syncthreads();
  float s0 = 0.f, s1 = 0.f, s2 = 0.f, s3 = 0.f;
  const float* wr = wtile + tid * 132;
#pragma unroll 4
  for (int d = 0; d < kD; d++) {
    float w = wr[d];
    s0 += w * hws[d * 4 + 0];
    s1 += w * hws[d * 4 + 1];
    s2 += w * hws[d * 4 + 2];
    s3 += w * hws[d * 4 + 3];
  }
  float4 o = {s0, s1, s2, s3};
  *(float4*)(g_Mq + (size_t)(ec * 128 + tid) * 64 + rh * 4) = o;
  if (ec == 0 && tid < 4) {
    float c = 0.f;
    for (int d = 0; d < kD; d++) c += bq[h * kD + d] * hws[d * 4 + tid];
    g_cq[rh * 4 + tid] = c;
  }
}

__global__ __launch_bounds__(256) void linhash_kernel(
    const float* __restrict__ query) {
  __shared__ float slin[8][64];
  int warp = threadIdx.x >> 5, lane = threadIdx.x & 31;
  int tb = blockIdx.x * 8 + warp;
  float acc0 = g_cq[lane], acc1 = g_cq[lane + 32];
  for (int e0 = 0; e0 < kE; e0 += 32) {
    float xv = query[(size_t)tb * kE + e0 + lane];
#pragma unroll
    for (int l2 = 0; l2 < 32; l2++) {
      float v = __shfl_sync(0xffffffffu, xv, l2);
      acc0 += v * g_Mq[(e0 + l2) * 64 + lane];
      acc1 += v * g_Mq[(e0 + l2) * 64 + lane + 32];
    }
  }
  slin[warp][lane] = acc0;
  slin[warp][lane + 32] = acc1;
  __syncwarp();
  if (lane < 16) {
    const float* p = &slin[warp][lane * 4];
    float best = p[0];
    int bi = 0;
#pragma unroll
    for (int n = 1; n < 4; n++)
      if (p[n] > best) { best = p[n]; bi = n; }
#pragma unroll
    for (int n = 0; n < 4; n++)
      if (-p[n] > best) { best = -p[n]; bi = 4 + n; }
    g_hash[tb * 16 + lane] = bi;
  }
}

// ---------------- normalize + scale ----------------
__global__ __launch_bounds__(256) void normalize_kernel() {
  int row = blockIdx.x;
  const float* x = g_QF + (size_t)row * kE;
  __shared__ float red[256];
  int tid = threadIdx.x;
  float s = 0.f;
#pragma unroll
  for (int i = 0; i < 4; i++) {
    float v = x[tid + i * 256];
    s += v * v;
  }
  red[tid] = s;
  __syncthreads();
  for (int off = 128; off > 0; off >>= 1) {
    if (tid < off) red[tid] += red[tid + off];
    __syncthreads();
  }
  float invn = 1.0f / sqrtf(red[0]);
#pragma unroll
  for (int i = 0; i < 4; i++) {
    int e = tid + i * 256;
    float v = x[e];
    g_Q[(size_t)row * kE + e] = v * kScale;
    g_K[(size_t)row * kE + e] = v * invn;
  }
}

// ---------------- stable counting sort per (b,r,h), scan-based ----------------
__global__ __launch_bounds__(256) void sort_kernel() {
  int brh = blockIdx.x;
  int h = brh & 7;
  int r = (brh >> 3) & 1;
  int b = brh >> 4;
  __shared__ int cntmat[kNH][256];
  __shared__ int btot[kNH];
  __shared__ int bbase[kNH];
  int tid = threadIdx.x;
  int w = tid >> 5, lane = tid & 31;

  int vals[8];
  int cnt[kNH];
#pragma unroll
  for (int i = 0; i < kNH; i++) cnt[i] = 0;
#pragma unroll
  for (int i = 0; i < 8; i++) {
    int t = tid * 8 + i;
    int v = g_hash[(t * kB + b) * 16 + r * 8 + h];
    vals[i] = v;
    cnt[v]++;
  }
#pragma unroll
  for (int i = 0; i < kNH; i++) cntmat[i][tid] = cnt[i];
  __syncthreads();
  {
    int run = 0;
#pragma unroll
    for (int chk = 0; chk < 8; chk++) {
      int orig = cntmat[w][chk * 32 + lane];
      int x = orig;
#pragma unroll
      for (int off = 1; off < 32; off <<= 1) {
        int y = __shfl_up_sync(0xffffffffu, x, off);
        if (lane >= off) x += y;
      }
      cntmat[w][chk * 32 + lane] = run + x - orig;
      run += __shfl_sync(0xffffffffu, x, 31);
    }
    if (lane == 0) btot[w] = run;
  }
  __syncthreads();
  if (tid == 0) {
    int s = 0;
    for (int i = 0; i < kNH; i++) {
      bbase[i] = s;
      s += btot[i];
    }
  }
  __syncthreads();
  int off[kNH];
#pragma unroll
  for (int i = 0; i < kNH; i++) off[i] = bbase[i] + cntmat[i][tid];
#pragma unroll
  for (int i = 0; i < 8; i++) {
    int v = vals[i];
    int pos = off[v]++;
    int t = tid * 8 + i;
    g_pq[brh * kT + pos] = t;
    g_invq[brh * kT + t] = pos;
  }
}

// ---------------- per-chunk window bitmask ----------------
__global__ __launch_bounds__(128) void mask_kernel() {
  int blk = blockIdx.x;
  int c = blk & (kC - 1);
  int brh = blk >> 6;
  unsigned* mw = g_mask + (size_t)blk * (kT / 32);
  int tid = threadIdx.x;
  if (tid < kT / 32) mw[tid] = 0u;
  __syncthreads();
  if (tid < kM) {
    int cc2 = (c + (tid >> 5) + kC - 1) & (kC - 1);
    int pos = cc2 * kCH + (tid & 31);
    int id = g_pq[brh * kT + pos];
    atomicOr(&mw[id >> 5], 1u << (id & 31));
  }
}

// ---------------- attention ----------------
constexpr int kQS = 132;
constexpr int ATTN_SMEM =
    (32 * kQS + 96 * kQS + 32 * 96 + 64) * 4 + (32 * 3 + 96 * 2) * 4;

__global__ __launch_bounds__(256, 2) void attn_kernel() {
  extern __shared__ float sm[];
  float* sq = sm;
  float* skv = sq + 32 * kQS;  // K, then V
  float* sc = skv + 96 * kQS;
  float* rinv = sc + 32 * 96;
  float* rowz = rinv + 32;
  int* qid = (int*)(rowz + 32);
  int* qhh = qid + 32;
  int* oc2 = qhh + 32;
  int* kid = oc2 + 32;
  int* khh = kid + 96;
  uint32_t skv_base = smem_u32(skv);

  int blk = blockIdx.x;
  int c = blk & (kC - 1);
  int brh = blk >> 6;
  int h = brh & 7;
  int r = (brh >> 3) & 1;
  int b = brh >> 4;
  int brho = (b * kR + (1 - r)) * kH + h;
  int tid = threadIdx.x;

  if (tid < 32) {
    int ts = c * kCH + tid;
    int tok = g_pq[brh * kT + ts];
    qid[tid] = tok;
    qhh[tid] = g_hash[(tok * kB + b) * 16 + r * 8 + h];
    oc2[tid] = g_invq[brho * kT + tok] >> 5;
  } else if (tid < 128) {
    int m = tid - 32;
    int cc2 = (c + (m >> 5) + kC - 1) & (kC - 1);
    int pos = cc2 * kCH + (m & 31);
    int tokk = g_pq[brh * kT + pos];
    kid[m] = tokk;
    khh[m] = g_hash[(tokk * kB + b) * 16 + r * 8 + h];
  }
  __syncthreads();

#pragma unroll
  for (int i = 0; i < 4; i++) {
    int idx = tid + i * 256;
    int l = idx >> 5, d4 = idx & 31;
    float4 v =
        *(const float4*)(g_Q + (size_t)(qid[l] * kB + b) * kE + h * kD + d4 * 4);
    *(float4*)&sq[l * kQS + d4 * 4] = v;
  }
#pragma unroll
  for (int i = 0; i < 12; i++) {
    int idx = tid + i * 256;
    int m = idx >> 5, d4 = idx & 31;
    *(float4*)&skv[m * kQS + d4 * 4] =
        *(const float4*)(g_K + (size_t)(kid[m] * kB + b) * kE + h * kD + d4 * 4);
  }
  __syncthreads();

  // scores: warp = 4 q-rows, lane = k-column (m = lane + 32j).
  // q loads are warp-broadcast (free); k loads stride 132 floats are
  // conflict-free per LDS.128 quarter-warp phases.
  {
    int w = tid >> 5, lane = tid & 31;
    float acc[4][3];
#pragma unroll
    for (int rr = 0; rr < 4; rr++)
#pragma unroll
      for (int j = 0; j < 3; j++) acc[rr][j] = 0.f;
    for (int d4 = 0; d4 < 32; d4++) {
      float4 kv[3];
#pragma unroll
      for (int j = 0; j < 3; j++)
        kv[j] = *(const float4*)&skv[(lane + 32 * j) * kQS + d4 * 4];
#pragma unroll
      for (int rr = 0; rr < 4; rr++) {
        float4 qv = *(const float4*)&sq[(w * 4 + rr) * kQS + d4 * 4];
#pragma unroll
        for (int j = 0; j < 3; j++)
          acc[rr][j] +=
              qv.x * kv[j].x + qv.y * kv[j].y + qv.z * kv[j].z + qv.w * kv[j].w;
      }
    }
#pragma unroll
    for (int j = 0; j < 3; j++) {
      int m = (tid & 31) + 32 * j;
      int id = kid[m];
      int kh = khh[m];
#pragma unroll
      for (int rr = 0; rr < 4; rr++) {
        int l = w * 4 + rr;
        float s = acc[rr][j];
        if (qhh[l] != kh) s -= kInfM;
        if (qid[l] == id) s -= kBigM;
        const unsigned* mw =
            g_mask + (size_t)(brho * kC + oc2[l]) * (kT / 32);
        if ((mw[id >> 5] >> (id & 31)) & 1u) s -= kLog2;
        sc[l * 96 + m] = s;
      }
    }
  }
  __syncthreads();  // all K reads done; safe to overwrite skv with V

  // issue async V loads into skv; overlap with softmax below
#pragma unroll
  for (int i = 0; i < 12; i++) {
    int idx = tid + i * 256;
    int m = idx >> 5, seg = idx & 31;
    cp16(skv_base + m * (kQS * 4) + seg * 16,
         g_V + (size_t)(kid[m] * kB + b) * kE + h * kD + seg * 4);
  }
  asm volatile("cp.async.commit_group;");

  {
    int w = tid >> 5, lane = tid & 31;
    for (int rr = 0; rr < 4; rr++) {
      int l = w * 4 + rr;
      float mx = -3.0e38f;
      for (int m = lane; m < 96; m += 32) mx = fmaxf(mx, sc[l * 96 + m]);
      for (int off = 16; off; off >>= 1)
        mx = fmaxf(mx, __shfl_xor_sync(0xffffffffu, mx, off));
      float s = 0.f;
      for (int m = lane; m < 96; m += 32) {
        float e = expf(sc[l * 96 + m] - mx);
        sc[l * 96 + m] = e;
        s += e;
      }
      for (int off = 16; off; off >>= 1)
        s += __shfl_xor_sync(0xffffffffu, s, off);
      if (lane == 0) {
        rinv[l] = 1.0f / s;
        rowz[l] = mx + logf(s);
      }
    }
  }
  asm volatile("cp.async.wait_group 0;");
  __syncthreads();

  // output: thread owns 4 d (float4) x 4 rows; V now in smem
  {
    int d4 = tid & 31, g = tid >> 5;
    float4 acc[4];
#pragma unroll
    for (int ll = 0; ll < 4; ll++) acc[ll] = {0.f, 0.f, 0.f, 0.f};
    for (int m = 0; m < 96; m++) {
      float4 v = *(const float4*)&skv[m * kQS + d4 * 4];
#pragma unroll
      for (int ll = 0; ll < 4; ll++) {
        float s = sc[(g * 4 + ll) * 96 + m];
        acc[ll].x += s * v.x;
        acc[ll].y += s * v.y;
        acc[ll].z += s * v.z;
        acc[ll].w += s * v.w;
      }
    }
#pragma unroll
    for (int ll = 0; ll < 4; ll++) {
      int l = g * 4 + ll;
      float ri = rinv[l];
      float4 o = {acc[ll].x * ri, acc[ll].y * ri, acc[ll].z * ri,
                  acc[ll].w * ri};
      *(float4*)(g_o + (size_t)(brh * kT + qid[l]) * kD + d4 * 4) = o;
    }
  }
  if (tid < 32) g_z[brh * kT + qid[tid]] = rowz[tid];
}

// ---------------- combine rounds (+ fused bf16 hi/lo split) ----------------
__global__ __launch_bounds__(256) void combine_kernel() {
  int idx = blockIdx.x * 256 + threadIdx.x;
  int d = idx & 127;
  int t = (idx >> 7) & (kT - 1);
  int h = (idx >> 18) & 7;
  int b = idx >> 21;
  int i0 = ((b * kR + 0) * kH + h) * kT + t;
  int i1 = ((b * kR + 1) * kH + h) * kT + t;
  float z0 = g_z[i0], z1 = g_z[i1];
  float m = fmaxf(z0, z1);
  float e0 = expf(z0 - m), e1 = expf(z1 - m);
  float inv = 1.0f / (e0 + e1);
  float val =
      (e0 * g_o[(size_t)i0 * kD + d] + e1 * g_o[(size_t)i1 * kD + d]) * inv;
  __nv_bfloat16 hi = __float2bfloat16(val);
  __nv_bfloat16 lo = __float2bfloat16(val - __bfloat162float(hi));
  size_t o = (size_t)(t * kB + b) * kE + h * kD + d;
  g_Ahi[o] = hi;
  g_Alo[o] = lo;
}

// ---------------- launch ----------------
extern "C" void kernel_launch(void* const* d_in, const int* in_sizes, int n_in,
                              void* d_out, int out_size) {
  (void)in_sizes;
  (void)n_in;
  (void)out_size;
  const float* query = (const float*)d_in[0];
  const float* value = (const float*)d_in[2];
  const float* Wq = (const float*)d_in[3];
  const float* bq = (const float*)d_in[4];
  const float* Wv = (const float*)d_in[5];
  const float* bv = (const float*)d_in[6];
  const float* Wo = (const float*)d_in[7];
  const float* bo = (const float*)d_in[8];
  const float* hw = (const float*)d_in[9];
  float* out = (float*)d_out;

  float *pQF, *pV;
  cudaGetSymbolAddress((void**)&pQF, g_QF);
  cudaGetSymbolAddress((void**)&pV, g_V);
  __nv_bfloat16 *pAH, *pAL, *pVH, *pVL;
  cudaGetSymbolAddress((void**)&pAH, g_Ahi);
  cudaGetSymbolAddress((void**)&pAL, g_Alo);
  cudaGetSymbolAddress((void**)&pVH, g_Vhi);
  cudaGetSymbolAddress((void**)&pVL, g_Vlo);
  __nv_bfloat16 *pWqH, *pWqL, *pWvH, *pWvL, *pWoH, *pWoL;
  cudaGetSymbolAddress((void**)&pWqH, g_WqThi);
  cudaGetSymbolAddress((void**)&pWqL, g_WqTlo);
  cudaGetSymbolAddress((void**)&pWvH, g_WvThi);
  cudaGetSymbolAddress((void**)&pWvL, g_WvTlo);
  cudaGetSymbolAddress((void**)&pWoH, g_WoThi);
  cudaGetSymbolAddress((void**)&pWoL, g_WoTlo);

  cudaFuncSetAttribute(gemm_mma, cudaFuncAttributeMaxDynamicSharedMemorySize,
                       kGSmem);
  cudaFuncSetAttribute(attn_kernel, cudaFuncAttributeMaxDynamicSharedMemorySize,
                       ATTN_SMEM);
  cudaFuncSetAttribute(prepM_kernel, cudaFuncAttributeMaxDynamicSharedMemorySize,
                       kPrepSmem);

  static cudaStream_t s2 = nullptr;
  static cudaEvent_t evF = nullptr, evJ = nullptr;
  if (s2 == nullptr) {
    cudaStreamCreateWithFlags(&s2, cudaStreamNonBlocking);
    cudaEventCreateWithFlags(&evF, cudaEventDisableTiming);
    cudaEventCreateWithFlags(&evJ, cudaEventDisableTiming);
  }

  dim3 tgrid(32, 32);
  dim3 tblk(32, 8);
  dim3 ggrid(kE / 128, kTB / 128);

  bool use_side = (s2 != nullptr);
  cudaStream_t sv = use_side ? s2 : (cudaStream_t)0;

  if (use_side) {
    cudaEventRecord(evF, 0);
    cudaStreamWaitEvent(s2, evF, 0);
  }

  // ---- side chain: V projection + prep (independent of Q chain) ----
  wsplit_kernel<<<tgrid, tblk, 0, sv>>>(Wv, pWvH, pWvL);
  wsplit_kernel<<<tgrid, tblk, 0, sv>>>(Wo, pWoH, pWoL);
  asplit_kernel<<<(kTB * kE / 4) / 256, 256, 0, sv>>>(value, pVH, pVL);
  prepM_kernel<<<dim3(16, 8), 128, kPrepSmem, sv>>>(Wq, bq, hw);
  linhash_kernel<<<kTB / 8, 256, 0, sv>>>(query);
  sort_kernel<<<kB * kR * kH, 256, 0, sv>>>();
  mask_kernel<<<kB * kR * kH * kC, 128, 0, sv>>>();
  gemm_mma<<<ggrid, 128, kGSmem, sv>>>(pVH, pVL, pWvH, pWvL, bv, pV);

  // ---- main chain: Q projection ----
  wsplit_kernel<<<tgrid, tblk>>>(Wq, pWqH, pWqL);
  asplit_kernel<<<(kTB * kE / 4) / 256, 256>>>(query, pAH, pAL);
  gemm_mma<<<ggrid, 128, kGSmem>>>(pAH, pAL, pWqH, pWqL, bq, pQF);
  normalize_kernel<<<kTB, 256>>>();

  if (use_side) {
    cudaEventRecord(evJ, s2);
    cudaStreamWaitEvent((cudaStream_t)0, evJ, 0);
  }

  attn_kernel<<<kB * kR * kH * kC, 256, ATTN_SMEM>>>();
  combine_kernel<<<(kB * kH * kT * kD) / 256, 256>>>();
  gemm_mma<<<ggrid, 128, kGSmem>>>(pAH, pAL, pWoH, pWoL, bo, out);
}

// round 14
// speedup vs baseline: 2.7154x; 1.1767x over previous
#include <cuda_runtime.h>
#include <cuda_bf16.h>
#include <math.h>
#include <stdint.h>

// ---------------- problem constants ----------------
constexpr int kT = 2048;
constexpr int kB = 2;
constexpr int kE = 1024;
constexpr int kH = 8;
constexpr int kD = 128;
constexpr int kR = 2;
constexpr int kNH = 8;
constexpr int kCH = 32;
constexpr int kC = kT / kCH;  // 64
constexpr int kM = 3 * kCH;   // 96
constexpr int kTB = kT * kB;  // 4096

constexpr float kScale = 0.08838834764831845f;  // D^-0.5
constexpr float kInfM = 1.0e16f;
constexpr float kBigM = 1.0e8f;
constexpr float kLog2 = 0.6931471805599453f;

// ---------------- device scratch ----------------
__device__ float g_QF[kTB * kE];
__device__ float g_o[kB * kR * kH * kT * kD];
__device__ float g_z[kB * kR * kH * kT];
__device__ int g_hash[kTB * 16];  // [tb][r*8+h]
__device__ int g_pq[kB * kR * kH * kT];
__device__ int g_invq[kB * kR * kH * kT];
__device__ unsigned g_mask[kB * kR * kH * kC * (kT / 32)];
__device__ float g_Mq[kE * 64];
__device__ float g_cq[64];
// bf16 hi/lo operand splits
__device__ __nv_bfloat16 g_Ahi[kTB * kE];   // query / combined-out splits
__device__ __nv_bfloat16 g_Alo[kTB * kE];
__device__ __nv_bfloat16 g_Vihi[kTB * kE];  // raw value input splits
__device__ __nv_bfloat16 g_Vilo[kTB * kE];
// projected tensors, bf16 hi/lo (consumed by attention)
__device__ __nv_bfloat16 g_Q16h[kTB * kE];
__device__ __nv_bfloat16 g_Q16l[kTB * kE];
__device__ __nv_bfloat16 g_K16h[kTB * kE];
__device__ __nv_bfloat16 g_K16l[kTB * kE];
__device__ __nv_bfloat16 g_V16h[kTB * kE];
__device__ __nv_bfloat16 g_V16l[kTB * kE];
// transposed + hi/lo split weights, [N=1024][K=1024]
__device__ __nv_bfloat16 g_WqThi[kE * kE];
__device__ __nv_bfloat16 g_WqTlo[kE * kE];
__device__ __nv_bfloat16 g_WvThi[kE * kE];
__device__ __nv_bfloat16 g_WvTlo[kE * kE];
__device__ __nv_bfloat16 g_WoThi[kE * kE];
__device__ __nv_bfloat16 g_WoTlo[kE * kE];

// ---------------- helpers ----------------
__device__ __forceinline__ uint32_t smem_u32(const void* p) {
  uint32_t a;
  asm("{ .reg .u64 t; cvta.to.shared.u64 t, %1; cvt.u32.u64 %0, t; }"
      : "=r"(a) : "l"(p));
  return a;
}
__device__ __forceinline__ void ldsm_x4(uint32_t* r, uint32_t addr) {
  asm volatile(
      "ldmatrix.sync.aligned.m8n8.x4.shared.b16 {%0,%1,%2,%3}, [%4];"
      : "=r"(r[0]), "=r"(r[1]), "=r"(r[2]), "=r"(r[3]) : "r"(addr));
}
__device__ __forceinline__ void ldsm_x2(uint32_t* r, uint32_t addr) {
  asm volatile(
      "ldmatrix.sync.aligned.m8n8.x2.shared.b16 {%0,%1}, [%2];"
      : "=r"(r[0]), "=r"(r[1]) : "r"(addr));
}
__device__ __forceinline__ void ldsm_x2t(uint32_t* r, uint32_t addr) {
  asm volatile(
      "ldmatrix.sync.aligned.m8n8.x2.trans.shared.b16 {%0,%1}, [%2];"
      : "=r"(r[0]), "=r"(r[1]) : "r"(addr));
}
__device__ __forceinline__ void mma16816(float* d, const uint32_t* a,
                                         const uint32_t* b) {
  asm volatile(
      "mma.sync.aligned.m16n8k16.row.col.f32.bf16.bf16.f32 "
      "{%0,%1,%2,%3}, {%4,%5,%6,%7}, {%8,%9}, {%0,%1,%2,%3};"
      : "+f"(d[0]), "+f"(d[1]), "+f"(d[2]), "+f"(d[3])
      : "r"(a[0]), "r"(a[1]), "r"(a[2]), "r"(a[3]), "r"(b[0]), "r"(b[1]));
}
__device__ __forceinline__ void cp16(uint32_t dst, const void* src) {
  asm volatile("cp.async.cg.shared.global [%0], [%1], 16;" ::"r"(dst),
               "l"(src));
}
__device__ __forceinline__ void split_bf16(float v, __nv_bfloat16& h,
                                           __nv_bfloat16& l) {
  h = __float2bfloat16(v);
  l = __float2bfloat16(v - __bfloat162float(h));
}

// ---------------- A fp32 -> bf16 hi/lo split ----------------
__global__ __launch_bounds__(256) void asplit_kernel(
    const float* __restrict__ A, __nv_bfloat16* __restrict__ outhi,
    __nv_bfloat16* __restrict__ outlo) {
  int idx = blockIdx.x * 256 + threadIdx.x;
  float4 v = ((const float4*)A)[idx];
  __nv_bfloat16 h0, h1, h2, h3, l0, l1, l2, l3;
  split_bf16(v.x, h0, l0);
  split_bf16(v.y, h1, l1);
  split_bf16(v.z, h2, l2);
  split_bf16(v.w, h3, l3);
  __nv_bfloat162 ph0 = {h0, h1}, ph1 = {h2, h3};
  __nv_bfloat162 pl0 = {l0, l1}, pl1 = {l2, l3};
  uint2 uh = {*(uint32_t*)&ph0, *(uint32_t*)&ph1};
  uint2 ul = {*(uint32_t*)&pl0, *(uint32_t*)&pl1};
  ((uint2*)outhi)[idx] = uh;
  ((uint2*)outlo)[idx] = ul;
}

// ---------------- weight transpose + bf16 hi/lo split ----------------
__global__ __launch_bounds__(256) void wsplit_kernel(
    const float* __restrict__ W, __nv_bfloat16* __restrict__ hi,
    __nv_bfloat16* __restrict__ lo) {
  __shared__ float t[32][33];
  int bx = blockIdx.x * 32;
  int by = blockIdx.y * 32;
  int x = threadIdx.x, y = threadIdx.y;
#pragma unroll
  for (int i = 0; i < 32; i += 8)
    t[y + i][x] = W[(size_t)(by + y + i) * kE + bx + x];
  __syncthreads();
#pragma unroll
  for (int i = 0; i < 32; i += 8) {
    float v = t[x][y + i];
    __nv_bfloat16 h, l;
    split_bf16(v, h, l);
    size_t o = (size_t)(bx + y + i) * kE + by + x;
    hi[o] = h;
    lo[o] = l;
  }
}

// ---------------- bf16x3 HMMA GEMM (4 warps, 64x64 warp tiles) ----------------
constexpr int kTileB = 128 * 80;
constexpr int kStageB = 4 * kTileB;
constexpr int kGSmem = 2 * kStageB;  // 81920

__global__ __launch_bounds__(128) void gemm_mma(
    const __nv_bfloat16* __restrict__ Ahi, const __nv_bfloat16* __restrict__ Alo,
    const __nv_bfloat16* __restrict__ Bhi, const __nv_bfloat16* __restrict__ Blo,
    const float* __restrict__ bias, float* __restrict__ Cfp,
    __nv_bfloat16* __restrict__ Chi, __nv_bfloat16* __restrict__ Clo) {
  extern __shared__ char smc[];
  uint32_t sbase = smem_u32(smc);
  int tid = threadIdx.x;
  int lane = tid & 31, wid = tid >> 5;
  int row0 = blockIdx.y * 128, col0 = blockIdx.x * 128;
  int m0w = (wid >> 1) * 64, n0w = (wid & 1) * 64;

  float acc[4][8][4];
#pragma unroll
  for (int i = 0; i < 4; i++)
#pragma unroll
    for (int j = 0; j < 8; j++)
#pragma unroll
      for (int q = 0; q < 4; q++) acc[i][j][q] = 0.f;

  const __nv_bfloat16* srcs[4] = {Ahi, Alo, Bhi, Blo};

  auto issue = [&](int ch, int s) {
    int k0 = ch * 32;
#pragma unroll
    for (int t = 0; t < 4; t++) {
      const __nv_bfloat16* src = srcs[t];
      int base0 = (t < 2) ? row0 : col0;
#pragma unroll
      for (int i = 0; i < 4; i++) {
        int idx = tid + i * 128;
        int row = idx >> 2, seg = idx & 3;
        uint32_t dst = sbase + s * kStageB + t * kTileB + row * 80 + seg * 16;
        cp16(dst, src + (size_t)(base0 + row) * kE + k0 + seg * 8);
      }
    }
    asm volatile("cp.async.commit_group;");
  };

  issue(0, 0);
  for (int ch = 0; ch < 32; ch++) {
    int s = ch & 1;
    if (ch + 1 < 32) {
      issue(ch + 1, s ^ 1);
      asm volatile("cp.async.wait_group 1;");
    } else {
      asm volatile("cp.async.wait_group 0;");
    }
    __syncthreads();
    uint32_t abase = sbase + s * kStageB;
    uint32_t bbase = sbase + s * kStageB + 2 * kTileB;
#pragma unroll
    for (int k16 = 0; k16 < 2; k16++) {
      uint32_t a_hi[4][4], a_lo[4][4], bf[8][2];
      uint32_t aoff = (k16 * 16 + (lane >> 4) * 8) * 2;
      uint32_t boff = (k16 * 16 + ((lane >> 3) & 1) * 8) * 2;
#pragma unroll
      for (int mt = 0; mt < 4; mt++) {
        uint32_t ra = (m0w + mt * 16 + (lane & 15)) * 80 + aoff;
        ldsm_x4(a_hi[mt], abase + ra);
        ldsm_x4(a_lo[mt], abase + kTileB + ra);
      }
#pragma unroll
      for (int nt = 0; nt < 8; nt++)
        ldsm_x2(bf[nt], bbase + (n0w + nt * 8 + (lane & 7)) * 80 + boff);
#pragma unroll
      for (int mt = 0; mt < 4; mt++)
#pragma unroll
        for (int nt = 0; nt < 8; nt++) mma16816(acc[mt][nt], a_hi[mt], bf[nt]);
#pragma unroll
      for (int mt = 0; mt < 4; mt++)
#pragma unroll
        for (int nt = 0; nt < 8; nt++) mma16816(acc[mt][nt], a_lo[mt], bf[nt]);
#pragma unroll
      for (int nt = 0; nt < 8; nt++)
        ldsm_x2(bf[nt],
                bbase + kTileB + (n0w + nt * 8 + (lane & 7)) * 80 + boff);
#pragma unroll
      for (int mt = 0; mt < 4; mt++)
#pragma unroll
        for (int nt = 0; nt < 8; nt++) mma16816(acc[mt][nt], a_hi[mt], bf[nt]);
    }
    __syncthreads();
  }
#pragma unroll
  for (int mt = 0; mt < 4; mt++) {
#pragma unroll
    for (int nt = 0; nt < 8; nt++) {
      int r = row0 + m0w + mt * 16 + (lane >> 2);
      int cc = col0 + n0w + nt * 8 + (lane & 3) * 2;
      float2 b0 = *(const float2*)(bias + cc);
      float v0 = acc[mt][nt][0] + b0.x, v1 = acc[mt][nt][1] + b0.y;
      float v2 = acc[mt][nt][2] + b0.x, v3 = acc[mt][nt][3] + b0.y;
      if (Cfp) {
        *(float2*)(Cfp + (size_t)r * kE + cc) = {v0, v1};
        *(float2*)(Cfp + (size_t)(r + 8) * kE + cc) = {v2, v3};
      } else {
        __nv_bfloat16 h0, h1, h2, h3, l0, l1, l2, l3;
        split_bf16(v0, h0, l0);
        split_bf16(v1, h1, l1);
        split_bf16(v2, h2, l2);
        split_bf16(v3, h3, l3);
        *(__nv_bfloat162*)(Chi + (size_t)r * kE + cc) = {h0, h1};
        *(__nv_bfloat162*)(Clo + (size_t)r * kE + cc) = {l0, l1};
        *(__nv_bfloat162*)(Chi + (size_t)(r + 8) * kE + cc) = {h2, h3};
        *(__nv_bfloat162*)(Clo + (size_t)(r + 8) * kE + cc) = {l2, l3};
      }
    }
  }
}

// ---------------- exact hash path ----------------
constexpr int kPrepSmem = (128 * 132 + 512) * 4;
__global__ __launch_bounds__(128) void prepM_kernel(
    const float* __restrict__ Wq, const float* __restrict__ bq,
    const float* __restrict__ hw) {
  extern __shared__ float ps[];
  float* wtile = ps;
  float* hws = ps + 128 * 132;
  int rh = blockIdx.x, ec = blockIdx.y;
  int h = rh & 7;
  int tid = threadIdx.x;
  for (int i = tid; i < 128; i += 128)
    *(float4*)&hws[i * 4] = *(const float4*)&hw[rh * 512 + i * 4];
#pragma unroll
  for (int it = 0; it < 32; it++) {
    int i = tid + it * 128;
    int row = i >> 5, c4 = i & 31;
    float4 v = *(const float4*)(Wq + (size_t)(ec * 128 + row) * kE + h * kD +
                                c4 * 4);
    *(float4*)&wtile[row * 132 + c4 * 4] = v;
  }
  __syncthreads();
  float s0 = 0.f, s1 = 0.f, s2 = 0.f, s3 = 0.f;
  const float* wr = wtile + tid * 132;
#pragma unroll 4
  for (int d = 0; d < kD; d++) {
    float w = wr[d];
    s0 += w * hws[d * 4 + 0];
    s1 += w * hws[d * 4 + 1];
    s2 += w * hws[d * 4 + 2];
    s3 += w * hws[d * 4 + 3];
  }
  float4 o = {s0, s1, s2, s3};
  *(float4*)(g_Mq + (size_t)(ec * 128 + tid) * 64 + rh * 4) = o;
  if (ec == 0 && tid < 4) {
    float c = 0.f;
    for (int d = 0; d < kD; d++) c += bq[h * kD + d] * hws[d * 4 + tid];
    g_cq[rh * 4 + tid] = c;
  }
}

__global__ __launch_bounds__(256) void linhash_kernel(
    const float* __restrict__ query) {
  __shared__ float slin[8][64];
  int warp = threadIdx.x >> 5, lane = threadIdx.x & 31;
  int tb = blockIdx.x * 8 + warp;
  float acc0 = g_cq[lane], acc1 = g_cq[lane + 32];
  for (int e0 = 0; e0 < kE; e0 += 32) {
    float xv = query[(size_t)tb * kE + e0 + lane];
#pragma unroll
    for (int l2 = 0; l2 < 32; l2++) {
      float v = __shfl_sync(0xffffffffu, xv, l2);
      acc0 += v * g_Mq[(e0 + l2) * 64 + lane];
      acc1 += v * g_Mq[(e0 + l2) * 64 + lane + 32];
    }
  }
  slin[warp][lane] = acc0;
  slin[warp][lane + 32] = acc1;
  __syncwarp();
  if (lane < 16) {
    const float* p = &slin[warp][lane * 4];
    float best = p[0];
    int bi = 0;
#pragma unroll
    for (int n = 1; n < 4; n++)
      if (p[n] > best) { best = p[n]; bi = n; }
#pragma unroll
    for (int n = 0; n < 4; n++)
      if (-p[n] > best) { best = -p[n]; bi = 4 + n; }
    g_hash[tb * 16 + lane] = bi;
  }
}

// ---------------- normalize + scale -> bf16 hi/lo ----------------
__global__ __launch_bounds__(256) void normalize_kernel() {
  int row = blockIdx.x;
  const float* x = g_QF + (size_t)row * kE;
  __shared__ float red[256];
  int tid = threadIdx.x;
  float s = 0.f;
#pragma unroll
  for (int i = 0; i < 4; i++) {
    float v = x[tid + i * 256];
    s += v * v;
  }
  red[tid] = s;
  __syncthreads();
  for (int off = 128; off > 0; off >>= 1) {
    if (tid < off) red[tid] += red[tid + off];
    __syncthreads();
  }
  float invn = 1.0f / sqrtf(red[0]);
#pragma unroll
  for (int i = 0; i < 4; i++) {
    int e = tid + i * 256;
    float v = x[e];
    size_t o = (size_t)row * kE + e;
    __nv_bfloat16 h, l;
    split_bf16(v * kScale, h, l);
    g_Q16h[o] = h;
    g_Q16l[o] = l;
    split_bf16(v * invn, h, l);
    g_K16h[o] = h;
    g_K16l[o] = l;
  }
}

// ---------------- stable counting sort per (b,r,h), scan-based ----------------
__global__ __launch_bounds__(256) void sort_kernel() {
  int brh = blockIdx.x;
  int h = brh & 7;
  int r = (brh >> 3) & 1;
  int b = brh >> 4;
  __shared__ int cntmat[kNH][256];
  __shared__ int btot[kNH];
  __shared__ int bbase[kNH];
  int tid = threadIdx.x;
  int w = tid >> 5, lane = tid & 31;

  int vals[8];
  int cnt[kNH];
#pragma unroll
  for (int i = 0; i < kNH; i++) cnt[i] = 0;
#pragma unroll
  for (int i = 0; i < 8; i++) {
    int t = tid * 8 + i;
    int v = g_hash[(t * kB + b) * 16 + r * 8 + h];
    vals[i] = v;
    cnt[v]++;
  }
#pragma unroll
  for (int i = 0; i < kNH; i++) cntmat[i][tid] = cnt[i];
  __syncthreads();
  {
    int run = 0;
#pragma unroll
    for (int chk = 0; chk < 8; chk++) {
      int orig = cntmat[w][chk * 32 + lane];
      int x = orig;
#pragma unroll
      for (int off = 1; off < 32; off <<= 1) {
        int y = __shfl_up_sync(0xffffffffu, x, off);
        if (lane >= off) x += y;
      }
      cntmat[w][chk * 32 + lane] = run + x - orig;
      run += __shfl_sync(0xffffffffu, x, 31);
    }
    if (lane == 0) btot[w] = run;
  }
  __syncthreads();
  if (tid == 0) {
    int s = 0;
    for (int i = 0; i < kNH; i++) {
      bbase[i] = s;
      s += btot[i];
    }
  }
  __syncthreads();
  int off[kNH];
#pragma unroll
  for (int i = 0; i < kNH; i++) off[i] = bbase[i] + cntmat[i][tid];
#pragma unroll
  for (int i = 0; i < 8; i++) {
    int v = vals[i];
    int pos = off[v]++;
    int t = tid * 8 + i;
    g_pq[brh * kT + pos] = t;
    g_invq[brh * kT + t] = pos;
  }
}

// ---------------- per-chunk window bitmask ----------------
__global__ __launch_bounds__(128) void mask_kernel() {
  int blk = blockIdx.x;
  int c = blk & (kC - 1);
  int brh = blk >> 6;
  unsigned* mw = g_mask + (size_t)blk * (kT / 32);
  int tid = threadIdx.x;
  if (tid < kT / 32) mw[tid] = 0u;
  __syncthreads();
  if (tid < kM) {
    int cc2 = (c + (tid >> 5) + kC - 1) & (kC - 1);
    int pos = cc2 * kCH + (tid & 31);
    int id = g_pq[brh * kT + pos];
    atomicOr(&mw[id >> 5], 1u << (id & 31));
  }
}

// ---------------- attention (HMMA bf16x3 scores + output) ----------------
// smem layout (bytes):
//   qhi @0      32x272 = 8704
//   qlo @8704
//   kvhi @17408 96x272 = 26112 (K for scores, then V)
//   kvlo @43520
//   sc   @69632 32x100 fp32 = 12800
//   phi  @82432 32x208 = 6656
//   plo  @89088
//   rinv @95744, rowz @95872, qid @96000, qhh @96128, oc2 @96256,
//   kid @96384 (96), khh @96768 (96) -> end 97152
constexpr int kQKS = 272;
constexpr int kPS = 208;
constexpr int kSCS = 100;
constexpr int ATTN_SMEM = 97152;

__global__ __launch_bounds__(256, 2) void attn_kernel() {
  extern __shared__ char smb[];
  uint32_t sb = smem_u32(smb);
  float* sc = (float*)(smb + 69632);
  float* rinv = (float*)(smb + 95744);
  float* rowz = (float*)(smb + 95872);
  int* qid = (int*)(smb + 96000);
  int* qhh = (int*)(smb + 96128);
  int* oc2 = (int*)(smb + 96256);
  int* kid = (int*)(smb + 96384);
  int* khh = (int*)(smb + 96768);

  int blk = blockIdx.x;
  int c = blk & (kC - 1);
  int brh = blk >> 6;
  int h = brh & 7;
  int r = (brh >> 3) & 1;
  int b = brh >> 4;
  int brho = (b * kR + (1 - r)) * kH + h;
  int tid = threadIdx.x;
  int lane = tid & 31, w = tid >> 5;

  if (tid < 32) {
    int ts = c * kCH + tid;
    int tok = g_pq[brh * kT + ts];
    qid[tid] = tok;
    qhh[tid] = g_hash[(tok * kB + b) * 16 + r * 8 + h];
    oc2[tid] = g_invq[brho * kT + tok] >> 5;
  } else if (tid < 128) {
    int m = tid - 32;
    int cc2 = (c + (m >> 5) + kC - 1) & (kC - 1);
    int pos = cc2 * kCH + (m & 31);
    int tokk = g_pq[brh * kT + pos];
    kid[m] = tokk;
    khh[m] = g_hash[(tokk * kB + b) * 16 + r * 8 + h];
  }
  __syncthreads();

  // load Q hi/lo (32 rows x 16 segs) and K hi/lo (96 rows x 16 segs)
#pragma unroll
  for (int i = 0; i < 2; i++) {
    int idx = tid + i * 256;
    int row = idx >> 4, seg = idx & 15;
    size_t src = (size_t)(qid[row] * kB + b) * kE + h * kD + seg * 8;
    cp16(sb + row * kQKS + seg * 16, g_Q16h + src);
    cp16(sb + 8704 + row * kQKS + seg * 16, g_Q16l + src);
  }
#pragma unroll
  for (int i = 0; i < 6; i++) {
    int idx = tid + i * 256;
    int row = idx >> 4, seg = idx & 15;
    size_t src = (size_t)(kid[row] * kB + b) * kE + h * kD + seg * 8;
    cp16(sb + 17408 + row * kQKS + seg * 16, g_K16h + src);
    cp16(sb + 43520 + row * kQKS + seg * 16, g_K16l + src);
  }
  asm volatile("cp.async.commit_group;");
  asm volatile("cp.async.wait_group 0;");
  __syncthreads();

  // scores: warp w -> m-half mh = w>>2 (16 rows), n-group ng = w&3
  // (cols ng*24..ng*24+23). 8 warps tile 32x96 exactly.
  {
    int mh = w >> 2, ng = w & 3;
    float acc[3][4];
#pragma unroll
    for (int nt = 0; nt < 3; nt++)
#pragma unroll
      for (int q = 0; q < 4; q++) acc[nt][q] = 0.f;
#pragma unroll
    for (int ks = 0; ks < 8; ks++) {
      uint32_t a_h[4], a_l[4], b_h[3][2], b_l[3][2];
      uint32_t aoff = ks * 32 + (lane >> 4) * 16;
      uint32_t boff = ks * 32 + ((lane >> 3) & 1) * 16;
      uint32_t ra = (mh * 16 + (lane & 15)) * kQKS + aoff;
      ldsm_x4(a_h, sb + ra);
      ldsm_x4(a_l, sb + 8704 + ra);
#pragma unroll
      for (int nt = 0; nt < 3; nt++) {
        uint32_t rb = (ng * 24 + nt * 8 + (lane & 7)) * kQKS + boff;
        ldsm_x2(b_h[nt], sb + 17408 + rb);
        ldsm_x2(b_l[nt], sb + 43520 + rb);
      }
#pragma unroll
      for (int nt = 0; nt < 3; nt++) {
        mma16816(acc[nt], a_h, b_h[nt]);
        mma16816(acc[nt], a_l, b_h[nt]);
        mma16816(acc[nt], a_h, b_l[nt]);
      }
    }
    // write S to sc (stride 100)
#pragma unroll
    for (int nt = 0; nt < 3; nt++) {
      int l0 = mh * 16 + (lane >> 2);
      int m = ng * 24 + nt * 8 + (lane & 3) * 2;
      *(float2*)&sc[l0 * kSCS + m] = {acc[nt][0], acc[nt][1]};
      *(float2*)&sc[(l0 + 8) * kSCS + m] = {acc[nt][2], acc[nt][3]};
    }
  }
  __syncthreads();  // K reads done; safe to overwrite kv buffers with V

  // async V hi/lo loads (overlap with mask+softmax)
#pragma unroll
  for (int i = 0; i < 6; i++) {
    int idx = tid + i * 256;
    int row = idx >> 4, seg = idx & 15;
    size_t src = (size_t)(kid[row] * kB + b) * kE + h * kD + seg * 8;
    cp16(sb + 17408 + row * kQKS + seg * 16, g_V16h + src);
    cp16(sb + 43520 + row * kQKS + seg * 16, g_V16l + src);
  }
  asm volatile("cp.async.commit_group;");

  // mask + softmax: warp = 4 rows, lane = cols m, m+32, m+64.
  {
    __nv_bfloat16* ph = (__nv_bfloat16*)(smb + 82432);
    __nv_bfloat16* pl = (__nv_bfloat16*)(smb + 89088);
#pragma unroll
    for (int rr = 0; rr < 4; rr++) {
      int l = w * 4 + rr;
      int myqh = qhh[l], myqid = qid[l];
      const unsigned* mw = g_mask + (size_t)(brho * kC + oc2[l]) * (kT / 32);
      float v[3];
#pragma unroll
      for (int j = 0; j < 3; j++) {
        int m = lane + 32 * j;
        float s = sc[l * kSCS + m];
        int id = kid[m];
        if (myqh != khh[m]) s -= kInfM;
        if (myqid == id) s -= kBigM;
        if ((mw[id >> 5] >> (id & 31)) & 1u) s -= kLog2;
        v[j] = s;
      }
      float mx = fmaxf(v[0], fmaxf(v[1], v[2]));
      for (int off = 16; off; off >>= 1)
        mx = fmaxf(mx, __shfl_xor_sync(0xffffffffu, mx, off));
      float ssum = 0.f;
#pragma unroll
      for (int j = 0; j < 3; j++) {
        int m = lane + 32 * j;
        float e = expf(v[j] - mx);
        ssum += e;
        __nv_bfloat16 hh, ll;
        split_bf16(e, hh, ll);
        ph[l * (kPS / 2) + m] = hh;
        pl[l * (kPS / 2) + m] = ll;
      }
      for (int off = 16; off; off >>= 1)
        ssum += __shfl_xor_sync(0xffffffffu, ssum, off);
      if (lane == 0) {
        rinv[l] = 1.0f / ssum;
        rowz[l] = mx + logf(ssum);
      }
    }
  }
  asm volatile("cp.async.wait_group 0;");
  __syncthreads();

  // output: O = P @ V, warp w owns cols w*16..w*16+15 (2 n-tiles), full M.
  {
    float acc[2][2][4];
#pragma unroll
    for (int mt = 0; mt < 2; mt++)
#pragma unroll
      for (int nt = 0; nt < 2; nt++)
#pragma unroll
        for (int q = 0; q < 4; q++) acc[mt][nt][q] = 0.f;
#pragma unroll
    for (int ks = 0; ks < 6; ks++) {
      uint32_t a_h[2][4], a_l[2][4], b_h[2][2], b_l[2][2];
      uint32_t aoff = ks * 32 + (lane >> 4) * 16;
#pragma unroll
      for (int mt = 0; mt < 2; mt++) {
        uint32_t ra = (mt * 16 + (lane & 15)) * kPS + aoff;
        ldsm_x4(a_h[mt], sb + 82432 + ra);
        ldsm_x4(a_l[mt], sb + 89088 + ra);
      }
#pragma unroll
      for (int nt = 0; nt < 2; nt++) {
        uint32_t rb = (ks * 16 + (lane & 15)) * kQKS + (w * 16 + nt * 8) * 2;
        ldsm_x2t(b_h[nt], sb + 17408 + rb);
        ldsm_x2t(b_l[nt], sb + 43520 + rb);
      }
#pragma unroll
      for (int mt = 0; mt < 2; mt++)
#pragma unroll
        for (int nt = 0; nt < 2; nt++) {
          mma16816(acc[mt][nt], a_h[mt], b_h[nt]);
          mma16816(acc[mt][nt], a_l[mt], b_h[nt]);
          mma16816(acc[mt][nt], a_h[mt], b_l[nt]);
        }
    }
#pragma unroll
    for (int mt = 0; mt < 2; mt++)
#pragma unroll
      for (int nt = 0; nt < 2; nt++) {
        int l0 = mt * 16 + (lane >> 2);
        int l1 = l0 + 8;
        int n = w * 16 + nt * 8 + (lane & 3) * 2;
        float ri0 = rinv[l0], ri1 = rinv[l1];
        *(float2*)(g_o + (size_t)(brh * kT + qid[l0]) * kD + n) = {
            acc[mt][nt][0] * ri0, acc[mt][nt][1] * ri0};
        *(float2*)(g_o + (size_t)(brh * kT + qid[l1]) * kD + n) = {
            acc[mt][nt][2] * ri1, acc[mt][nt][3] * ri1};
      }
  }
  if (tid < 32) g_z[brh * kT + qid[tid]] = rowz[tid];
}

// ---------------- combine rounds (+ fused bf16 hi/lo split) ----------------
__global__ __launch_bounds__(256) void combine_kernel() {
  int idx = blockIdx.x * 256 + threadIdx.x;
  int d = idx & 127;
  int t = (idx >> 7) & (kT - 1);
  int h = (idx >> 18) & 7;
  int b = idx >> 21;
  int i0 = ((b * kR + 0) * kH + h) * kT + t;
  int i1 = ((b * kR + 1) * kH + h) * kT + t;
  float z0 = g_z[i0], z1 = g_z[i1];
  float m = fmaxf(z0, z1);
  float e0 = expf(z0 - m), e1 = expf(z1 - m);
  float inv = 1.0f / (e0 + e1);
  float val =
      (e0 * g_o[(size_t)i0 * kD + d] + e1 * g_o[(size_t)i1 * kD + d]) * inv;
  __nv_bfloat16 hi, lo;
  split_bf16(val, hi, lo);
  size_t o = (size_t)(t * kB + b) * kE + h * kD + d;
  g_Ahi[o] = hi;
  g_Alo[o] = lo;
}

// ---------------- launch ----------------
extern "C" void kernel_launch(void* const* d_in, const int* in_sizes, int n_in,
                              void* d_out, int out_size) {
  (void)in_sizes;
  (void)n_in;
  (void)out_size;
  const float* query = (const float*)d_in[0];
  const float* value = (const float*)d_in[2];
  const float* Wq = (const float*)d_in[3];
  const float* bq = (const float*)d_in[4];
  const float* Wv = (const float*)d_in[5];
  const float* bv = (const float*)d_in[6];
  const float* Wo = (const float*)d_in[7];
  const float* bo = (const float*)d_in[8];
  const float* hw = (const float*)d_in[9];
  float* out = (float*)d_out;

  float* pQF;
  cudaGetSymbolAddress((void**)&pQF, g_QF);
  __nv_bfloat16 *pAH, *pAL, *pViH, *pViL, *pV16h, *pV16l;
  cudaGetSymbolAddress((void**)&pAH, g_Ahi);
  cudaGetSymbolAddress((void**)&pAL, g_Alo);
  cudaGetSymbolAddress((void**)&pViH, g_Vihi);
  cudaGetSymbolAddress((void**)&pViL, g_Vilo);
  cudaGetSymbolAddress((void**)&pV16h, g_V16h);
  cudaGetSymbolAddress((void**)&pV16l, g_V16l);
  __nv_bfloat16 *pWqH, *pWqL, *pWvH, *pWvL, *pWoH, *pWoL;
  cudaGetSymbolAddress((void**)&pWqH, g_WqThi);
  cudaGetSymbolAddress((void**)&pWqL, g_WqTlo);
  cudaGetSymbolAddress((void**)&pWvH, g_WvThi);
  cudaGetSymbolAddress((void**)&pWvL, g_WvTlo);
  cudaGetSymbolAddress((void**)&pWoH, g_WoThi);
  cudaGetSymbolAddress((void**)&pWoL, g_WoTlo);

  cudaFuncSetAttribute(gemm_mma, cudaFuncAttributeMaxDynamicSharedMemorySize,
                       kGSmem);
  cudaFuncSetAttribute(attn_kernel, cudaFuncAttributeMaxDynamicSharedMemorySize,
                       ATTN_SMEM);
  cudaFuncSetAttribute(prepM_kernel, cudaFuncAttributeMaxDynamicSharedMemorySize,
                       kPrepSmem);

  static cudaStream_t s2 = nullptr;
  static cudaEvent_t evF = nullptr, evJ = nullptr;
  if (s2 == nullptr) {
    cudaStreamCreateWithFlags(&s2, cudaStreamNonBlocking);
    cudaEventCreateWithFlags(&evF, cudaEventDisableTiming);
    cudaEventCreateWithFlags(&evJ, cudaEventDisableTiming);
  }

  dim3 tgrid(32, 32);
  dim3 tblk(32, 8);
  dim3 ggrid(kE / 128, kTB / 128);

  bool use_side = (s2 != nullptr);
  cudaStream_t sv = use_side ? s2 : (cudaStream_t)0;

  if (use_side) {
    cudaEventRecord(evF, 0);
    cudaStreamWaitEvent(s2, evF, 0);
  }

  // ---- side chain: V projection (bf16 split output) + prep ----
  wsplit_kernel<<<tgrid, tblk, 0, sv>>>(Wv, pWvH, pWvL);
  wsplit_kernel<<<tgrid, tblk, 0, sv>>>(Wo, pWoH, pWoL);
  asplit_kernel<<<(kTB * kE / 4) / 256, 256, 0, sv>>>(value, pViH, pViL);
  prepM_kernel<<<dim3(16, 8), 128, kPrepSmem, sv>>>(Wq, bq, hw);
  linhash_kernel<<<kTB / 8, 256, 0, sv>>>(query);
  sort_kernel<<<kB * kR * kH, 256, 0, sv>>>();
  mask_kernel<<<kB * kR * kH * kC, 128, 0, sv>>>();
  gemm_mma<<<ggrid, 128, kGSmem, sv>>>(pViH, pViL, pWvH, pWvL, bv, nullptr,
                                       pV16h, pV16l);

  // ---- main chain: Q projection ----
  wsplit_kernel<<<tgrid, tblk>>>(Wq, pWqH, pWqL);
  asplit_kernel<<<(kTB * kE / 4) / 256, 256>>>(query, pAH, pAL);
  gemm_mma<<<ggrid, 128, kGSmem>>>(pAH, pAL, pWqH, pWqL, bq, pQF, nullptr,
                                   nullptr);
  normalize_kernel<<<kTB, 256>>>();

  if (use_side) {
    cudaEventRecord(evJ, s2);
    cudaStreamWaitEvent((cudaStream_t)0, evJ, 0);
  }

  attn_kernel<<<kB * kR * kH * kC, 256, ATTN_SMEM>>>();
  combine_kernel<<<(kB * kH * kT * kD) / 256, 256>>>();
  gemm_mma<<<ggrid, 128, kGSmem>>>(pAH, pAL, pWoH, pWoL, bo, out, nullptr,
                                   nullptr);
}